// round 3
// baseline (speedup 1.0000x reference)
#include <cuda_runtime.h>
#include <cstdint>

// Problem constants
#define DD    1024
#define HH    16
#define DHD   64
#define DFF   4096
#define TT    2048
#define BB    2
#define MM    4096   // B*T

// ---------------- scratch (device globals; no allocation) ----------------
__device__ float g_h   [MM * DD];        // LN1 output
__device__ float g_wqkv[DD * 3 * DD];    // repacked QKV weights [K=1024, N=3072]
__device__ float g_qkv [MM * 3 * DD];    // Q|K|V per row
__device__ float g_x1  [MM * DD];        // x + attn
__device__ float g_h2  [MM * DD];        // LN2 output
__device__ float g_ff1 [MM * DFF];       // relu(h2 W1 + b1)

// ---------------- LayerNorm (ddof=1) ----------------
__global__ __launch_bounds__(256) void ln_kernel(const float* __restrict__ x,
                                                 const float* __restrict__ g,
                                                 const float* __restrict__ bta,
                                                 float* __restrict__ out) {
    int row = blockIdx.x;
    int tid = threadIdx.x;
    const float4* xr = (const float4*)(x + (size_t)row * DD);
    float4 v = xr[tid];
    float s  = v.x + v.y + v.z + v.w;
    float sq = v.x * v.x + v.y * v.y + v.z * v.z + v.w * v.w;
#pragma unroll
    for (int o = 16; o; o >>= 1) {
        s  += __shfl_xor_sync(0xffffffffu, s,  o);
        sq += __shfl_xor_sync(0xffffffffu, sq, o);
    }
    __shared__ float ss[8], sqs[8];
    int w = tid >> 5, ln = tid & 31;
    if (ln == 0) { ss[w] = s; sqs[w] = sq; }
    __syncthreads();
    s = 0.f; sq = 0.f;
#pragma unroll
    for (int i = 0; i < 8; i++) { s += ss[i]; sq += sqs[i]; }
    float mean = s * (1.f / 1024.f);
    float var  = (sq - 1024.f * mean * mean) * (1.f / 1023.f);
    float r    = rsqrtf(var + 1e-5f);
    float4 gv = ((const float4*)g)[tid];
    float4 bv = ((const float4*)bta)[tid];
    float4 o;
    o.x = gv.x * (v.x - mean) * r + bv.x;
    o.y = gv.y * (v.y - mean) * r + bv.y;
    o.z = gv.z * (v.z - mean) * r + bv.z;
    o.w = gv.w * (v.w - mean) * r + bv.w;
    ((float4*)(out + (size_t)row * DD))[tid] = o;
}

// ---------------- repack Wq/Wk/Wv [H,D,DH] -> flat [D, 3*D] ----------------
__global__ __launch_bounds__(256) void repack_kernel(const float* __restrict__ Wq,
                                                     const float* __restrict__ Wk,
                                                     const float* __restrict__ Wv,
                                                     float* __restrict__ out) {
    int idx = blockIdx.x * 256 + threadIdx.x;   // 0 .. 1024*3072-1
    int k = idx / 3072;
    int n = idx - k * 3072;
    int w = n >> 10;
    int rem = n & 1023;
    int h = rem >> 6;
    int e = rem & 63;
    const float* W = (w == 0) ? Wq : ((w == 1) ? Wk : Wv);
    out[idx] = W[h * (DD * DHD) + k * DHD + e];
}

// ---------------- SGEMM 128x128x16, 8x8 microtile ----------------
// EPI: 0=plain  1=relu(bias+)  2=bias+residual
template <int EPI>
__global__ __launch_bounds__(256) void gemm_kernel(const float* __restrict__ A,
                                                   const float* __restrict__ B,
                                                   float* __restrict__ C,
                                                   int K, int N,
                                                   const float* __restrict__ bias,
                                                   const float* __restrict__ res) {
    __shared__ float As[16][128];
    __shared__ float Bs[16][128];
    int tid  = threadIdx.x;
    int crow = blockIdx.y * 128;
    int ccol = blockIdx.x * 128;
    int tr = (tid >> 4) << 3;    // 0..120
    int tc = (tid & 15) << 3;    // 0..120
    int aRow = tid >> 2;                 // 0..63
    int aCol = (tid & 3) << 2;           // 0..12
    int bRow = tid >> 5;                 // 0..7
    int bCol = (tid & 31) << 2;          // 0..124
    float acc[8][8];
#pragma unroll
    for (int i = 0; i < 8; i++)
#pragma unroll
        for (int j = 0; j < 8; j++) acc[i][j] = 0.f;

    const float* Aptr = A + (size_t)crow * K;
    for (int k0 = 0; k0 < K; k0 += 16) {
        float4 a0 = *(const float4*)(Aptr + (size_t)aRow * K        + k0 + aCol);
        float4 a1 = *(const float4*)(Aptr + (size_t)(aRow + 64) * K + k0 + aCol);
        float4 b0 = *(const float4*)(B + (size_t)(k0 + bRow) * N     + ccol + bCol);
        float4 b1 = *(const float4*)(B + (size_t)(k0 + bRow + 8) * N + ccol + bCol);
        __syncthreads();
        As[aCol + 0][aRow] = a0.x; As[aCol + 1][aRow] = a0.y;
        As[aCol + 2][aRow] = a0.z; As[aCol + 3][aRow] = a0.w;
        As[aCol + 0][aRow + 64] = a1.x; As[aCol + 1][aRow + 64] = a1.y;
        As[aCol + 2][aRow + 64] = a1.z; As[aCol + 3][aRow + 64] = a1.w;
        *(float4*)&Bs[bRow][bCol]     = b0;
        *(float4*)&Bs[bRow + 8][bCol] = b1;
        __syncthreads();
#pragma unroll
        for (int kk = 0; kk < 16; kk++) {
            float ar[8], br[8];
            *(float4*)(ar)     = *(const float4*)&As[kk][tr];
            *(float4*)(ar + 4) = *(const float4*)&As[kk][tr + 4];
            *(float4*)(br)     = *(const float4*)&Bs[kk][tc];
            *(float4*)(br + 4) = *(const float4*)&Bs[kk][tc + 4];
#pragma unroll
            for (int i = 0; i < 8; i++)
#pragma unroll
                for (int j = 0; j < 8; j++) acc[i][j] += ar[i] * br[j];
        }
    }

#pragma unroll
    for (int i = 0; i < 8; i++) {
        size_t r = (size_t)(crow + tr + i);
#pragma unroll
        for (int j = 0; j < 8; j += 4) {
            int c = ccol + tc + j;
            float4 v;
            v.x = acc[i][j]; v.y = acc[i][j + 1]; v.z = acc[i][j + 2]; v.w = acc[i][j + 3];
            if (EPI == 1) {
                v.x = fmaxf(v.x + bias[c],     0.f);
                v.y = fmaxf(v.y + bias[c + 1], 0.f);
                v.z = fmaxf(v.z + bias[c + 2], 0.f);
                v.w = fmaxf(v.w + bias[c + 3], 0.f);
            } else if (EPI == 2) {
                float4 rb = *(const float4*)(res + r * N + c);
                v.x += bias[c]     + rb.x;
                v.y += bias[c + 1] + rb.y;
                v.z += bias[c + 2] + rb.z;
                v.w += bias[c + 3] + rb.w;
            }
            *(float4*)(C + r * N + c) = v;
        }
    }
}

// ---------------- Flash attention (causal), 64-query tiles ----------------
// grid (32 qtiles, 32 b*h), 256 threads: part = tid/64 (j-slab & O-col slab),
// row = tid%64 (query row). All K/V smem reads are warp-broadcast; P tile
// aliases K tile (K fully consumed before P write).
__global__ __launch_bounds__(256) void attn_kernel(const float* __restrict__ qkv,
                                                   const float* __restrict__ x,
                                                   float* __restrict__ x1) {
    __shared__ float Ks[64 * 68];        // K tile (pitch 68); aliased as P (pitch 65)
    __shared__ float Vs[64 * 64];
    __shared__ float redm[4 * 64];
    __shared__ float reds[4 * 64];
    int qt = blockIdx.x;
    int bh = blockIdx.y;
    int b = bh >> 4, h = bh & 15;
    int tid = threadIdx.x;
    int part = tid >> 6;      // 0..3
    int row  = tid & 63;      // 0..63
    int qg = qt * 64 + row;

    const float* qptr = qkv + ((size_t)(b * TT + qg)) * 3072 + h * 64;
    float4 q4[16];
#pragma unroll
    for (int i = 0; i < 16; i++) {
        float4 v = ((const float4*)qptr)[i];
        v.x *= 0.03125f; v.y *= 0.03125f; v.z *= 0.03125f; v.w *= 0.03125f;  // 1/sqrt(1024)
        q4[i] = v;
    }
    float4 O4[4];
#pragma unroll
    for (int i = 0; i < 4; i++) { O4[i].x = O4[i].y = O4[i].z = O4[i].w = 0.f; }
    float m = -1e30f, l = 0.f;

    for (int kt = 0; kt <= qt; ++kt) {
        __syncthreads();   // protect Ks/Vs/P from previous-iter readers
        {
            int jr = tid >> 4;           // 0..15
            int c  = (tid & 15) << 2;    // 0..60
            const float* kbase = qkv + ((size_t)(b * TT + kt * 64)) * 3072 + 1024 + h * 64;
            const float* vbase = kbase + 1024;
#pragma unroll
            for (int it = 0; it < 4; ++it) {
                int j = jr + it * 16;
                *(float4*)&Ks[j * 68 + c] = *(const float4*)(kbase + (size_t)j * 3072 + c);
                *(float4*)&Vs[j * 64 + c] = *(const float4*)(vbase + (size_t)j * 3072 + c);
            }
        }
        __syncthreads();

        float s[16];
        float tm = -1e30f;
        int j0 = part * 16;
#pragma unroll
        for (int jj = 0; jj < 16; ++jj) {
            const float4* kr = (const float4*)&Ks[(j0 + jj) * 68];
            float acc = 0.f;
#pragma unroll
            for (int e = 0; e < 16; e++) {
                float4 kv = kr[e];
                acc += q4[e].x * kv.x + q4[e].y * kv.y + q4[e].z * kv.z + q4[e].w * kv.w;
            }
            if (kt == qt && (j0 + jj) > row) acc = -1e30f;
            s[jj] = acc;
            tm = fmaxf(tm, acc);
        }
        redm[part * 64 + row] = tm;
        __syncthreads();  // sync1: all S done (Ks reads complete -> safe to alias P)
        float mt = fmaxf(fmaxf(redm[row], redm[64 + row]),
                         fmaxf(redm[128 + row], redm[192 + row]));
        float mnew = fmaxf(m, mt);
        float sc = __expf(m - mnew);
        float ps = 0.f;
#pragma unroll
        for (int jj = 0; jj < 16; ++jj) {
            float p = __expf(s[jj] - mnew);
            Ks[row * 65 + j0 + jj] = p;   // P tile aliased onto Ks
            ps += p;
        }
        reds[part * 64 + row] = ps;
        __syncthreads();  // sync2: P complete
        float rs = reds[row] + reds[64 + row] + reds[128 + row] + reds[192 + row];
        l = l * sc + rs;
        m = mnew;
#pragma unroll
        for (int i = 0; i < 4; i++) { O4[i].x *= sc; O4[i].y *= sc; O4[i].z *= sc; O4[i].w *= sc; }
#pragma unroll 8
        for (int j = 0; j < 64; ++j) {
            float p = Ks[row * 65 + j];
            const float4* vr = (const float4*)&Vs[j * 64 + part * 16];
#pragma unroll
            for (int i = 0; i < 4; i++) {
                float4 vv = vr[i];
                O4[i].x += p * vv.x; O4[i].y += p * vv.y;
                O4[i].z += p * vv.z; O4[i].w += p * vv.w;
            }
        }
    }

    float inv = 1.f / l;
    size_t ob = ((size_t)(b * TT + qg)) * DD + h * 64 + part * 16;
    const float4* xr = (const float4*)(x + ob);
    float4* orow = (float4*)(x1 + ob);
#pragma unroll
    for (int i = 0; i < 4; i++) {
        float4 xv = xr[i];
        float4 ov;
        ov.x = xv.x + O4[i].x * inv;
        ov.y = xv.y + O4[i].y * inv;
        ov.z = xv.z + O4[i].z * inv;
        ov.w = xv.w + O4[i].w * inv;
        orow[i] = ov;
    }
}

// ---------------- launch ----------------
extern "C" void kernel_launch(void* const* d_in, const int* in_sizes, int n_in,
                              void* d_out, int out_size) {
    const float* x      = (const float*)d_in[0];
    const float* Wq     = (const float*)d_in[1];
    const float* Wk     = (const float*)d_in[2];
    const float* Wv     = (const float*)d_in[3];
    const float* W1     = (const float*)d_in[4];
    const float* b1     = (const float*)d_in[5];
    const float* W2     = (const float*)d_in[6];
    const float* b2     = (const float*)d_in[7];
    const float* gamma1 = (const float*)d_in[8];
    const float* beta1  = (const float*)d_in[9];
    const float* gamma2 = (const float*)d_in[10];
    const float* beta2  = (const float*)d_in[11];
    float* out = (float*)d_out;

    float *hbuf, *wqkv, *qkv, *x1, *h2, *ff1;
    cudaGetSymbolAddress((void**)&hbuf, g_h);
    cudaGetSymbolAddress((void**)&wqkv, g_wqkv);
    cudaGetSymbolAddress((void**)&qkv,  g_qkv);
    cudaGetSymbolAddress((void**)&x1,   g_x1);
    cudaGetSymbolAddress((void**)&h2,   g_h2);
    cudaGetSymbolAddress((void**)&ff1,  g_ff1);

    // 1. LN1
    ln_kernel<<<MM, 256>>>(x, gamma1, beta1, hbuf);
    // 2. repack QKV weights
    repack_kernel<<<(DD * 3 * DD) / 256, 256>>>(Wq, Wk, Wv, wqkv);
    // 3. QKV projection: [4096,1024] x [1024,3072]
    gemm_kernel<0><<<dim3(3 * DD / 128, MM / 128), 256>>>(hbuf, wqkv, qkv, DD, 3 * DD,
                                                          nullptr, nullptr);
    // 4. attention + residual -> x1
    attn_kernel<<<dim3(TT / 64, BB * HH), 256>>>(qkv, x, x1);
    // 5. LN2
    ln_kernel<<<MM, 256>>>(x1, gamma2, beta2, h2);
    // 6. FFN1: relu(h2 @ W1 + b1)
    gemm_kernel<1><<<dim3(DFF / 128, MM / 128), 256>>>(h2, W1, ff1, DD, DFF, b1, nullptr);
    // 7. FFN2: ff1 @ W2 + b2 + x1 -> out
    gemm_kernel<2><<<dim3(DD / 128, MM / 128), 256>>>(ff1, W2, out, DFF, DD, b2, x1);
}

// round 5
// speedup vs baseline: 1.9555x; 1.9555x over previous
#include <cuda_runtime.h>
#include <cuda_bf16.h>
#include <cstdint>

// Problem constants
#define DD    1024
#define HH    16
#define DHD   64
#define DFF   4096
#define TT    2048
#define BB    2
#define MM    4096   // B*T

// ---------------- scratch (device globals; no allocation) ----------------
__device__ __nv_bfloat16 g_a_hi[MM * DD], g_a_lo[MM * DD];          // LN out hi/lo (reused LN1/LN2)
__device__ __nv_bfloat16 g_wqkv_hi[3 * DD * DD], g_wqkv_lo[3 * DD * DD];  // [N=3072,K=1024]
__device__ __nv_bfloat16 g_w1_hi[DFF * DD], g_w1_lo[DFF * DD];      // [N=4096,K=1024]
__device__ __nv_bfloat16 g_w2_hi[DD * DFF], g_w2_lo[DD * DFF];      // [N=1024,K=4096]
__device__ __nv_bfloat16 g_ff1_hi[(size_t)MM * DFF], g_ff1_lo[(size_t)MM * DFF];
__device__ float g_qkv[(size_t)MM * 3 * DD];
__device__ float g_x1 [MM * DD];

// ---------------- helpers ----------------
static __device__ __forceinline__ uint32_t su32(const void* p) {
    uint32_t a;
    asm("{ .reg .u64 t; cvta.to.shared.u64 t, %1; cvt.u32.u64 %0, t; }" : "=r"(a) : "l"(p));
    return a;
}
static __device__ __forceinline__ uint32_t sw128(uint32_t off) {
    return off ^ ((off >> 3) & 0x70);
}
static __device__ __forceinline__ void cpasync16(uint32_t dst, const void* src) {
    asm volatile("cp.async.cg.shared.global [%0], [%1], 16;" :: "r"(dst), "l"(src));
}
#define CP_COMMIT()  asm volatile("cp.async.commit_group;" ::: "memory")
#define CP_WAIT(n)   asm volatile("cp.async.wait_group %0;" :: "n"(n) : "memory")

static __device__ __forceinline__ void ldm_x4(uint32_t* r, uint32_t addr) {
    asm volatile("ldmatrix.sync.aligned.m8n8.x4.shared.b16 {%0,%1,%2,%3}, [%4];"
                 : "=r"(r[0]), "=r"(r[1]), "=r"(r[2]), "=r"(r[3]) : "r"(addr));
}
static __device__ __forceinline__ void mma16816(float* d, const uint32_t* a, const uint32_t* b) {
    asm volatile(
        "mma.sync.aligned.m16n8k16.row.col.f32.bf16.bf16.f32 "
        "{%0,%1,%2,%3}, {%4,%5,%6,%7}, {%8,%9}, {%0,%1,%2,%3};"
        : "+f"(d[0]), "+f"(d[1]), "+f"(d[2]), "+f"(d[3])
        : "r"(a[0]), "r"(a[1]), "r"(a[2]), "r"(a[3]), "r"(b[0]), "r"(b[1]));
}
static __device__ __forceinline__ void split_bf16(float v, __nv_bfloat16& h, __nv_bfloat16& l) {
    h = __float2bfloat16(v);
    l = __float2bfloat16(v - __bfloat162float(h));
}

// ---------------- LayerNorm (ddof=1), bf16 hi/lo output ----------------
__global__ __launch_bounds__(256) void ln_bf16_kernel(const float* __restrict__ x,
                                                      const float* __restrict__ g,
                                                      const float* __restrict__ bta,
                                                      __nv_bfloat16* __restrict__ ohi,
                                                      __nv_bfloat16* __restrict__ olo) {
    int row = blockIdx.x;
    int tid = threadIdx.x;
    const float4* xr = (const float4*)(x + (size_t)row * DD);
    float4 v = xr[tid];
    float s  = v.x + v.y + v.z + v.w;
    float sq = v.x * v.x + v.y * v.y + v.z * v.z + v.w * v.w;
#pragma unroll
    for (int o = 16; o; o >>= 1) {
        s  += __shfl_xor_sync(0xffffffffu, s,  o);
        sq += __shfl_xor_sync(0xffffffffu, sq, o);
    }
    __shared__ float ss[8], sqs[8];
    int w = tid >> 5, ln = tid & 31;
    if (ln == 0) { ss[w] = s; sqs[w] = sq; }
    __syncthreads();
    s = 0.f; sq = 0.f;
#pragma unroll
    for (int i = 0; i < 8; i++) { s += ss[i]; sq += sqs[i]; }
    float mean = s * (1.f / 1024.f);
    float var  = (sq - 1024.f * mean * mean) * (1.f / 1023.f);
    float r    = rsqrtf(var + 1e-5f);
    float4 gv = ((const float4*)g)[tid];
    float4 bv = ((const float4*)bta)[tid];
    float o0 = gv.x * (v.x - mean) * r + bv.x;
    float o1 = gv.y * (v.y - mean) * r + bv.y;
    float o2 = gv.z * (v.z - mean) * r + bv.z;
    float o3 = gv.w * (v.w - mean) * r + bv.w;
    __nv_bfloat16 h0, h1, h2, h3, l0, l1, l2, l3;
    split_bf16(o0, h0, l0); split_bf16(o1, h1, l1);
    split_bf16(o2, h2, l2); split_bf16(o3, h3, l3);
    __nv_bfloat162* hp = (__nv_bfloat162*)(ohi + (size_t)row * DD);
    __nv_bfloat162* lp = (__nv_bfloat162*)(olo + (size_t)row * DD);
    hp[tid * 2]     = __halves2bfloat162(h0, h1);
    hp[tid * 2 + 1] = __halves2bfloat162(h2, h3);
    lp[tid * 2]     = __halves2bfloat162(l0, l1);
    lp[tid * 2 + 1] = __halves2bfloat162(l2, l3);
}

// ---------------- repack Wq/Wk/Wv [H,D,DH] -> [N=3072, K=1024] bf16 hi/lo ----------------
__global__ __launch_bounds__(256) void repack_qkv_kernel(const float* __restrict__ Wq,
                                                         const float* __restrict__ Wk,
                                                         const float* __restrict__ Wv,
                                                         __nv_bfloat16* __restrict__ ohi,
                                                         __nv_bfloat16* __restrict__ olo) {
    int idx = blockIdx.x * 256 + threadIdx.x;     // over 3072*1024, n*1024 + k
    int n = idx >> 10;
    int k = idx & 1023;
    int w = n >> 10;
    int h = (n >> 6) & 15;
    int e = n & 63;
    const float* W = (w == 0) ? Wq : ((w == 1) ? Wk : Wv);
    float v = W[h * (DD * DHD) + k * DHD + e];
    __nv_bfloat16 hi, lo;
    split_bf16(v, hi, lo);
    ohi[idx] = hi;
    olo[idx] = lo;
}

// ---------------- tiled transpose+convert: in [Kd, Nd] fp32 -> out [Nd, Kd] bf16 hi/lo ----------------
__global__ __launch_bounds__(256) void transpose_bf16_kernel(const float* __restrict__ in,
                                                             __nv_bfloat16* __restrict__ ohi,
                                                             __nv_bfloat16* __restrict__ olo,
                                                             int Kd, int Nd) {
    __shared__ float t[32][33];
    int nt = blockIdx.x * 32, kt = blockIdx.y * 32;
    int tx = threadIdx.x, ty = threadIdx.y;   // 32 x 8
#pragma unroll
    for (int i = 0; i < 32; i += 8)
        t[ty + i][tx] = in[(size_t)(kt + ty + i) * Nd + nt + tx];
    __syncthreads();
#pragma unroll
    for (int i = 0; i < 32; i += 8) {
        float v = t[tx][ty + i];
        __nv_bfloat16 hi, lo;
        split_bf16(v, hi, lo);
        size_t o = (size_t)(nt + ty + i) * Kd + kt + tx;
        ohi[o] = hi;
        olo[o] = lo;
    }
}

// ---------------- HMMA bf16-split GEMM: C[M,N] = A[M,K] * B'[N,K]^T ----------------
// 128x128 CTA tile, K chunks of 64, cp.async double-buffered.
// 8 warps: wm = wid&3 (32 M-rows each), wn = wid>>2 (64 N-cols each).
// 3 terms: AhiBhi + AloBhi + AhiBlo.
// EPI: 0 = fp32 store   1 = relu(+bias) -> bf16 hi/lo   2 = +bias +residual -> fp32
#define TILE_B   16384          // 128 rows x 64 bf16 (128B/row)
#define STAGE_B  (4 * TILE_B)   // Ahi | Alo | Bhi | Blo
#define DSM_B    (2 * STAGE_B + 1024)

template <int EPI>
__global__ __launch_bounds__(256, 1) void hmma_gemm_kernel(const __nv_bfloat16* __restrict__ Ahi,
                                                           const __nv_bfloat16* __restrict__ Alo,
                                                           const __nv_bfloat16* __restrict__ Bhi,
                                                           const __nv_bfloat16* __restrict__ Blo,
                                                           int K, int N,
                                                           float* __restrict__ Cf,
                                                           __nv_bfloat16* __restrict__ Chi,
                                                           __nv_bfloat16* __restrict__ Clo,
                                                           const float* __restrict__ bias,
                                                           const float* __restrict__ res) {
    extern __shared__ __align__(16) char dsm[];
    int tid  = threadIdx.x;
    int wid  = tid >> 5;
    int lane = tid & 31;
    int wm = wid & 3;
    int wn = wid >> 2;

    // align dynamic smem to 1024 (swizzle assumes 128B-row-aligned tiles)
    uint32_t b32 = su32(dsm);
    uint32_t pad = (1024u - (b32 & 1023u)) & 1023u;
    b32 += pad;

    const int m0 = blockIdx.y * 128;
    const int n0 = blockIdx.x * 128;
    const int nch = K >> 6;

    const __nv_bfloat16* srcA_hi = Ahi + (size_t)m0 * K;
    const __nv_bfloat16* srcA_lo = Alo + (size_t)m0 * K;
    const __nv_bfloat16* srcB_hi = Bhi + (size_t)n0 * K;
    const __nv_bfloat16* srcB_lo = Blo + (size_t)n0 * K;

    // staging indices (per thread): 4 x 16B per tile
    int srow[4], scol[4];
    uint32_t soff[4];
#pragma unroll
    for (int i = 0; i < 4; i++) {
        int idx = i * 256 + tid;
        srow[i] = idx >> 3;
        scol[i] = idx & 7;
        soff[i] = sw128((uint32_t)(srow[i] * 128 + scol[i] * 16));
    }

#define STAGE_CHUNK(c)                                                            \
    do {                                                                          \
        uint32_t stg = b32 + ((c) & 1) * STAGE_B;                                 \
        int koff = (c) * 64;                                                      \
        _Pragma("unroll")                                                         \
        for (int i = 0; i < 4; i++) {                                             \
            size_t goff = (size_t)srow[i] * K + koff + scol[i] * 8;               \
            cpasync16(stg + 0 * TILE_B + soff[i], srcA_hi + goff);                \
            cpasync16(stg + 1 * TILE_B + soff[i], srcA_lo + goff);                \
            cpasync16(stg + 2 * TILE_B + soff[i], srcB_hi + goff);                \
            cpasync16(stg + 3 * TILE_B + soff[i], srcB_lo + goff);                \
        }                                                                         \
        CP_COMMIT();                                                              \
    } while (0)

    float acc[2][8][4];
#pragma unroll
    for (int mi = 0; mi < 2; mi++)
#pragma unroll
        for (int t = 0; t < 8; t++)
#pragma unroll
            for (int q = 0; q < 4; q++) acc[mi][t][q] = 0.f;

    // ldmatrix per-lane geometry
    int g  = lane >> 3;
    int li = lane & 7;
    int a_row0 = wm * 32 + (g & 1) * 8 + li;      // + mi*16
    int a_kb   = (g >> 1) * 16;
    int b_row0 = wn * 64 + (g >> 1) * 8 + li;     // + j*16
    int b_kb   = (g & 1) * 16;

    STAGE_CHUNK(0);

    for (int c = 0; c < nch; c++) {
        if (c + 1 < nch) { STAGE_CHUNK(c + 1); CP_WAIT(1); }
        else             { CP_WAIT(0); }
        __syncthreads();

        uint32_t stg = b32 + (c & 1) * STAGE_B;
        uint32_t aHiB = stg, aLoB = stg + TILE_B, bHiB = stg + 2 * TILE_B, bLoB = stg + 3 * TILE_B;

#pragma unroll
        for (int ks = 0; ks < 4; ks++) {
            uint32_t ah[2][4], al[2][4], bb[4][4];
#pragma unroll
            for (int mi = 0; mi < 2; mi++) {
                uint32_t off = sw128((uint32_t)((a_row0 + mi * 16) * 128 + ks * 32 + a_kb));
                ldm_x4(ah[mi], aHiB + off);
                ldm_x4(al[mi], aLoB + off);
            }
#pragma unroll
            for (int j = 0; j < 4; j++) {
                uint32_t off = sw128((uint32_t)((b_row0 + j * 16) * 128 + ks * 32 + b_kb));
                ldm_x4(bb[j], bHiB + off);
            }
#pragma unroll
            for (int mi = 0; mi < 2; mi++)
#pragma unroll
                for (int t = 0; t < 8; t++)
                    mma16816(acc[mi][t], ah[mi], &bb[t >> 1][(t & 1) * 2]);
#pragma unroll
            for (int mi = 0; mi < 2; mi++)
#pragma unroll
                for (int t = 0; t < 8; t++)
                    mma16816(acc[mi][t], al[mi], &bb[t >> 1][(t & 1) * 2]);
#pragma unroll
            for (int j = 0; j < 4; j++) {
                uint32_t off = sw128((uint32_t)((b_row0 + j * 16) * 128 + ks * 32 + b_kb));
                ldm_x4(bb[j], bLoB + off);
            }
#pragma unroll
            for (int mi = 0; mi < 2; mi++)
#pragma unroll
                for (int t = 0; t < 8; t++)
                    mma16816(acc[mi][t], ah[mi], &bb[t >> 1][(t & 1) * 2]);
        }
        __syncthreads();
    }

    // epilogue: thread holds C[r][n],C[r][n+1],C[r+8][n],C[r+8][n+1] per (mi,t)
    int r_base = m0 + wm * 32 + (lane >> 2);
    int n_base = n0 + wn * 64 + (lane & 3) * 2;
#pragma unroll
    for (int mi = 0; mi < 2; mi++) {
#pragma unroll
        for (int t = 0; t < 8; t++) {
            int r = r_base + mi * 16;
            int n = n_base + t * 8;
            float c0 = acc[mi][t][0], c1 = acc[mi][t][1];
            float c2 = acc[mi][t][2], c3 = acc[mi][t][3];
            if (EPI == 0) {
                float2 v0 = { c0, c1 }, v1 = { c2, c3 };
                *(float2*)(Cf + (size_t)r * N + n)       = v0;
                *(float2*)(Cf + (size_t)(r + 8) * N + n) = v1;
            } else if (EPI == 1) {
                float bi0 = bias[n], bi1 = bias[n + 1];
                float v0 = fmaxf(c0 + bi0, 0.f), v1 = fmaxf(c1 + bi1, 0.f);
                float v2 = fmaxf(c2 + bi0, 0.f), v3 = fmaxf(c3 + bi1, 0.f);
                __nv_bfloat16 h0, h1, h2, h3, l0, l1, l2, l3;
                split_bf16(v0, h0, l0); split_bf16(v1, h1, l1);
                split_bf16(v2, h2, l2); split_bf16(v3, h3, l3);
                *(__nv_bfloat162*)(Chi + (size_t)r * N + n)       = __halves2bfloat162(h0, h1);
                *(__nv_bfloat162*)(Clo + (size_t)r * N + n)       = __halves2bfloat162(l0, l1);
                *(__nv_bfloat162*)(Chi + (size_t)(r + 8) * N + n) = __halves2bfloat162(h2, h3);
                *(__nv_bfloat162*)(Clo + (size_t)(r + 8) * N + n) = __halves2bfloat162(l2, l3);
            } else {
                float bi0 = bias[n], bi1 = bias[n + 1];
                float2 r0 = *(const float2*)(res + (size_t)r * N + n);
                float2 r1 = *(const float2*)(res + (size_t)(r + 8) * N + n);
                float2 v0 = { c0 + bi0 + r0.x, c1 + bi1 + r0.y };
                float2 v1 = { c2 + bi0 + r1.x, c3 + bi1 + r1.y };
                *(float2*)(Cf + (size_t)r * N + n)       = v0;
                *(float2*)(Cf + (size_t)(r + 8) * N + n) = v1;
            }
        }
    }
#undef STAGE_CHUNK
}

// ---------------- Flash attention (causal), 64-query tiles (fp32) ----------------
__global__ __launch_bounds__(256) void attn_kernel(const float* __restrict__ qkv,
                                                   const float* __restrict__ x,
                                                   float* __restrict__ x1) {
    __shared__ float Ks[64 * 68];        // K tile (pitch 68); aliased as P (pitch 65)
    __shared__ float Vs[64 * 64];
    __shared__ float redm[4 * 64];
    __shared__ float reds[4 * 64];
    int qt = blockIdx.x;
    int bh = blockIdx.y;
    int b = bh >> 4, h = bh & 15;
    int tid = threadIdx.x;
    int part = tid >> 6;
    int row  = tid & 63;
    int qg = qt * 64 + row;

    const float* qptr = qkv + ((size_t)(b * TT + qg)) * 3072 + h * 64;
    float4 q4[16];
#pragma unroll
    for (int i = 0; i < 16; i++) {
        float4 v = ((const float4*)qptr)[i];
        v.x *= 0.03125f; v.y *= 0.03125f; v.z *= 0.03125f; v.w *= 0.03125f;
        q4[i] = v;
    }
    float4 O4[4];
#pragma unroll
    for (int i = 0; i < 4; i++) { O4[i].x = O4[i].y = O4[i].z = O4[i].w = 0.f; }
    float m = -1e30f, l = 0.f;

    for (int kt = 0; kt <= qt; ++kt) {
        __syncthreads();
        {
            int jr = tid >> 4;
            int c  = (tid & 15) << 2;
            const float* kbase = qkv + ((size_t)(b * TT + kt * 64)) * 3072 + 1024 + h * 64;
            const float* vbase = kbase + 1024;
#pragma unroll
            for (int it = 0; it < 4; ++it) {
                int j = jr + it * 16;
                *(float4*)&Ks[j * 68 + c] = *(const float4*)(kbase + (size_t)j * 3072 + c);
                *(float4*)&Vs[j * 64 + c] = *(const float4*)(vbase + (size_t)j * 3072 + c);
            }
        }
        __syncthreads();

        float s[16];
        float tm = -1e30f;
        int j0 = part * 16;
#pragma unroll
        for (int jj = 0; jj < 16; ++jj) {
            const float4* kr = (const float4*)&Ks[(j0 + jj) * 68];
            float acc = 0.f;
#pragma unroll
            for (int e = 0; e < 16; e++) {
                float4 kv = kr[e];
                acc += q4[e].x * kv.x + q4[e].y * kv.y + q4[e].z * kv.z + q4[e].w * kv.w;
            }
            if (kt == qt && (j0 + jj) > row) acc = -1e30f;
            s[jj] = acc;
            tm = fmaxf(tm, acc);
        }
        redm[part * 64 + row] = tm;
        __syncthreads();
        float mt = fmaxf(fmaxf(redm[row], redm[64 + row]),
                         fmaxf(redm[128 + row], redm[192 + row]));
        float mnew = fmaxf(m, mt);
        float sc = __expf(m - mnew);
        float ps = 0.f;
#pragma unroll
        for (int jj = 0; jj < 16; ++jj) {
            float p = __expf(s[jj] - mnew);
            Ks[row * 65 + j0 + jj] = p;
            ps += p;
        }
        reds[part * 64 + row] = ps;
        __syncthreads();
        float rs = reds[row] + reds[64 + row] + reds[128 + row] + reds[192 + row];
        l = l * sc + rs;
        m = mnew;
#pragma unroll
        for (int i = 0; i < 4; i++) { O4[i].x *= sc; O4[i].y *= sc; O4[i].z *= sc; O4[i].w *= sc; }
#pragma unroll 8
        for (int j = 0; j < 64; ++j) {
            float p = Ks[row * 65 + j];
            const float4* vr = (const float4*)&Vs[j * 64 + part * 16];
#pragma unroll
            for (int i = 0; i < 4; i++) {
                float4 vv = vr[i];
                O4[i].x += p * vv.x; O4[i].y += p * vv.y;
                O4[i].z += p * vv.z; O4[i].w += p * vv.w;
            }
        }
    }

    float inv = 1.f / l;
    size_t ob = ((size_t)(b * TT + qg)) * DD + h * 64 + part * 16;
    const float4* xr = (const float4*)(x + ob);
    float4* orow = (float4*)(x1 + ob);
#pragma unroll
    for (int i = 0; i < 4; i++) {
        float4 xv = xr[i];
        float4 ov;
        ov.x = xv.x + O4[i].x * inv;
        ov.y = xv.y + O4[i].y * inv;
        ov.z = xv.z + O4[i].z * inv;
        ov.w = xv.w + O4[i].w * inv;
        orow[i] = ov;
    }
}

// ---------------- launch ----------------
extern "C" void kernel_launch(void* const* d_in, const int* in_sizes, int n_in,
                              void* d_out, int out_size) {
    const float* x      = (const float*)d_in[0];
    const float* Wq     = (const float*)d_in[1];
    const float* Wk     = (const float*)d_in[2];
    const float* Wv     = (const float*)d_in[3];
    const float* W1     = (const float*)d_in[4];
    const float* b1     = (const float*)d_in[5];
    const float* W2     = (const float*)d_in[6];
    const float* b2     = (const float*)d_in[7];
    const float* gamma1 = (const float*)d_in[8];
    const float* beta1  = (const float*)d_in[9];
    const float* gamma2 = (const float*)d_in[10];
    const float* beta2  = (const float*)d_in[11];
    float* out = (float*)d_out;

    __nv_bfloat16 *a_hi, *a_lo, *wqkv_hi, *wqkv_lo, *w1_hi, *w1_lo, *w2_hi, *w2_lo, *f_hi, *f_lo;
    float *qkv, *x1;
    cudaGetSymbolAddress((void**)&a_hi, g_a_hi);
    cudaGetSymbolAddress((void**)&a_lo, g_a_lo);
    cudaGetSymbolAddress((void**)&wqkv_hi, g_wqkv_hi);
    cudaGetSymbolAddress((void**)&wqkv_lo, g_wqkv_lo);
    cudaGetSymbolAddress((void**)&w1_hi, g_w1_hi);
    cudaGetSymbolAddress((void**)&w1_lo, g_w1_lo);
    cudaGetSymbolAddress((void**)&w2_hi, g_w2_hi);
    cudaGetSymbolAddress((void**)&w2_lo, g_w2_lo);
    cudaGetSymbolAddress((void**)&f_hi, g_ff1_hi);
    cudaGetSymbolAddress((void**)&f_lo, g_ff1_lo);
    cudaGetSymbolAddress((void**)&qkv, g_qkv);
    cudaGetSymbolAddress((void**)&x1, g_x1);

    cudaFuncSetAttribute(hmma_gemm_kernel<0>, cudaFuncAttributeMaxDynamicSharedMemorySize, DSM_B);
    cudaFuncSetAttribute(hmma_gemm_kernel<1>, cudaFuncAttributeMaxDynamicSharedMemorySize, DSM_B);
    cudaFuncSetAttribute(hmma_gemm_kernel<2>, cudaFuncAttributeMaxDynamicSharedMemorySize, DSM_B);

    // 1. LN1 -> bf16 hi/lo
    ln_bf16_kernel<<<MM, 256>>>(x, gamma1, beta1, a_hi, a_lo);
    // 2. weight repacks (transpose + bf16 split)
    repack_qkv_kernel<<<(3 * DD * DD) / 256, 256>>>(Wq, Wk, Wv, wqkv_hi, wqkv_lo);
    transpose_bf16_kernel<<<dim3(DFF / 32, DD / 32), dim3(32, 8)>>>(W1, w1_hi, w1_lo, DD, DFF);
    transpose_bf16_kernel<<<dim3(DD / 32, DFF / 32), dim3(32, 8)>>>(W2, w2_hi, w2_lo, DFF, DD);
    // 3. QKV projection (HMMA): [4096,1024] x [1024,3072] -> fp32
    hmma_gemm_kernel<0><<<dim3(3 * DD / 128, MM / 128), 256, DSM_B>>>(
        a_hi, a_lo, wqkv_hi, wqkv_lo, DD, 3 * DD, qkv, nullptr, nullptr, nullptr, nullptr);
    // 4. attention + residual -> x1
    attn_kernel<<<dim3(TT / 64, BB * HH), 256>>>(qkv, x, x1);
    // 5. LN2 -> bf16 hi/lo (reuse buffers)
    ln_bf16_kernel<<<MM, 256>>>(x1, gamma2, beta2, a_hi, a_lo);
    // 6. FFN1 (HMMA): relu(h2 @ W1 + b1) -> bf16 hi/lo
    hmma_gemm_kernel<1><<<dim3(DFF / 128, MM / 128), 256, DSM_B>>>(
        a_hi, a_lo, w1_hi, w1_lo, DD, DFF, nullptr, f_hi, f_lo, b1, nullptr);
    // 7. FFN2 (HMMA): ff1 @ W2 + b2 + x1 -> out
    hmma_gemm_kernel<2><<<dim3(DD / 128, MM / 128), 256, DSM_B>>>(
        f_hi, f_lo, w2_hi, w2_lo, DFF, DD, out, nullptr, nullptr, b2, x1);
}

// round 6
// speedup vs baseline: 3.2029x; 1.6379x over previous
#include <cuda_runtime.h>
#include <cuda_bf16.h>
#include <cstdint>

// Problem constants
#define DD    1024
#define HH    16
#define DHD   64
#define DFF   4096
#define TT    2048
#define BB    2
#define MM    4096   // B*T

// ---------------- scratch (device globals; no allocation) ----------------
__device__ __nv_bfloat16 g_a_hi[MM * DD], g_a_lo[MM * DD];          // LN out hi/lo (reused LN1/LN2)
__device__ __nv_bfloat16 g_wqkv_hi[3 * DD * DD], g_wqkv_lo[3 * DD * DD];  // [N=3072,K=1024]
__device__ __nv_bfloat16 g_w1_hi[DFF * DD], g_w1_lo[DFF * DD];      // [N=4096,K=1024]
__device__ __nv_bfloat16 g_w2_hi[DD * DFF], g_w2_lo[DD * DFF];      // [N=1024,K=4096]
__device__ __nv_bfloat16 g_ff1_hi[(size_t)MM * DFF], g_ff1_lo[(size_t)MM * DFF];
__device__ __nv_bfloat16 g_qkv_hi[(size_t)MM * 3 * DD], g_qkv_lo[(size_t)MM * 3 * DD];
__device__ float g_x1 [MM * DD];

// ---------------- helpers ----------------
static __device__ __forceinline__ uint32_t su32(const void* p) {
    uint32_t a;
    asm("{ .reg .u64 t; cvta.to.shared.u64 t, %1; cvt.u32.u64 %0, t; }" : "=r"(a) : "l"(p));
    return a;
}
static __device__ __forceinline__ uint32_t sw128(uint32_t off) {
    return off ^ ((off >> 3) & 0x70);
}
static __device__ __forceinline__ void cpasync16(uint32_t dst, const void* src) {
    asm volatile("cp.async.cg.shared.global [%0], [%1], 16;" :: "r"(dst), "l"(src));
}
#define CP_COMMIT()  asm volatile("cp.async.commit_group;" ::: "memory")
#define CP_WAIT(n)   asm volatile("cp.async.wait_group %0;" :: "n"(n) : "memory")

static __device__ __forceinline__ void ldm_x4(uint32_t* r, uint32_t addr) {
    asm volatile("ldmatrix.sync.aligned.m8n8.x4.shared.b16 {%0,%1,%2,%3}, [%4];"
                 : "=r"(r[0]), "=r"(r[1]), "=r"(r[2]), "=r"(r[3]) : "r"(addr));
}
static __device__ __forceinline__ void ldm_x4t(uint32_t* r, uint32_t addr) {
    asm volatile("ldmatrix.sync.aligned.m8n8.x4.trans.shared.b16 {%0,%1,%2,%3}, [%4];"
                 : "=r"(r[0]), "=r"(r[1]), "=r"(r[2]), "=r"(r[3]) : "r"(addr));
}
static __device__ __forceinline__ void mma16816(float* d, const uint32_t* a, const uint32_t* b) {
    asm volatile(
        "mma.sync.aligned.m16n8k16.row.col.f32.bf16.bf16.f32 "
        "{%0,%1,%2,%3}, {%4,%5,%6,%7}, {%8,%9}, {%0,%1,%2,%3};"
        : "+f"(d[0]), "+f"(d[1]), "+f"(d[2]), "+f"(d[3])
        : "r"(a[0]), "r"(a[1]), "r"(a[2]), "r"(a[3]), "r"(b[0]), "r"(b[1]));
}
static __device__ __forceinline__ void split_bf16(float v, __nv_bfloat16& h, __nv_bfloat16& l) {
    h = __float2bfloat16(v);
    l = __float2bfloat16(v - __bfloat162float(h));
}
static __device__ __forceinline__ uint32_t packbf(float a, float b) {
    __nv_bfloat162 t = __halves2bfloat162(__float2bfloat16(a), __float2bfloat16(b));
    return *reinterpret_cast<uint32_t*>(&t);
}

// ---------------- LayerNorm (ddof=1), bf16 hi/lo output ----------------
__global__ __launch_bounds__(256) void ln_bf16_kernel(const float* __restrict__ x,
                                                      const float* __restrict__ g,
                                                      const float* __restrict__ bta,
                                                      __nv_bfloat16* __restrict__ ohi,
                                                      __nv_bfloat16* __restrict__ olo) {
    int row = blockIdx.x;
    int tid = threadIdx.x;
    const float4* xr = (const float4*)(x + (size_t)row * DD);
    float4 v = xr[tid];
    float s  = v.x + v.y + v.z + v.w;
    float sq = v.x * v.x + v.y * v.y + v.z * v.z + v.w * v.w;
#pragma unroll
    for (int o = 16; o; o >>= 1) {
        s  += __shfl_xor_sync(0xffffffffu, s,  o);
        sq += __shfl_xor_sync(0xffffffffu, sq, o);
    }
    __shared__ float ss[8], sqs[8];
    int w = tid >> 5, ln = tid & 31;
    if (ln == 0) { ss[w] = s; sqs[w] = sq; }
    __syncthreads();
    s = 0.f; sq = 0.f;
#pragma unroll
    for (int i = 0; i < 8; i++) { s += ss[i]; sq += sqs[i]; }
    float mean = s * (1.f / 1024.f);
    float var  = (sq - 1024.f * mean * mean) * (1.f / 1023.f);
    float r    = rsqrtf(var + 1e-5f);
    float4 gv = ((const float4*)g)[tid];
    float4 bv = ((const float4*)bta)[tid];
    float o0 = gv.x * (v.x - mean) * r + bv.x;
    float o1 = gv.y * (v.y - mean) * r + bv.y;
    float o2 = gv.z * (v.z - mean) * r + bv.z;
    float o3 = gv.w * (v.w - mean) * r + bv.w;
    __nv_bfloat16 h0, h1, h2, h3, l0, l1, l2, l3;
    split_bf16(o0, h0, l0); split_bf16(o1, h1, l1);
    split_bf16(o2, h2, l2); split_bf16(o3, h3, l3);
    __nv_bfloat162* hp = (__nv_bfloat162*)(ohi + (size_t)row * DD);
    __nv_bfloat162* lp = (__nv_bfloat162*)(olo + (size_t)row * DD);
    hp[tid * 2]     = __halves2bfloat162(h0, h1);
    hp[tid * 2 + 1] = __halves2bfloat162(h2, h3);
    lp[tid * 2]     = __halves2bfloat162(l0, l1);
    lp[tid * 2 + 1] = __halves2bfloat162(l2, l3);
}

// ---------------- repack Wq/Wk/Wv [H,D,DH] -> [N=3072, K=1024] bf16 hi/lo ----------------
__global__ __launch_bounds__(256) void repack_qkv_kernel(const float* __restrict__ Wq,
                                                         const float* __restrict__ Wk,
                                                         const float* __restrict__ Wv,
                                                         __nv_bfloat16* __restrict__ ohi,
                                                         __nv_bfloat16* __restrict__ olo) {
    int idx = blockIdx.x * 256 + threadIdx.x;     // over 3072*1024, n*1024 + k
    int n = idx >> 10;
    int k = idx & 1023;
    int w = n >> 10;
    int h = (n >> 6) & 15;
    int e = n & 63;
    const float* W = (w == 0) ? Wq : ((w == 1) ? Wk : Wv);
    float v = W[h * (DD * DHD) + k * DHD + e];
    __nv_bfloat16 hi, lo;
    split_bf16(v, hi, lo);
    ohi[idx] = hi;
    olo[idx] = lo;
}

// ---------------- tiled transpose+convert: in [Kd, Nd] fp32 -> out [Nd, Kd] bf16 hi/lo ----------------
__global__ __launch_bounds__(256) void transpose_bf16_kernel(const float* __restrict__ in,
                                                             __nv_bfloat16* __restrict__ ohi,
                                                             __nv_bfloat16* __restrict__ olo,
                                                             int Kd, int Nd) {
    __shared__ float t[32][33];
    int nt = blockIdx.x * 32, kt = blockIdx.y * 32;
    int tx = threadIdx.x, ty = threadIdx.y;   // 32 x 8
#pragma unroll
    for (int i = 0; i < 32; i += 8)
        t[ty + i][tx] = in[(size_t)(kt + ty + i) * Nd + nt + tx];
    __syncthreads();
#pragma unroll
    for (int i = 0; i < 32; i += 8) {
        float v = t[tx][ty + i];
        __nv_bfloat16 hi, lo;
        split_bf16(v, hi, lo);
        size_t o = (size_t)(nt + ty + i) * Kd + kt + tx;
        ohi[o] = hi;
        olo[o] = lo;
    }
}

// ---------------- HMMA bf16-split GEMM: C[M,N] = A[M,K] * B'[N,K]^T ----------------
// EPI: 0 = fp32 store  1 = relu(+bias)->bf16 hi/lo  2 = +bias+residual->fp32  3 = bf16 hi/lo
#define TILE_B   16384          // 128 rows x 64 bf16 (128B/row)
#define STAGE_B  (4 * TILE_B)   // Ahi | Alo | Bhi | Blo
#define DSM_B    (2 * STAGE_B + 1024)

template <int EPI>
__global__ __launch_bounds__(256, 1) void hmma_gemm_kernel(const __nv_bfloat16* __restrict__ Ahi,
                                                           const __nv_bfloat16* __restrict__ Alo,
                                                           const __nv_bfloat16* __restrict__ Bhi,
                                                           const __nv_bfloat16* __restrict__ Blo,
                                                           int K, int N,
                                                           float* __restrict__ Cf,
                                                           __nv_bfloat16* __restrict__ Chi,
                                                           __nv_bfloat16* __restrict__ Clo,
                                                           const float* __restrict__ bias,
                                                           const float* __restrict__ res) {
    extern __shared__ __align__(16) char dsm[];
    int tid  = threadIdx.x;
    int wid  = tid >> 5;
    int lane = tid & 31;
    int wm = wid & 3;
    int wn = wid >> 2;

    uint32_t b32 = su32(dsm);
    uint32_t pad = (1024u - (b32 & 1023u)) & 1023u;
    b32 += pad;

    const int m0 = blockIdx.y * 128;
    const int n0 = blockIdx.x * 128;
    const int nch = K >> 6;

    const __nv_bfloat16* srcA_hi = Ahi + (size_t)m0 * K;
    const __nv_bfloat16* srcA_lo = Alo + (size_t)m0 * K;
    const __nv_bfloat16* srcB_hi = Bhi + (size_t)n0 * K;
    const __nv_bfloat16* srcB_lo = Blo + (size_t)n0 * K;

    int srow[4], scol[4];
    uint32_t soff[4];
#pragma unroll
    for (int i = 0; i < 4; i++) {
        int idx = i * 256 + tid;
        srow[i] = idx >> 3;
        scol[i] = idx & 7;
        soff[i] = sw128((uint32_t)(srow[i] * 128 + scol[i] * 16));
    }

#define STAGE_CHUNK(c)                                                            \
    do {                                                                          \
        uint32_t stg = b32 + ((c) & 1) * STAGE_B;                                 \
        int koff = (c) * 64;                                                      \
        _Pragma("unroll")                                                         \
        for (int i = 0; i < 4; i++) {                                             \
            size_t goff = (size_t)srow[i] * K + koff + scol[i] * 8;               \
            cpasync16(stg + 0 * TILE_B + soff[i], srcA_hi + goff);                \
            cpasync16(stg + 1 * TILE_B + soff[i], srcA_lo + goff);                \
            cpasync16(stg + 2 * TILE_B + soff[i], srcB_hi + goff);                \
            cpasync16(stg + 3 * TILE_B + soff[i], srcB_lo + goff);                \
        }                                                                         \
        CP_COMMIT();                                                              \
    } while (0)

    float acc[2][8][4];
#pragma unroll
    for (int mi = 0; mi < 2; mi++)
#pragma unroll
        for (int t = 0; t < 8; t++)
#pragma unroll
            for (int q = 0; q < 4; q++) acc[mi][t][q] = 0.f;

    int g  = lane >> 3;
    int li = lane & 7;
    int a_row0 = wm * 32 + (g & 1) * 8 + li;
    int a_kb   = (g >> 1) * 16;
    int b_row0 = wn * 64 + (g >> 1) * 8 + li;
    int b_kb   = (g & 1) * 16;

    STAGE_CHUNK(0);

    for (int c = 0; c < nch; c++) {
        if (c + 1 < nch) { STAGE_CHUNK(c + 1); CP_WAIT(1); }
        else             { CP_WAIT(0); }
        __syncthreads();

        uint32_t stg = b32 + (c & 1) * STAGE_B;
        uint32_t aHiB = stg, aLoB = stg + TILE_B, bHiB = stg + 2 * TILE_B, bLoB = stg + 3 * TILE_B;

#pragma unroll
        for (int ks = 0; ks < 4; ks++) {
            uint32_t ah[2][4], al[2][4], bb[4][4];
#pragma unroll
            for (int mi = 0; mi < 2; mi++) {
                uint32_t off = sw128((uint32_t)((a_row0 + mi * 16) * 128 + ks * 32 + a_kb));
                ldm_x4(ah[mi], aHiB + off);
                ldm_x4(al[mi], aLoB + off);
            }
#pragma unroll
            for (int j = 0; j < 4; j++) {
                uint32_t off = sw128((uint32_t)((b_row0 + j * 16) * 128 + ks * 32 + b_kb));
                ldm_x4(bb[j], bHiB + off);
            }
#pragma unroll
            for (int mi = 0; mi < 2; mi++)
#pragma unroll
                for (int t = 0; t < 8; t++)
                    mma16816(acc[mi][t], ah[mi], &bb[t >> 1][(t & 1) * 2]);
#pragma unroll
            for (int mi = 0; mi < 2; mi++)
#pragma unroll
                for (int t = 0; t < 8; t++)
                    mma16816(acc[mi][t], al[mi], &bb[t >> 1][(t & 1) * 2]);
#pragma unroll
            for (int j = 0; j < 4; j++) {
                uint32_t off = sw128((uint32_t)((b_row0 + j * 16) * 128 + ks * 32 + b_kb));
                ldm_x4(bb[j], bLoB + off);
            }
#pragma unroll
            for (int mi = 0; mi < 2; mi++)
#pragma unroll
                for (int t = 0; t < 8; t++)
                    mma16816(acc[mi][t], ah[mi], &bb[t >> 1][(t & 1) * 2]);
        }
        __syncthreads();
    }

    int r_base = m0 + wm * 32 + (lane >> 2);
    int n_base = n0 + wn * 64 + (lane & 3) * 2;
#pragma unroll
    for (int mi = 0; mi < 2; mi++) {
#pragma unroll
        for (int t = 0; t < 8; t++) {
            int r = r_base + mi * 16;
            int n = n_base + t * 8;
            float c0 = acc[mi][t][0], c1 = acc[mi][t][1];
            float c2 = acc[mi][t][2], c3 = acc[mi][t][3];
            if (EPI == 0) {
                float2 v0 = { c0, c1 }, v1 = { c2, c3 };
                *(float2*)(Cf + (size_t)r * N + n)       = v0;
                *(float2*)(Cf + (size_t)(r + 8) * N + n) = v1;
            } else if (EPI == 1 || EPI == 3) {
                float v0 = c0, v1 = c1, v2 = c2, v3 = c3;
                if (EPI == 1) {
                    float bi0 = bias[n], bi1 = bias[n + 1];
                    v0 = fmaxf(v0 + bi0, 0.f); v1 = fmaxf(v1 + bi1, 0.f);
                    v2 = fmaxf(v2 + bi0, 0.f); v3 = fmaxf(v3 + bi1, 0.f);
                }
                __nv_bfloat16 h0, h1, h2, h3, l0, l1, l2, l3;
                split_bf16(v0, h0, l0); split_bf16(v1, h1, l1);
                split_bf16(v2, h2, l2); split_bf16(v3, h3, l3);
                *(__nv_bfloat162*)(Chi + (size_t)r * N + n)       = __halves2bfloat162(h0, h1);
                *(__nv_bfloat162*)(Clo + (size_t)r * N + n)       = __halves2bfloat162(l0, l1);
                *(__nv_bfloat162*)(Chi + (size_t)(r + 8) * N + n) = __halves2bfloat162(h2, h3);
                *(__nv_bfloat162*)(Clo + (size_t)(r + 8) * N + n) = __halves2bfloat162(l2, l3);
            } else {
                float bi0 = bias[n], bi1 = bias[n + 1];
                float2 r0 = *(const float2*)(res + (size_t)r * N + n);
                float2 r1 = *(const float2*)(res + (size_t)(r + 8) * N + n);
                float2 v0 = { c0 + bi0 + r0.x, c1 + bi1 + r0.y };
                float2 v1 = { c2 + bi0 + r1.x, c3 + bi1 + r1.y };
                *(float2*)(Cf + (size_t)r * N + n)       = v0;
                *(float2*)(Cf + (size_t)(r + 8) * N + n) = v1;
            }
        }
    }
#undef STAGE_CHUNK
}

// ---------------- HMMA flash attention (causal) ----------------
// 128-query CTA tile, 64-key tiles. 8 warps x 16 q-rows. QK: 3-term split.
// PV: (Phi+Plo) * Vhi, P stays in registers (S frag == A frag layout).
// smem stage: Khi[8K] | Klo[8K] | Vhi[8K] = 24KB, double-buffered.
#define AT_STAGE 24576
#define AT_DSM   (2 * AT_STAGE + 1024)

__global__ __launch_bounds__(256, 1) void attn_hmma_kernel(const __nv_bfloat16* __restrict__ qkv_hi,
                                                           const __nv_bfloat16* __restrict__ qkv_lo,
                                                           const float* __restrict__ x,
                                                           float* __restrict__ x1) {
    extern __shared__ __align__(16) char dsm[];
    int tid  = threadIdx.x;
    int wid  = tid >> 5;
    int lane = tid & 31;
    int g  = lane >> 3;
    int li = lane & 7;
    int gr = lane >> 2;
    int gc = lane & 3;

    uint32_t b32 = su32(dsm);
    uint32_t pad = (1024u - (b32 & 1023u)) & 1023u;
    b32 += pad;

    int qt = gridDim.x - 1 - blockIdx.x;     // big tiles first
    int bh = blockIdx.y;
    int b = bh >> 4, h = bh & 15;
    int qbase = qt * 128;

    const __nv_bfloat16* qh_g = qkv_hi + (size_t)b * TT * 3072;
    const __nv_bfloat16* ql_g = qkv_lo + (size_t)b * TT * 3072;

    // ---- stage Q (hi at b32, lo at b32+16384), ldmatrix to regs ----
#pragma unroll
    for (int i = 0; i < 4; i++) {
        int idx = i * 256 + tid;
        int row = idx >> 3;
        int col = idx & 7;
        uint32_t so = sw128((uint32_t)(row * 128 + col * 16));
        size_t go = (size_t)(qbase + row) * 3072 + h * 64 + col * 8;
        cpasync16(b32 + so,         qh_g + go);
        cpasync16(b32 + 16384 + so, ql_g + go);
    }
    CP_COMMIT();
    CP_WAIT(0);
    __syncthreads();

    uint32_t qfh[4][4], qfl[4][4];
    {
        int a_row = wid * 16 + (g & 1) * 8 + li;
        int a_kb  = (g >> 1) * 16;
#pragma unroll
        for (int ks = 0; ks < 4; ks++) {
            uint32_t off = sw128((uint32_t)(a_row * 128 + ks * 32 + a_kb));
            ldm_x4(qfh[ks], b32 + off);
            ldm_x4(qfl[ks], b32 + 16384 + off);
        }
    }
    __syncthreads();   // Q regs done; smem free for K/V stages

    float m0f = -1e30f, m1f = -1e30f, l0f = 0.f, l1f = 0.f;
    float acc_o[8][4];
#pragma unroll
    for (int t = 0; t < 8; t++)
#pragma unroll
        for (int q = 0; q < 4; q++) acc_o[t][q] = 0.f;

    const int kts = 2 * qt + 2;
    const int wrow_min = qbase + wid * 16;
    const int wrow_max = wrow_min + 15;
    const int b_row = (g >> 1) * 8 + li;
    const int b_kb  = (g & 1) * 16;

#define STAGE_KV(c)                                                                     \
    do {                                                                                \
        uint32_t stg = b32 + ((c) & 1) * AT_STAGE;                                      \
        const __nv_bfloat16* kh_g = qh_g + (size_t)((c) * 64) * 3072 + 1024 + h * 64;   \
        const __nv_bfloat16* kl_g = ql_g + (size_t)((c) * 64) * 3072 + 1024 + h * 64;   \
        _Pragma("unroll")                                                               \
        for (int i = 0; i < 2; i++) {                                                   \
            int idx = i * 256 + tid;                                                    \
            int row = idx >> 3;                                                         \
            int col = idx & 7;                                                          \
            uint32_t so = sw128((uint32_t)(row * 128 + col * 16));                      \
            size_t go = (size_t)row * 3072 + col * 8;                                   \
            cpasync16(stg + so,          kh_g + go);                                    \
            cpasync16(stg + 8192 + so,   kl_g + go);                                    \
            cpasync16(stg + 16384 + so,  kh_g + 1024 + go);                             \
        }                                                                               \
        CP_COMMIT();                                                                    \
    } while (0)

    STAGE_KV(0);

    for (int kt = 0; kt < kts; kt++) {
        if (kt + 1 < kts) { STAGE_KV(kt + 1); CP_WAIT(1); }
        else              { CP_WAIT(0); }
        __syncthreads();

        if (kt * 64 <= wrow_max) {
            uint32_t stg = b32 + (kt & 1) * AT_STAGE;
            uint32_t khB = stg, klB = stg + 8192, vhB = stg + 16384;

            float sacc[8][4];
#pragma unroll
            for (int t = 0; t < 8; t++)
#pragma unroll
                for (int q = 0; q < 4; q++) sacc[t][q] = 0.f;

#pragma unroll
            for (int ks = 0; ks < 4; ks++) {
#pragma unroll
                for (int j = 0; j < 4; j++) {
                    uint32_t off = sw128((uint32_t)((j * 16 + b_row) * 128 + ks * 32 + b_kb));
                    uint32_t kb[4];
                    ldm_x4(kb, khB + off);
                    mma16816(sacc[2 * j],     qfh[ks], kb);
                    mma16816(sacc[2 * j + 1], qfh[ks], kb + 2);
                    mma16816(sacc[2 * j],     qfl[ks], kb);
                    mma16816(sacc[2 * j + 1], qfl[ks], kb + 2);
                    ldm_x4(kb, klB + off);
                    mma16816(sacc[2 * j],     qfh[ks], kb);
                    mma16816(sacc[2 * j + 1], qfh[ks], kb + 2);
                }
            }

            // scale + causal mask
            int row0 = wrow_min + gr;
            bool domask = (kt * 64 + 63) > wrow_min;
#pragma unroll
            for (int t = 0; t < 8; t++) {
                int colb = kt * 64 + t * 8 + gc * 2;
#pragma unroll
                for (int q = 0; q < 4; q++) {
                    float s = sacc[t][q] * 0.03125f;
                    if (domask) {
                        int col = colb + (q & 1);
                        int row = row0 + ((q >> 1) << 3);
                        if (col > row) s = -1e30f;
                    }
                    sacc[t][q] = s;
                }
            }
            // row max
            float tm0 = -1e30f, tm1 = -1e30f;
#pragma unroll
            for (int t = 0; t < 8; t++) {
                tm0 = fmaxf(tm0, fmaxf(sacc[t][0], sacc[t][1]));
                tm1 = fmaxf(tm1, fmaxf(sacc[t][2], sacc[t][3]));
            }
#pragma unroll
            for (int o = 1; o <= 2; o <<= 1) {
                tm0 = fmaxf(tm0, __shfl_xor_sync(0xffffffffu, tm0, o));
                tm1 = fmaxf(tm1, __shfl_xor_sync(0xffffffffu, tm1, o));
            }
            float mn0 = fmaxf(m0f, tm0), mn1 = fmaxf(m1f, tm1);
            float sc0 = __expf(m0f - mn0), sc1 = __expf(m1f - mn1);
            m0f = mn0; m1f = mn1;
            // exp + row sum
            float ls0 = 0.f, ls1 = 0.f;
#pragma unroll
            for (int t = 0; t < 8; t++) {
                float p0 = __expf(sacc[t][0] - mn0);
                float p1 = __expf(sacc[t][1] - mn0);
                float p2 = __expf(sacc[t][2] - mn1);
                float p3 = __expf(sacc[t][3] - mn1);
                sacc[t][0] = p0; sacc[t][1] = p1; sacc[t][2] = p2; sacc[t][3] = p3;
                ls0 += p0 + p1; ls1 += p2 + p3;
            }
#pragma unroll
            for (int o = 1; o <= 2; o <<= 1) {
                ls0 += __shfl_xor_sync(0xffffffffu, ls0, o);
                ls1 += __shfl_xor_sync(0xffffffffu, ls1, o);
            }
            l0f = l0f * sc0 + ls0;
            l1f = l1f * sc1 + ls1;
#pragma unroll
            for (int t = 0; t < 8; t++) {
                acc_o[t][0] *= sc0; acc_o[t][1] *= sc0;
                acc_o[t][2] *= sc1; acc_o[t][3] *= sc1;
            }
            // PV: (Phi + Plo) * Vhi
#pragma unroll
            for (int ks = 0; ks < 4; ks++) {
                float* p0 = sacc[2 * ks];
                float* p1 = sacc[2 * ks + 1];
                uint32_t ah[4], al[4];
                ah[0] = packbf(p0[0], p0[1]);
                ah[1] = packbf(p0[2], p0[3]);
                ah[2] = packbf(p1[0], p1[1]);
                ah[3] = packbf(p1[2], p1[3]);
                {
                    __nv_bfloat162 t0 = *reinterpret_cast<__nv_bfloat162*>(&ah[0]);
                    __nv_bfloat162 t1 = *reinterpret_cast<__nv_bfloat162*>(&ah[1]);
                    __nv_bfloat162 t2 = *reinterpret_cast<__nv_bfloat162*>(&ah[2]);
                    __nv_bfloat162 t3 = *reinterpret_cast<__nv_bfloat162*>(&ah[3]);
                    al[0] = packbf(p0[0] - __bfloat162float(t0.x), p0[1] - __bfloat162float(t0.y));
                    al[1] = packbf(p0[2] - __bfloat162float(t1.x), p0[3] - __bfloat162float(t1.y));
                    al[2] = packbf(p1[0] - __bfloat162float(t2.x), p1[1] - __bfloat162float(t2.y));
                    al[3] = packbf(p1[2] - __bfloat162float(t3.x), p1[3] - __bfloat162float(t3.y));
                }
#pragma unroll
                for (int dj = 0; dj < 4; dj++) {
                    // V trans ldmatrix: 16k x 16d
                    int krow = ks * 16 + (g & 1) * 8 + li;
                    int dcol = dj * 16 + (g >> 1) * 8;
                    uint32_t off = sw128((uint32_t)(krow * 128 + dcol * 2));
                    uint32_t vb[4];
                    ldm_x4t(vb, vhB + off);
                    mma16816(acc_o[2 * dj],     ah, vb);
                    mma16816(acc_o[2 * dj + 1], ah, vb + 2);
                    mma16816(acc_o[2 * dj],     al, vb);
                    mma16816(acc_o[2 * dj + 1], al, vb + 2);
                }
            }
        }
        __syncthreads();
    }

    // epilogue: out = x + O/l
    float inv0 = 1.f / l0f, inv1 = 1.f / l1f;
    int r0 = b * TT + wrow_min + gr;
    int r1 = r0 + 8;
    int cb = h * 64 + gc * 2;
#pragma unroll
    for (int dj = 0; dj < 8; dj++) {
        int col = cb + dj * 8;
        float2 x0 = *(const float2*)(x + (size_t)r0 * DD + col);
        float2 x1v = *(const float2*)(x + (size_t)r1 * DD + col);
        float2 o0 = { acc_o[dj][0] * inv0 + x0.x,  acc_o[dj][1] * inv0 + x0.y };
        float2 o1 = { acc_o[dj][2] * inv1 + x1v.x, acc_o[dj][3] * inv1 + x1v.y };
        *(float2*)(x1 + (size_t)r0 * DD + col) = o0;
        *(float2*)(x1 + (size_t)r1 * DD + col) = o1;
    }
#undef STAGE_KV
}

// ---------------- launch ----------------
extern "C" void kernel_launch(void* const* d_in, const int* in_sizes, int n_in,
                              void* d_out, int out_size) {
    const float* x      = (const float*)d_in[0];
    const float* Wq     = (const float*)d_in[1];
    const float* Wk     = (const float*)d_in[2];
    const float* Wv     = (const float*)d_in[3];
    const float* W1     = (const float*)d_in[4];
    const float* b1     = (const float*)d_in[5];
    const float* W2     = (const float*)d_in[6];
    const float* b2     = (const float*)d_in[7];
    const float* gamma1 = (const float*)d_in[8];
    const float* beta1  = (const float*)d_in[9];
    const float* gamma2 = (const float*)d_in[10];
    const float* beta2  = (const float*)d_in[11];
    float* out = (float*)d_out;

    __nv_bfloat16 *a_hi, *a_lo, *wqkv_hi, *wqkv_lo, *w1_hi, *w1_lo, *w2_hi, *w2_lo, *f_hi, *f_lo;
    __nv_bfloat16 *qkv_hi, *qkv_lo;
    float *x1;
    cudaGetSymbolAddress((void**)&a_hi, g_a_hi);
    cudaGetSymbolAddress((void**)&a_lo, g_a_lo);
    cudaGetSymbolAddress((void**)&wqkv_hi, g_wqkv_hi);
    cudaGetSymbolAddress((void**)&wqkv_lo, g_wqkv_lo);
    cudaGetSymbolAddress((void**)&w1_hi, g_w1_hi);
    cudaGetSymbolAddress((void**)&w1_lo, g_w1_lo);
    cudaGetSymbolAddress((void**)&w2_hi, g_w2_hi);
    cudaGetSymbolAddress((void**)&w2_lo, g_w2_lo);
    cudaGetSymbolAddress((void**)&f_hi, g_ff1_hi);
    cudaGetSymbolAddress((void**)&f_lo, g_ff1_lo);
    cudaGetSymbolAddress((void**)&qkv_hi, g_qkv_hi);
    cudaGetSymbolAddress((void**)&qkv_lo, g_qkv_lo);
    cudaGetSymbolAddress((void**)&x1, g_x1);

    cudaFuncSetAttribute(hmma_gemm_kernel<1>, cudaFuncAttributeMaxDynamicSharedMemorySize, DSM_B);
    cudaFuncSetAttribute(hmma_gemm_kernel<2>, cudaFuncAttributeMaxDynamicSharedMemorySize, DSM_B);
    cudaFuncSetAttribute(hmma_gemm_kernel<3>, cudaFuncAttributeMaxDynamicSharedMemorySize, DSM_B);
    cudaFuncSetAttribute(attn_hmma_kernel, cudaFuncAttributeMaxDynamicSharedMemorySize, AT_DSM);

    // 1. LN1 -> bf16 hi/lo
    ln_bf16_kernel<<<MM, 256>>>(x, gamma1, beta1, a_hi, a_lo);
    // 2. weight repacks (transpose + bf16 split)
    repack_qkv_kernel<<<(3 * DD * DD) / 256, 256>>>(Wq, Wk, Wv, wqkv_hi, wqkv_lo);
    transpose_bf16_kernel<<<dim3(DFF / 32, DD / 32), dim3(32, 8)>>>(W1, w1_hi, w1_lo, DD, DFF);
    transpose_bf16_kernel<<<dim3(DD / 32, DFF / 32), dim3(32, 8)>>>(W2, w2_hi, w2_lo, DFF, DD);
    // 3. QKV projection (HMMA) -> bf16 hi/lo
    hmma_gemm_kernel<3><<<dim3(3 * DD / 128, MM / 128), 256, DSM_B>>>(
        a_hi, a_lo, wqkv_hi, wqkv_lo, DD, 3 * DD, nullptr, qkv_hi, qkv_lo, nullptr, nullptr);
    // 4. HMMA flash attention + residual -> x1
    attn_hmma_kernel<<<dim3(TT / 128, BB * HH), 256, AT_DSM>>>(qkv_hi, qkv_lo, x, x1);
    // 5. LN2 -> bf16 hi/lo (reuse buffers)
    ln_bf16_kernel<<<MM, 256>>>(x1, gamma2, beta2, a_hi, a_lo);
    // 6. FFN1 (HMMA): relu(h2 @ W1 + b1) -> bf16 hi/lo
    hmma_gemm_kernel<1><<<dim3(DFF / 128, MM / 128), 256, DSM_B>>>(
        a_hi, a_lo, w1_hi, w1_lo, DD, DFF, nullptr, f_hi, f_lo, b1, nullptr);
    // 7. FFN2 (HMMA): ff1 @ W2 + b2 + x1 -> out
    hmma_gemm_kernel<2><<<dim3(DD / 128, MM / 128), 256, DSM_B>>>(
        f_hi, f_lo, w2_hi, w2_lo, DFF, DD, out, nullptr, nullptr, b2, x1);
}

// round 8
// speedup vs baseline: 4.2275x; 1.3199x over previous
#include <cuda_runtime.h>
#include <cuda_fp16.h>
#include <cstdint>

// Problem constants
#define DD    1024
#define HH    16
#define DHD   64
#define DFF   4096
#define TT    2048
#define BB    2
#define MM    4096   // B*T

// ---------------- scratch (device globals; no allocation) ----------------
__device__ __half g_a_hi[MM * DD], g_a_lo[MM * DD];          // LN out hi/lo (reused LN1/LN2)
__device__ __half g_wqkv_hi[3 * DD * DD];                    // [N=3072,K=1024] (hi only)
__device__ __half g_w1_hi[DFF * DD];                         // [N=4096,K=1024]
__device__ __half g_w2_hi[DD * DFF];                         // [N=1024,K=4096]
__device__ __half g_ff1_hi[(size_t)MM * DFF], g_ff1_lo[(size_t)MM * DFF];
__device__ __half g_qkv_hi[(size_t)MM * 3 * DD], g_qkv_lo[(size_t)MM * 3 * DD];
__device__ float g_x1 [MM * DD];

// ---------------- helpers ----------------
static __device__ __forceinline__ uint32_t su32(const void* p) {
    uint32_t a;
    asm("{ .reg .u64 t; cvta.to.shared.u64 t, %1; cvt.u32.u64 %0, t; }" : "=r"(a) : "l"(p));
    return a;
}
static __device__ __forceinline__ uint32_t sw128(uint32_t off) {
    return off ^ ((off >> 3) & 0x70);
}
static __device__ __forceinline__ void cpasync16(uint32_t dst, const void* src) {
    asm volatile("cp.async.cg.shared.global [%0], [%1], 16;" :: "r"(dst), "l"(src));
}
#define CP_COMMIT()  asm volatile("cp.async.commit_group;" ::: "memory")
#define CP_WAIT(n)   asm volatile("cp.async.wait_group %0;" :: "n"(n) : "memory")

static __device__ __forceinline__ void ldm_x4(uint32_t* r, uint32_t addr) {
    asm volatile("ldmatrix.sync.aligned.m8n8.x4.shared.b16 {%0,%1,%2,%3}, [%4];"
                 : "=r"(r[0]), "=r"(r[1]), "=r"(r[2]), "=r"(r[3]) : "r"(addr));
}
static __device__ __forceinline__ void ldm_x4t(uint32_t* r, uint32_t addr) {
    asm volatile("ldmatrix.sync.aligned.m8n8.x4.trans.shared.b16 {%0,%1,%2,%3}, [%4];"
                 : "=r"(r[0]), "=r"(r[1]), "=r"(r[2]), "=r"(r[3]) : "r"(addr));
}
static __device__ __forceinline__ void mma16816(float* d, const uint32_t* a, const uint32_t* b) {
    asm volatile(
        "mma.sync.aligned.m16n8k16.row.col.f32.f16.f16.f32 "
        "{%0,%1,%2,%3}, {%4,%5,%6,%7}, {%8,%9}, {%0,%1,%2,%3};"
        : "+f"(d[0]), "+f"(d[1]), "+f"(d[2]), "+f"(d[3])
        : "r"(a[0]), "r"(a[1]), "r"(a[2]), "r"(a[3]), "r"(b[0]), "r"(b[1]));
}
static __device__ __forceinline__ void split_f16(float v, __half& h, __half& l) {
    h = __float2half_rn(v);
    l = __float2half_rn(v - __half2float(h));
}
static __device__ __forceinline__ uint32_t packh(float a, float b) {
    __half2 t = __halves2half2(__float2half_rn(a), __float2half_rn(b));
    return *reinterpret_cast<uint32_t*>(&t);
}

// ---------------- LayerNorm (ddof=1), fp16 hi/lo output ----------------
__global__ __launch_bounds__(256) void ln_f16_kernel(const float* __restrict__ x,
                                                     const float* __restrict__ g,
                                                     const float* __restrict__ bta,
                                                     __half* __restrict__ ohi,
                                                     __half* __restrict__ olo) {
    int row = blockIdx.x;
    int tid = threadIdx.x;
    const float4* xr = (const float4*)(x + (size_t)row * DD);
    float4 v = xr[tid];
    float s  = v.x + v.y + v.z + v.w;
    float sq = v.x * v.x + v.y * v.y + v.z * v.z + v.w * v.w;
#pragma unroll
    for (int o = 16; o; o >>= 1) {
        s  += __shfl_xor_sync(0xffffffffu, s,  o);
        sq += __shfl_xor_sync(0xffffffffu, sq, o);
    }
    __shared__ float ss[8], sqs[8];
    int w = tid >> 5, ln = tid & 31;
    if (ln == 0) { ss[w] = s; sqs[w] = sq; }
    __syncthreads();
    s = 0.f; sq = 0.f;
#pragma unroll
    for (int i = 0; i < 8; i++) { s += ss[i]; sq += sqs[i]; }
    float mean = s * (1.f / 1024.f);
    float var  = (sq - 1024.f * mean * mean) * (1.f / 1023.f);
    float r    = rsqrtf(var + 1e-5f);
    float4 gv = ((const float4*)g)[tid];
    float4 bv = ((const float4*)bta)[tid];
    float o0 = gv.x * (v.x - mean) * r + bv.x;
    float o1 = gv.y * (v.y - mean) * r + bv.y;
    float o2 = gv.z * (v.z - mean) * r + bv.z;
    float o3 = gv.w * (v.w - mean) * r + bv.w;
    __half h0, h1, h2, h3, l0, l1, l2, l3;
    split_f16(o0, h0, l0); split_f16(o1, h1, l1);
    split_f16(o2, h2, l2); split_f16(o3, h3, l3);
    __half2* hp = (__half2*)(ohi + (size_t)row * DD);
    __half2* lp = (__half2*)(olo + (size_t)row * DD);
    hp[tid * 2]     = __halves2half2(h0, h1);
    hp[tid * 2 + 1] = __halves2half2(h2, h3);
    lp[tid * 2]     = __halves2half2(l0, l1);
    lp[tid * 2 + 1] = __halves2half2(l2, l3);
}

// ---------------- repack Wq/Wk/Wv [H,D,DH] -> [N=3072, K=1024] fp16 (hi only) ----------------
__global__ __launch_bounds__(256) void repack_qkv_kernel(const float* __restrict__ Wq,
                                                         const float* __restrict__ Wk,
                                                         const float* __restrict__ Wv,
                                                         __half* __restrict__ ohi) {
    int idx = blockIdx.x * 256 + threadIdx.x;     // over 3072*1024, n*1024 + k
    int n = idx >> 10;
    int k = idx & 1023;
    int w = n >> 10;
    int h = (n >> 6) & 15;
    int e = n & 63;
    const float* W = (w == 0) ? Wq : ((w == 1) ? Wk : Wv);
    ohi[idx] = __float2half_rn(W[h * (DD * DHD) + k * DHD + e]);
}

// ---------------- tiled transpose+convert: in [Kd, Nd] fp32 -> out [Nd, Kd] fp16 ----------------
__global__ __launch_bounds__(256) void transpose_f16_kernel(const float* __restrict__ in,
                                                            __half* __restrict__ ohi,
                                                            int Kd, int Nd) {
    __shared__ float t[32][33];
    int nt = blockIdx.x * 32, kt = blockIdx.y * 32;
    int tx = threadIdx.x, ty = threadIdx.y;   // 32 x 8
#pragma unroll
    for (int i = 0; i < 32; i += 8)
        t[ty + i][tx] = in[(size_t)(kt + ty + i) * Nd + nt + tx];
    __syncthreads();
#pragma unroll
    for (int i = 0; i < 32; i += 8) {
        size_t o = (size_t)(nt + ty + i) * Kd + kt + tx;
        ohi[o] = __float2half_rn(t[tx][ty + i]);
    }
}

// ---------------- HMMA fp16 2-term GEMM: C[M,N] = (Ahi+Alo) * Bhi'[N,K]^T ----------------
// EPI: 1 = relu(+bias)->fp16 hi/lo  2 = +bias+residual->fp32  3 = fp16 hi/lo (lo only for n<DD)
#define TILE_B   16384          // 128 rows x 64 fp16 (128B/row)
#define STAGE_B  (3 * TILE_B)   // Ahi | Alo | Bhi
#define DSM_B    (2 * STAGE_B + 1024)

template <int EPI>
__global__ __launch_bounds__(256, 1) void hmma_gemm_kernel(const __half* __restrict__ Ahi,
                                                           const __half* __restrict__ Alo,
                                                           const __half* __restrict__ Bhi,
                                                           int K, int N,
                                                           float* __restrict__ Cf,
                                                           __half* __restrict__ Chi,
                                                           __half* __restrict__ Clo,
                                                           const float* __restrict__ bias,
                                                           const float* __restrict__ res) {
    extern __shared__ __align__(16) char dsm[];
    int tid  = threadIdx.x;
    int wid  = tid >> 5;
    int lane = tid & 31;
    int wm = wid & 3;
    int wn = wid >> 2;

    uint32_t b32 = su32(dsm);
    uint32_t pad = (1024u - (b32 & 1023u)) & 1023u;
    b32 += pad;

    const int m0 = blockIdx.y * 128;
    const int n0 = blockIdx.x * 128;
    const int nch = K >> 6;

    const __half* srcA_hi = Ahi + (size_t)m0 * K;
    const __half* srcA_lo = Alo + (size_t)m0 * K;
    const __half* srcB_hi = Bhi + (size_t)n0 * K;

    int srow[4], scol[4];
    uint32_t soff[4];
#pragma unroll
    for (int i = 0; i < 4; i++) {
        int idx = i * 256 + tid;
        srow[i] = idx >> 3;
        scol[i] = idx & 7;
        soff[i] = sw128((uint32_t)(srow[i] * 128 + scol[i] * 16));
    }

#define STAGE_CHUNK(c)                                                            \
    do {                                                                          \
        uint32_t stg = b32 + ((c) & 1) * STAGE_B;                                 \
        int koff = (c) * 64;                                                      \
        _Pragma("unroll")                                                         \
        for (int i = 0; i < 4; i++) {                                             \
            size_t goff = (size_t)srow[i] * K + koff + scol[i] * 8;               \
            cpasync16(stg + 0 * TILE_B + soff[i], srcA_hi + goff);                \
            cpasync16(stg + 1 * TILE_B + soff[i], srcA_lo + goff);                \
            cpasync16(stg + 2 * TILE_B + soff[i], srcB_hi + goff);                \
        }                                                                         \
        CP_COMMIT();                                                              \
    } while (0)

    float acc[2][8][4];
#pragma unroll
    for (int mi = 0; mi < 2; mi++)
#pragma unroll
        for (int t = 0; t < 8; t++)
#pragma unroll
            for (int q = 0; q < 4; q++) acc[mi][t][q] = 0.f;

    int g  = lane >> 3;
    int li = lane & 7;
    int a_row0 = wm * 32 + (g & 1) * 8 + li;
    int a_kb   = (g >> 1) * 16;
    int b_row0 = wn * 64 + (g >> 1) * 8 + li;
    int b_kb   = (g & 1) * 16;

    STAGE_CHUNK(0);

    for (int c = 0; c < nch; c++) {
        if (c + 1 < nch) { STAGE_CHUNK(c + 1); CP_WAIT(1); }
        else             { CP_WAIT(0); }
        __syncthreads();

        uint32_t stg = b32 + (c & 1) * STAGE_B;
        uint32_t aHiB = stg, aLoB = stg + TILE_B, bHiB = stg + 2 * TILE_B;

#pragma unroll
        for (int ks = 0; ks < 4; ks++) {
            uint32_t ah[2][4], al[2][4], bb[4][4];
#pragma unroll
            for (int mi = 0; mi < 2; mi++) {
                uint32_t off = sw128((uint32_t)((a_row0 + mi * 16) * 128 + ks * 32 + a_kb));
                ldm_x4(ah[mi], aHiB + off);
                ldm_x4(al[mi], aLoB + off);
            }
#pragma unroll
            for (int j = 0; j < 4; j++) {
                uint32_t off = sw128((uint32_t)((b_row0 + j * 16) * 128 + ks * 32 + b_kb));
                ldm_x4(bb[j], bHiB + off);
            }
#pragma unroll
            for (int mi = 0; mi < 2; mi++)
#pragma unroll
                for (int t = 0; t < 8; t++)
                    mma16816(acc[mi][t], ah[mi], &bb[t >> 1][(t & 1) * 2]);
#pragma unroll
            for (int mi = 0; mi < 2; mi++)
#pragma unroll
                for (int t = 0; t < 8; t++)
                    mma16816(acc[mi][t], al[mi], &bb[t >> 1][(t & 1) * 2]);
        }
        __syncthreads();
    }

    int r_base = m0 + wm * 32 + (lane >> 2);
    int n_base = n0 + wn * 64 + (lane & 3) * 2;
#pragma unroll
    for (int mi = 0; mi < 2; mi++) {
#pragma unroll
        for (int t = 0; t < 8; t++) {
            int r = r_base + mi * 16;
            int n = n_base + t * 8;
            float c0 = acc[mi][t][0], c1 = acc[mi][t][1];
            float c2 = acc[mi][t][2], c3 = acc[mi][t][3];
            if (EPI == 1 || EPI == 3) {
                float v0 = c0, v1 = c1, v2 = c2, v3 = c3;
                if (EPI == 1) {
                    float bi0 = bias[n], bi1 = bias[n + 1];
                    v0 = fmaxf(v0 + bi0, 0.f); v1 = fmaxf(v1 + bi1, 0.f);
                    v2 = fmaxf(v2 + bi0, 0.f); v3 = fmaxf(v3 + bi1, 0.f);
                }
                __half h0, h1, h2, h3, l0, l1, l2, l3;
                split_f16(v0, h0, l0); split_f16(v1, h1, l1);
                split_f16(v2, h2, l2); split_f16(v3, h3, l3);
                *(__half2*)(Chi + (size_t)r * N + n)       = __halves2half2(h0, h1);
                *(__half2*)(Chi + (size_t)(r + 8) * N + n) = __halves2half2(h2, h3);
                if (EPI == 1 || n < DD) {   // qkv: lo needed only for Q cols
                    *(__half2*)(Clo + (size_t)r * N + n)       = __halves2half2(l0, l1);
                    *(__half2*)(Clo + (size_t)(r + 8) * N + n) = __halves2half2(l2, l3);
                }
            } else {
                float bi0 = bias[n], bi1 = bias[n + 1];
                float2 r0 = *(const float2*)(res + (size_t)r * N + n);
                float2 r1 = *(const float2*)(res + (size_t)(r + 8) * N + n);
                float2 v0 = { c0 + bi0 + r0.x, c1 + bi1 + r0.y };
                float2 v1 = { c2 + bi0 + r1.x, c3 + bi1 + r1.y };
                *(float2*)(Cf + (size_t)r * N + n)       = v0;
                *(float2*)(Cf + (size_t)(r + 8) * N + n) = v1;
            }
        }
    }
#undef STAGE_CHUNK
}

// ---------------- HMMA flash attention (causal), fp16 ----------------
// 128-query CTA tile, 64-key tiles. QK: 2-term (Qhi+Qlo)*Khi. PV: (Phi+Plo)*Vhi.
// smem stage: Khi[8K] | Vhi[8K] = 16KB, double-buffered.
#define AT_STAGE 16384
#define AT_DSM   (2 * AT_STAGE + 1024)

__global__ __launch_bounds__(256, 1) void attn_hmma_kernel(const __half* __restrict__ qkv_hi,
                                                           const __half* __restrict__ qkv_lo,
                                                           const float* __restrict__ x,
                                                           float* __restrict__ x1) {
    extern __shared__ __align__(16) char dsm[];
    int tid  = threadIdx.x;
    int wid  = tid >> 5;
    int lane = tid & 31;
    int g  = lane >> 3;
    int li = lane & 7;
    int gr = lane >> 2;
    int gc = lane & 3;

    uint32_t b32 = su32(dsm);
    uint32_t pad = (1024u - (b32 & 1023u)) & 1023u;
    b32 += pad;

    int qt = gridDim.x - 1 - blockIdx.x;     // big tiles first
    int bh = blockIdx.y;
    int b = bh >> 4, h = bh & 15;
    int qbase = qt * 128;

    const __half* qh_g = qkv_hi + (size_t)b * TT * 3072;
    const __half* ql_g = qkv_lo + (size_t)b * TT * 3072;

    // ---- stage Q (hi at b32, lo at b32+16384), ldmatrix to regs ----
#pragma unroll
    for (int i = 0; i < 4; i++) {
        int idx = i * 256 + tid;
        int row = idx >> 3;
        int col = idx & 7;
        uint32_t so = sw128((uint32_t)(row * 128 + col * 16));
        size_t go = (size_t)(qbase + row) * 3072 + h * 64 + col * 8;
        cpasync16(b32 + so,         qh_g + go);
        cpasync16(b32 + 16384 + so, ql_g + go);
    }
    CP_COMMIT();
    CP_WAIT(0);
    __syncthreads();

    uint32_t qfh[4][4], qfl[4][4];
    {
        int a_row = wid * 16 + (g & 1) * 8 + li;
        int a_kb  = (g >> 1) * 16;
#pragma unroll
        for (int ks = 0; ks < 4; ks++) {
            uint32_t off = sw128((uint32_t)(a_row * 128 + ks * 32 + a_kb));
            ldm_x4(qfh[ks], b32 + off);
            ldm_x4(qfl[ks], b32 + 16384 + off);
        }
    }
    __syncthreads();   // Q regs done; smem free for K/V stages

    float m0f = -1e30f, m1f = -1e30f, l0f = 0.f, l1f = 0.f;
    float acc_o[8][4];
#pragma unroll
    for (int t = 0; t < 8; t++)
#pragma unroll
        for (int q = 0; q < 4; q++) acc_o[t][q] = 0.f;

    const int kts = 2 * qt + 2;
    const int wrow_min = qbase + wid * 16;
    const int wrow_max = wrow_min + 15;
    const int b_row = (g >> 1) * 8 + li;
    const int b_kb  = (g & 1) * 16;

#define STAGE_KV(c)                                                                     \
    do {                                                                                \
        uint32_t stg = b32 + ((c) & 1) * AT_STAGE;                                      \
        const __half* kh_g = qh_g + (size_t)((c) * 64) * 3072 + 1024 + h * 64;          \
        _Pragma("unroll")                                                               \
        for (int i = 0; i < 2; i++) {                                                   \
            int idx = i * 256 + tid;                                                    \
            int row = idx >> 3;                                                         \
            int col = idx & 7;                                                          \
            uint32_t so = sw128((uint32_t)(row * 128 + col * 16));                      \
            size_t go = (size_t)row * 3072 + col * 8;                                   \
            cpasync16(stg + so,         kh_g + go);                                     \
            cpasync16(stg + 8192 + so,  kh_g + 1024 + go);                              \
        }                                                                               \
        CP_COMMIT();                                                                    \
    } while (0)

    STAGE_KV(0);

    for (int kt = 0; kt < kts; kt++) {
        if (kt + 1 < kts) { STAGE_KV(kt + 1); CP_WAIT(1); }
        else              { CP_WAIT(0); }
        __syncthreads();

        if (kt * 64 <= wrow_max) {
            uint32_t stg = b32 + (kt & 1) * AT_STAGE;
            uint32_t khB = stg, vhB = stg + 8192;

            float sacc[8][4];
#pragma unroll
            for (int t = 0; t < 8; t++)
#pragma unroll
                for (int q = 0; q < 4; q++) sacc[t][q] = 0.f;

#pragma unroll
            for (int ks = 0; ks < 4; ks++) {
#pragma unroll
                for (int j = 0; j < 4; j++) {
                    uint32_t off = sw128((uint32_t)((j * 16 + b_row) * 128 + ks * 32 + b_kb));
                    uint32_t kb[4];
                    ldm_x4(kb, khB + off);
                    mma16816(sacc[2 * j],     qfh[ks], kb);
                    mma16816(sacc[2 * j + 1], qfh[ks], kb + 2);
                    mma16816(sacc[2 * j],     qfl[ks], kb);
                    mma16816(sacc[2 * j + 1], qfl[ks], kb + 2);
                }
            }

            // scale + causal mask
            int row0 = wrow_min + gr;
            bool domask = (kt * 64 + 63) > wrow_min;
#pragma unroll
            for (int t = 0; t < 8; t++) {
                int colb = kt * 64 + t * 8 + gc * 2;
#pragma unroll
                for (int q = 0; q < 4; q++) {
                    float s = sacc[t][q] * 0.03125f;
                    if (domask) {
                        int col = colb + (q & 1);
                        int row = row0 + ((q >> 1) << 3);
                        if (col > row) s = -1e30f;
                    }
                    sacc[t][q] = s;
                }
            }
            // row max
            float tm0 = -1e30f, tm1 = -1e30f;
#pragma unroll
            for (int t = 0; t < 8; t++) {
                tm0 = fmaxf(tm0, fmaxf(sacc[t][0], sacc[t][1]));
                tm1 = fmaxf(tm1, fmaxf(sacc[t][2], sacc[t][3]));
            }
#pragma unroll
            for (int o = 1; o <= 2; o <<= 1) {
                tm0 = fmaxf(tm0, __shfl_xor_sync(0xffffffffu, tm0, o));
                tm1 = fmaxf(tm1, __shfl_xor_sync(0xffffffffu, tm1, o));
            }
            float mn0 = fmaxf(m0f, tm0), mn1 = fmaxf(m1f, tm1);
            float sc0 = __expf(m0f - mn0), sc1 = __expf(m1f - mn1);
            m0f = mn0; m1f = mn1;
            // exp + row sum
            float ls0 = 0.f, ls1 = 0.f;
#pragma unroll
            for (int t = 0; t < 8; t++) {
                float p0 = __expf(sacc[t][0] - mn0);
                float p1 = __expf(sacc[t][1] - mn0);
                float p2 = __expf(sacc[t][2] - mn1);
                float p3 = __expf(sacc[t][3] - mn1);
                sacc[t][0] = p0; sacc[t][1] = p1; sacc[t][2] = p2; sacc[t][3] = p3;
                ls0 += p0 + p1; ls1 += p2 + p3;
            }
#pragma unroll
            for (int o = 1; o <= 2; o <<= 1) {
                ls0 += __shfl_xor_sync(0xffffffffu, ls0, o);
                ls1 += __shfl_xor_sync(0xffffffffu, ls1, o);
            }
            l0f = l0f * sc0 + ls0;
            l1f = l1f * sc1 + ls1;
#pragma unroll
            for (int t = 0; t < 8; t++) {
                acc_o[t][0] *= sc0; acc_o[t][1] *= sc0;
                acc_o[t][2] *= sc1; acc_o[t][3] *= sc1;
            }
            // PV: (Phi + Plo) * Vhi
#pragma unroll
            for (int ks = 0; ks < 4; ks++) {
                float* p0 = sacc[2 * ks];
                float* p1 = sacc[2 * ks + 1];
                uint32_t ah[4], al[4];
                ah[0] = packh(p0[0], p0[1]);
                ah[1] = packh(p0[2], p0[3]);
                ah[2] = packh(p1[0], p1[1]);
                ah[3] = packh(p1[2], p1[3]);
                {
                    __half2 t0 = *reinterpret_cast<__half2*>(&ah[0]);
                    __half2 t1 = *reinterpret_cast<__half2*>(&ah[1]);
                    __half2 t2 = *reinterpret_cast<__half2*>(&ah[2]);
                    __half2 t3 = *reinterpret_cast<__half2*>(&ah[3]);
                    al[0] = packh(p0[0] - __half2float(t0.x), p0[1] - __half2float(t0.y));
                    al[1] = packh(p0[2] - __half2float(t1.x), p0[3] - __half2float(t1.y));
                    al[2] = packh(p1[0] - __half2float(t2.x), p1[1] - __half2float(t2.y));
                    al[3] = packh(p1[2] - __half2float(t3.x), p1[3] - __half2float(t3.y));
                }
#pragma unroll
                for (int dj = 0; dj < 4; dj++) {
                    // V trans ldmatrix: 16k x 16d
                    int krow = ks * 16 + (g & 1) * 8 + li;
                    int dcol = dj * 16 + (g >> 1) * 8;
                    uint32_t off = sw128((uint32_t)(krow * 128 + dcol * 2));
                    uint32_t vb[4];
                    ldm_x4t(vb, vhB + off);
                    mma16816(acc_o[2 * dj],     ah, vb);
                    mma16816(acc_o[2 * dj + 1], ah, vb + 2);
                    mma16816(acc_o[2 * dj],     al, vb);
                    mma16816(acc_o[2 * dj + 1], al, vb + 2);
                }
            }
        }
        __syncthreads();
    }

    // epilogue: out = x + O/l
    float inv0 = 1.f / l0f, inv1 = 1.f / l1f;
    int r0 = b * TT + wrow_min + gr;
    int r1 = r0 + 8;
    int cb = h * 64 + gc * 2;
#pragma unroll
    for (int dj = 0; dj < 8; dj++) {
        int col = cb + dj * 8;
        float2 x0 = *(const float2*)(x + (size_t)r0 * DD + col);
        float2 x1v = *(const float2*)(x + (size_t)r1 * DD + col);
        float2 o0 = { acc_o[dj][0] * inv0 + x0.x,  acc_o[dj][1] * inv0 + x0.y };
        float2 o1 = { acc_o[dj][2] * inv1 + x1v.x, acc_o[dj][3] * inv1 + x1v.y };
        *(float2*)(x1 + (size_t)r0 * DD + col) = o0;
        *(float2*)(x1 + (size_t)r1 * DD + col) = o1;
    }
#undef STAGE_KV
}

// ---------------- launch ----------------
extern "C" void kernel_launch(void* const* d_in, const int* in_sizes, int n_in,
                              void* d_out, int out_size) {
    const float* x      = (const float*)d_in[0];
    const float* Wq     = (const float*)d_in[1];
    const float* Wk     = (const float*)d_in[2];
    const float* Wv     = (const float*)d_in[3];
    const float* W1     = (const float*)d_in[4];
    const float* b1     = (const float*)d_in[5];
    const float* W2     = (const float*)d_in[6];
    const float* b2     = (const float*)d_in[7];
    const float* gamma1 = (const float*)d_in[8];
    const float* beta1  = (const float*)d_in[9];
    const float* gamma2 = (const float*)d_in[10];
    const float* beta2  = (const float*)d_in[11];
    float* out = (float*)d_out;

    __half *a_hi, *a_lo, *wqkv_hi, *w1_hi, *w2_hi, *f_hi, *f_lo, *qkv_hi, *qkv_lo;
    float *x1;
    cudaGetSymbolAddress((void**)&a_hi, g_a_hi);
    cudaGetSymbolAddress((void**)&a_lo, g_a_lo);
    cudaGetSymbolAddress((void**)&wqkv_hi, g_wqkv_hi);
    cudaGetSymbolAddress((void**)&w1_hi, g_w1_hi);
    cudaGetSymbolAddress((void**)&w2_hi, g_w2_hi);
    cudaGetSymbolAddress((void**)&f_hi, g_ff1_hi);
    cudaGetSymbolAddress((void**)&f_lo, g_ff1_lo);
    cudaGetSymbolAddress((void**)&qkv_hi, g_qkv_hi);
    cudaGetSymbolAddress((void**)&qkv_lo, g_qkv_lo);
    cudaGetSymbolAddress((void**)&x1, g_x1);

    cudaFuncSetAttribute(hmma_gemm_kernel<1>, cudaFuncAttributeMaxDynamicSharedMemorySize, DSM_B);
    cudaFuncSetAttribute(hmma_gemm_kernel<2>, cudaFuncAttributeMaxDynamicSharedMemorySize, DSM_B);
    cudaFuncSetAttribute(hmma_gemm_kernel<3>, cudaFuncAttributeMaxDynamicSharedMemorySize, DSM_B);
    cudaFuncSetAttribute(attn_hmma_kernel, cudaFuncAttributeMaxDynamicSharedMemorySize, AT_DSM);

    // 1. LN1 -> fp16 hi/lo
    ln_f16_kernel<<<MM, 256>>>(x, gamma1, beta1, a_hi, a_lo);
    // 2. weight repacks (transpose + fp16)
    repack_qkv_kernel<<<(3 * DD * DD) / 256, 256>>>(Wq, Wk, Wv, wqkv_hi);
    transpose_f16_kernel<<<dim3(DFF / 32, DD / 32), dim3(32, 8)>>>(W1, w1_hi, DD, DFF);
    transpose_f16_kernel<<<dim3(DD / 32, DFF / 32), dim3(32, 8)>>>(W2, w2_hi, DFF, DD);
    // 3. QKV projection -> fp16 hi/lo (lo stored only for Q cols)
    hmma_gemm_kernel<3><<<dim3(3 * DD / 128, MM / 128), 256, DSM_B>>>(
        a_hi, a_lo, wqkv_hi, DD, 3 * DD, nullptr, qkv_hi, qkv_lo, nullptr, nullptr);
    // 4. HMMA flash attention + residual -> x1
    attn_hmma_kernel<<<dim3(TT / 128, BB * HH), 256, AT_DSM>>>(qkv_hi, qkv_lo, x, x1);
    // 5. LN2 -> fp16 hi/lo (reuse buffers)
    ln_f16_kernel<<<MM, 256>>>(x1, gamma2, beta2, a_hi, a_lo);
    // 6. FFN1: relu(h2 @ W1 + b1) -> fp16 hi/lo
    hmma_gemm_kernel<1><<<dim3(DFF / 128, MM / 128), 256, DSM_B>>>(
        a_hi, a_lo, w1_hi, DD, DFF, nullptr, f_hi, f_lo, b1, nullptr);
    // 7. FFN2: ff1 @ W2 + b2 + x1 -> out
    hmma_gemm_kernel<2><<<dim3(DD / 128, MM / 128), 256, DSM_B>>>(
        f_hi, f_lo, w2_hi, DFF, DD, out, nullptr, nullptr, b2, x1);
}

// round 9
// speedup vs baseline: 6.3089x; 1.4924x over previous
#include <cuda_runtime.h>
#include <cuda_fp16.h>
#include <cstdint>

// Problem constants
#define DD    1024
#define HH    16
#define DHD   64
#define DFF   4096
#define TT    2048
#define BB    2
#define MM    4096   // B*T

// ---------------- scratch (device globals; no allocation) ----------------
__device__ __half g_a_hi[MM * DD];                           // LN out (reused LN1/LN2)
__device__ __half g_wqkv_hi[3 * DD * DD];                    // [N=3072,K=1024]
__device__ __half g_w1_hi[DFF * DD];                         // [N=4096,K=1024]
__device__ __half g_w2_hi[DD * DFF];                         // [N=1024,K=4096]
__device__ __half g_ff1_hi[(size_t)MM * DFF];
__device__ __half g_qkv_hi[(size_t)MM * 3 * DD];
__device__ float g_x1 [MM * DD];

// ---------------- helpers ----------------
static __device__ __forceinline__ uint32_t su32(const void* p) {
    uint32_t a;
    asm("{ .reg .u64 t; cvta.to.shared.u64 t, %1; cvt.u32.u64 %0, t; }" : "=r"(a) : "l"(p));
    return a;
}
static __device__ __forceinline__ uint32_t sw128(uint32_t off) {
    return off ^ ((off >> 3) & 0x70);
}
static __device__ __forceinline__ void cpasync16(uint32_t dst, const void* src) {
    asm volatile("cp.async.cg.shared.global [%0], [%1], 16;" :: "r"(dst), "l"(src));
}
#define CP_COMMIT()  asm volatile("cp.async.commit_group;" ::: "memory")
#define CP_WAIT(n)   asm volatile("cp.async.wait_group %0;" :: "n"(n) : "memory")

static __device__ __forceinline__ void ldm_x4(uint32_t* r, uint32_t addr) {
    asm volatile("ldmatrix.sync.aligned.m8n8.x4.shared.b16 {%0,%1,%2,%3}, [%4];"
                 : "=r"(r[0]), "=r"(r[1]), "=r"(r[2]), "=r"(r[3]) : "r"(addr));
}
static __device__ __forceinline__ void ldm_x4t(uint32_t* r, uint32_t addr) {
    asm volatile("ldmatrix.sync.aligned.m8n8.x4.trans.shared.b16 {%0,%1,%2,%3}, [%4];"
                 : "=r"(r[0]), "=r"(r[1]), "=r"(r[2]), "=r"(r[3]) : "r"(addr));
}
static __device__ __forceinline__ void mma16816(float* d, const uint32_t* a, const uint32_t* b) {
    asm volatile(
        "mma.sync.aligned.m16n8k16.row.col.f32.f16.f16.f32 "
        "{%0,%1,%2,%3}, {%4,%5,%6,%7}, {%8,%9}, {%0,%1,%2,%3};"
        : "+f"(d[0]), "+f"(d[1]), "+f"(d[2]), "+f"(d[3])
        : "r"(a[0]), "r"(a[1]), "r"(a[2]), "r"(a[3]), "r"(b[0]), "r"(b[1]));
}
static __device__ __forceinline__ uint32_t packh(float a, float b) {
    __half2 t = __halves2half2(__float2half_rn(a), __float2half_rn(b));
    return *reinterpret_cast<uint32_t*>(&t);
}

// ---------------- LayerNorm (ddof=1), fp16 output ----------------
__global__ __launch_bounds__(256) void ln_f16_kernel(const float* __restrict__ x,
                                                     const float* __restrict__ g,
                                                     const float* __restrict__ bta,
                                                     __half* __restrict__ ohi) {
    int row = blockIdx.x;
    int tid = threadIdx.x;
    const float4* xr = (const float4*)(x + (size_t)row * DD);
    float4 v = xr[tid];
    float s  = v.x + v.y + v.z + v.w;
    float sq = v.x * v.x + v.y * v.y + v.z * v.z + v.w * v.w;
#pragma unroll
    for (int o = 16; o; o >>= 1) {
        s  += __shfl_xor_sync(0xffffffffu, s,  o);
        sq += __shfl_xor_sync(0xffffffffu, sq, o);
    }
    __shared__ float ss[8], sqs[8];
    int w = tid >> 5, ln = tid & 31;
    if (ln == 0) { ss[w] = s; sqs[w] = sq; }
    __syncthreads();
    s = 0.f; sq = 0.f;
#pragma unroll
    for (int i = 0; i < 8; i++) { s += ss[i]; sq += sqs[i]; }
    float mean = s * (1.f / 1024.f);
    float var  = (sq - 1024.f * mean * mean) * (1.f / 1023.f);
    float r    = rsqrtf(var + 1e-5f);
    float4 gv = ((const float4*)g)[tid];
    float4 bv = ((const float4*)bta)[tid];
    float o0 = gv.x * (v.x - mean) * r + bv.x;
    float o1 = gv.y * (v.y - mean) * r + bv.y;
    float o2 = gv.z * (v.z - mean) * r + bv.z;
    float o3 = gv.w * (v.w - mean) * r + bv.w;
    __half2* hp = (__half2*)(ohi + (size_t)row * DD);
    hp[tid * 2]     = __halves2half2(__float2half_rn(o0), __float2half_rn(o1));
    hp[tid * 2 + 1] = __halves2half2(__float2half_rn(o2), __float2half_rn(o3));
}

// ---------------- repack Wq/Wk/Wv [H,D,DH] -> [N=3072, K=1024] fp16 ----------------
__global__ __launch_bounds__(256) void repack_qkv_kernel(const float* __restrict__ Wq,
                                                         const float* __restrict__ Wk,
                                                         const float* __restrict__ Wv,
                                                         __half* __restrict__ ohi) {
    int idx = blockIdx.x * 256 + threadIdx.x;     // over 3072*1024, n*1024 + k
    int n = idx >> 10;
    int k = idx & 1023;
    int w = n >> 10;
    int h = (n >> 6) & 15;
    int e = n & 63;
    const float* W = (w == 0) ? Wq : ((w == 1) ? Wk : Wv);
    ohi[idx] = __float2half_rn(W[h * (DD * DHD) + k * DHD + e]);
}

// ---------------- tiled transpose+convert: in [Kd, Nd] fp32 -> out [Nd, Kd] fp16 ----------------
__global__ __launch_bounds__(256) void transpose_f16_kernel(const float* __restrict__ in,
                                                            __half* __restrict__ ohi,
                                                            int Kd, int Nd) {
    __shared__ float t[32][33];
    int nt = blockIdx.x * 32, kt = blockIdx.y * 32;
    int tx = threadIdx.x, ty = threadIdx.y;   // 32 x 8
#pragma unroll
    for (int i = 0; i < 32; i += 8)
        t[ty + i][tx] = in[(size_t)(kt + ty + i) * Nd + nt + tx];
    __syncthreads();
#pragma unroll
    for (int i = 0; i < 32; i += 8) {
        size_t o = (size_t)(nt + ty + i) * Kd + kt + tx;
        ohi[o] = __float2half_rn(t[tx][ty + i]);
    }
}

// ---------------- HMMA fp16 GEMM: C[M,N] = A[M,K] * B'[N,K]^T ----------------
// EPI: 1 = relu(+bias)->fp16  2 = +bias+residual->fp32  3 = fp16
#define TILE_B   16384          // 128 rows x 64 fp16 (128B/row)
#define STAGE_B  (2 * TILE_B)   // A | B
#define DSM_B    (2 * STAGE_B + 1024)

template <int EPI>
__global__ __launch_bounds__(256, 1) void hmma_gemm_kernel(const __half* __restrict__ Ahi,
                                                           const __half* __restrict__ Bhi,
                                                           int K, int N,
                                                           float* __restrict__ Cf,
                                                           __half* __restrict__ Chi,
                                                           const float* __restrict__ bias,
                                                           const float* __restrict__ res) {
    extern __shared__ __align__(16) char dsm[];
    int tid  = threadIdx.x;
    int wid  = tid >> 5;
    int lane = tid & 31;
    int wm = wid & 3;
    int wn = wid >> 2;

    uint32_t b32 = su32(dsm);
    uint32_t pad = (1024u - (b32 & 1023u)) & 1023u;
    b32 += pad;

    const int m0 = blockIdx.y * 128;
    const int n0 = blockIdx.x * 128;
    const int nch = K >> 6;

    const __half* srcA = Ahi + (size_t)m0 * K;
    const __half* srcB = Bhi + (size_t)n0 * K;

    int srow[4], scol[4];
    uint32_t soff[4];
#pragma unroll
    for (int i = 0; i < 4; i++) {
        int idx = i * 256 + tid;
        srow[i] = idx >> 3;
        scol[i] = idx & 7;
        soff[i] = sw128((uint32_t)(srow[i] * 128 + scol[i] * 16));
    }

#define STAGE_CHUNK(c)                                                            \
    do {                                                                          \
        uint32_t stg = b32 + ((c) & 1) * STAGE_B;                                 \
        int koff = (c) * 64;                                                      \
        _Pragma("unroll")                                                         \
        for (int i = 0; i < 4; i++) {                                             \
            size_t goff = (size_t)srow[i] * K + koff + scol[i] * 8;               \
            cpasync16(stg + soff[i],          srcA + goff);                       \
            cpasync16(stg + TILE_B + soff[i], srcB + goff);                       \
        }                                                                         \
        CP_COMMIT();                                                              \
    } while (0)

    float acc[2][8][4];
#pragma unroll
    for (int mi = 0; mi < 2; mi++)
#pragma unroll
        for (int t = 0; t < 8; t++)
#pragma unroll
            for (int q = 0; q < 4; q++) acc[mi][t][q] = 0.f;

    int g  = lane >> 3;
    int li = lane & 7;
    int a_row0 = wm * 32 + (g & 1) * 8 + li;
    int a_kb   = (g >> 1) * 16;
    int b_row0 = wn * 64 + (g >> 1) * 8 + li;
    int b_kb   = (g & 1) * 16;

    STAGE_CHUNK(0);

    for (int c = 0; c < nch; c++) {
        if (c + 1 < nch) { STAGE_CHUNK(c + 1); CP_WAIT(1); }
        else             { CP_WAIT(0); }
        __syncthreads();

        uint32_t stg = b32 + (c & 1) * STAGE_B;
        uint32_t aB = stg, bB = stg + TILE_B;

#pragma unroll
        for (int ks = 0; ks < 4; ks++) {
            uint32_t ah[2][4], bb[4][4];
#pragma unroll
            for (int mi = 0; mi < 2; mi++) {
                uint32_t off = sw128((uint32_t)((a_row0 + mi * 16) * 128 + ks * 32 + a_kb));
                ldm_x4(ah[mi], aB + off);
            }
#pragma unroll
            for (int j = 0; j < 4; j++) {
                uint32_t off = sw128((uint32_t)((b_row0 + j * 16) * 128 + ks * 32 + b_kb));
                ldm_x4(bb[j], bB + off);
            }
#pragma unroll
            for (int mi = 0; mi < 2; mi++)
#pragma unroll
                for (int t = 0; t < 8; t++)
                    mma16816(acc[mi][t], ah[mi], &bb[t >> 1][(t & 1) * 2]);
        }
        __syncthreads();
    }

    int r_base = m0 + wm * 32 + (lane >> 2);
    int n_base = n0 + wn * 64 + (lane & 3) * 2;
#pragma unroll
    for (int mi = 0; mi < 2; mi++) {
#pragma unroll
        for (int t = 0; t < 8; t++) {
            int r = r_base + mi * 16;
            int n = n_base + t * 8;
            float c0 = acc[mi][t][0], c1 = acc[mi][t][1];
            float c2 = acc[mi][t][2], c3 = acc[mi][t][3];
            if (EPI == 1 || EPI == 3) {
                float v0 = c0, v1 = c1, v2 = c2, v3 = c3;
                if (EPI == 1) {
                    float bi0 = bias[n], bi1 = bias[n + 1];
                    v0 = fmaxf(v0 + bi0, 0.f); v1 = fmaxf(v1 + bi1, 0.f);
                    v2 = fmaxf(v2 + bi0, 0.f); v3 = fmaxf(v3 + bi1, 0.f);
                }
                *(__half2*)(Chi + (size_t)r * N + n) =
                    __halves2half2(__float2half_rn(v0), __float2half_rn(v1));
                *(__half2*)(Chi + (size_t)(r + 8) * N + n) =
                    __halves2half2(__float2half_rn(v2), __float2half_rn(v3));
            } else {
                float bi0 = bias[n], bi1 = bias[n + 1];
                float2 r0 = *(const float2*)(res + (size_t)r * N + n);
                float2 r1 = *(const float2*)(res + (size_t)(r + 8) * N + n);
                float2 v0 = { c0 + bi0 + r0.x, c1 + bi1 + r0.y };
                float2 v1 = { c2 + bi0 + r1.x, c3 + bi1 + r1.y };
                *(float2*)(Cf + (size_t)r * N + n)       = v0;
                *(float2*)(Cf + (size_t)(r + 8) * N + n) = v1;
            }
        }
    }
#undef STAGE_CHUNK
}

// ---------------- HMMA flash attention (causal), pure fp16 ----------------
// 128-query CTA tile, 64-key tiles. QK: Qhi*Khi. PV: Phi*Vhi.
// smem stage: Khi[8K] | Vhi[8K] = 16KB, double-buffered.
#define AT_STAGE 16384
#define AT_DSM   (2 * AT_STAGE + 1024)

__global__ __launch_bounds__(256, 1) void attn_hmma_kernel(const __half* __restrict__ qkv_hi,
                                                           const float* __restrict__ x,
                                                           float* __restrict__ x1) {
    extern __shared__ __align__(16) char dsm[];
    int tid  = threadIdx.x;
    int wid  = tid >> 5;
    int lane = tid & 31;
    int g  = lane >> 3;
    int li = lane & 7;
    int gr = lane >> 2;
    int gc = lane & 3;

    uint32_t b32 = su32(dsm);
    uint32_t pad = (1024u - (b32 & 1023u)) & 1023u;
    b32 += pad;

    int qt = gridDim.x - 1 - blockIdx.x;     // big tiles first
    int bh = blockIdx.y;
    int b = bh >> 4, h = bh & 15;
    int qbase = qt * 128;

    const __half* qh_g = qkv_hi + (size_t)b * TT * 3072;

    // ---- stage Q, ldmatrix to regs ----
#pragma unroll
    for (int i = 0; i < 4; i++) {
        int idx = i * 256 + tid;
        int row = idx >> 3;
        int col = idx & 7;
        uint32_t so = sw128((uint32_t)(row * 128 + col * 16));
        size_t go = (size_t)(qbase + row) * 3072 + h * 64 + col * 8;
        cpasync16(b32 + so, qh_g + go);
    }
    CP_COMMIT();
    CP_WAIT(0);
    __syncthreads();

    uint32_t qfh[4][4];
    {
        int a_row = wid * 16 + (g & 1) * 8 + li;
        int a_kb  = (g >> 1) * 16;
#pragma unroll
        for (int ks = 0; ks < 4; ks++) {
            uint32_t off = sw128((uint32_t)(a_row * 128 + ks * 32 + a_kb));
            ldm_x4(qfh[ks], b32 + off);
        }
    }
    __syncthreads();   // Q regs done; smem free for K/V stages

    float m0f = -1e30f, m1f = -1e30f, l0f = 0.f, l1f = 0.f;
    float acc_o[8][4];
#pragma unroll
    for (int t = 0; t < 8; t++)
#pragma unroll
        for (int q = 0; q < 4; q++) acc_o[t][q] = 0.f;

    const int kts = 2 * qt + 2;
    const int wrow_min = qbase + wid * 16;
    const int wrow_max = wrow_min + 15;
    const int b_row = (g >> 1) * 8 + li;
    const int b_kb  = (g & 1) * 16;

#define STAGE_KV(c)                                                                     \
    do {                                                                                \
        uint32_t stg = b32 + ((c) & 1) * AT_STAGE;                                      \
        const __half* kh_g = qh_g + (size_t)((c) * 64) * 3072 + 1024 + h * 64;          \
        _Pragma("unroll")                                                               \
        for (int i = 0; i < 2; i++) {                                                   \
            int idx = i * 256 + tid;                                                    \
            int row = idx >> 3;                                                         \
            int col = idx & 7;                                                          \
            uint32_t so = sw128((uint32_t)(row * 128 + col * 16));                      \
            size_t go = (size_t)row * 3072 + col * 8;                                   \
            cpasync16(stg + so,         kh_g + go);                                     \
            cpasync16(stg + 8192 + so,  kh_g + 1024 + go);                              \
        }                                                                               \
        CP_COMMIT();                                                                    \
    } while (0)

    STAGE_KV(0);

    for (int kt = 0; kt < kts; kt++) {
        if (kt + 1 < kts) { STAGE_KV(kt + 1); CP_WAIT(1); }
        else              { CP_WAIT(0); }
        __syncthreads();

        if (kt * 64 <= wrow_max) {
            uint32_t stg = b32 + (kt & 1) * AT_STAGE;
            uint32_t khB = stg, vhB = stg + 8192;

            float sacc[8][4];
#pragma unroll
            for (int t = 0; t < 8; t++)
#pragma unroll
                for (int q = 0; q < 4; q++) sacc[t][q] = 0.f;

#pragma unroll
            for (int ks = 0; ks < 4; ks++) {
#pragma unroll
                for (int j = 0; j < 4; j++) {
                    uint32_t off = sw128((uint32_t)((j * 16 + b_row) * 128 + ks * 32 + b_kb));
                    uint32_t kb[4];
                    ldm_x4(kb, khB + off);
                    mma16816(sacc[2 * j],     qfh[ks], kb);
                    mma16816(sacc[2 * j + 1], qfh[ks], kb + 2);
                }
            }

            // scale + causal mask
            int row0 = wrow_min + gr;
            bool domask = (kt * 64 + 63) > wrow_min;
#pragma unroll
            for (int t = 0; t < 8; t++) {
                int colb = kt * 64 + t * 8 + gc * 2;
#pragma unroll
                for (int q = 0; q < 4; q++) {
                    float s = sacc[t][q] * 0.03125f;
                    if (domask) {
                        int col = colb + (q & 1);
                        int row = row0 + ((q >> 1) << 3);
                        if (col > row) s = -1e30f;
                    }
                    sacc[t][q] = s;
                }
            }
            // row max
            float tm0 = -1e30f, tm1 = -1e30f;
#pragma unroll
            for (int t = 0; t < 8; t++) {
                tm0 = fmaxf(tm0, fmaxf(sacc[t][0], sacc[t][1]));
                tm1 = fmaxf(tm1, fmaxf(sacc[t][2], sacc[t][3]));
            }
#pragma unroll
            for (int o = 1; o <= 2; o <<= 1) {
                tm0 = fmaxf(tm0, __shfl_xor_sync(0xffffffffu, tm0, o));
                tm1 = fmaxf(tm1, __shfl_xor_sync(0xffffffffu, tm1, o));
            }
            float mn0 = fmaxf(m0f, tm0), mn1 = fmaxf(m1f, tm1);
            float sc0 = __expf(m0f - mn0), sc1 = __expf(m1f - mn1);
            m0f = mn0; m1f = mn1;
            // exp + row sum
            float ls0 = 0.f, ls1 = 0.f;
#pragma unroll
            for (int t = 0; t < 8; t++) {
                float p0 = __expf(sacc[t][0] - mn0);
                float p1 = __expf(sacc[t][1] - mn0);
                float p2 = __expf(sacc[t][2] - mn1);
                float p3 = __expf(sacc[t][3] - mn1);
                sacc[t][0] = p0; sacc[t][1] = p1; sacc[t][2] = p2; sacc[t][3] = p3;
                ls0 += p0 + p1; ls1 += p2 + p3;
            }
#pragma unroll
            for (int o = 1; o <= 2; o <<= 1) {
                ls0 += __shfl_xor_sync(0xffffffffu, ls0, o);
                ls1 += __shfl_xor_sync(0xffffffffu, ls1, o);
            }
            l0f = l0f * sc0 + ls0;
            l1f = l1f * sc1 + ls1;
#pragma unroll
            for (int t = 0; t < 8; t++) {
                acc_o[t][0] *= sc0; acc_o[t][1] *= sc0;
                acc_o[t][2] *= sc1; acc_o[t][3] *= sc1;
            }
            // PV: Phi * Vhi
#pragma unroll
            for (int ks = 0; ks < 4; ks++) {
                float* p0 = sacc[2 * ks];
                float* p1 = sacc[2 * ks + 1];
                uint32_t ah[4];
                ah[0] = packh(p0[0], p0[1]);
                ah[1] = packh(p0[2], p0[3]);
                ah[2] = packh(p1[0], p1[1]);
                ah[3] = packh(p1[2], p1[3]);
#pragma unroll
                for (int dj = 0; dj < 4; dj++) {
                    // V trans ldmatrix: 16k x 16d
                    int krow = ks * 16 + (g & 1) * 8 + li;
                    int dcol = dj * 16 + (g >> 1) * 8;
                    uint32_t off = sw128((uint32_t)(krow * 128 + dcol * 2));
                    uint32_t vb[4];
                    ldm_x4t(vb, vhB + off);
                    mma16816(acc_o[2 * dj],     ah, vb);
                    mma16816(acc_o[2 * dj + 1], ah, vb + 2);
                }
            }
        }
        __syncthreads();
    }

    // epilogue: out = x + O/l
    float inv0 = 1.f / l0f, inv1 = 1.f / l1f;
    int r0 = b * TT + wrow_min + gr;
    int r1 = r0 + 8;
    int cb = h * 64 + gc * 2;
#pragma unroll
    for (int dj = 0; dj < 8; dj++) {
        int col = cb + dj * 8;
        float2 x0 = *(const float2*)(x + (size_t)r0 * DD + col);
        float2 x1v = *(const float2*)(x + (size_t)r1 * DD + col);
        float2 o0 = { acc_o[dj][0] * inv0 + x0.x,  acc_o[dj][1] * inv0 + x0.y };
        float2 o1 = { acc_o[dj][2] * inv1 + x1v.x, acc_o[dj][3] * inv1 + x1v.y };
        *(float2*)(x1 + (size_t)r0 * DD + col) = o0;
        *(float2*)(x1 + (size_t)r1 * DD + col) = o1;
    }
#undef STAGE_KV
}

// ---------------- launch ----------------
extern "C" void kernel_launch(void* const* d_in, const int* in_sizes, int n_in,
                              void* d_out, int out_size) {
    const float* x      = (const float*)d_in[0];
    const float* Wq     = (const float*)d_in[1];
    const float* Wk     = (const float*)d_in[2];
    const float* Wv     = (const float*)d_in[3];
    const float* W1     = (const float*)d_in[4];
    const float* b1     = (const float*)d_in[5];
    const float* W2     = (const float*)d_in[6];
    const float* b2     = (const float*)d_in[7];
    const float* gamma1 = (const float*)d_in[8];
    const float* beta1  = (const float*)d_in[9];
    const float* gamma2 = (const float*)d_in[10];
    const float* beta2  = (const float*)d_in[11];
    float* out = (float*)d_out;

    __half *a_hi, *wqkv_hi, *w1_hi, *w2_hi, *f_hi, *qkv_hi;
    float *x1;
    cudaGetSymbolAddress((void**)&a_hi, g_a_hi);
    cudaGetSymbolAddress((void**)&wqkv_hi, g_wqkv_hi);
    cudaGetSymbolAddress((void**)&w1_hi, g_w1_hi);
    cudaGetSymbolAddress((void**)&w2_hi, g_w2_hi);
    cudaGetSymbolAddress((void**)&f_hi, g_ff1_hi);
    cudaGetSymbolAddress((void**)&qkv_hi, g_qkv_hi);
    cudaGetSymbolAddress((void**)&x1, g_x1);

    cudaFuncSetAttribute(hmma_gemm_kernel<1>, cudaFuncAttributeMaxDynamicSharedMemorySize, DSM_B);
    cudaFuncSetAttribute(hmma_gemm_kernel<2>, cudaFuncAttributeMaxDynamicSharedMemorySize, DSM_B);
    cudaFuncSetAttribute(hmma_gemm_kernel<3>, cudaFuncAttributeMaxDynamicSharedMemorySize, DSM_B);
    cudaFuncSetAttribute(attn_hmma_kernel, cudaFuncAttributeMaxDynamicSharedMemorySize, AT_DSM);

    // 1. LN1 -> fp16
    ln_f16_kernel<<<MM, 256>>>(x, gamma1, beta1, a_hi);
    // 2. weight repacks (transpose + fp16)
    repack_qkv_kernel<<<(3 * DD * DD) / 256, 256>>>(Wq, Wk, Wv, wqkv_hi);
    transpose_f16_kernel<<<dim3(DFF / 32, DD / 32), dim3(32, 8)>>>(W1, w1_hi, DD, DFF);
    transpose_f16_kernel<<<dim3(DD / 32, DFF / 32), dim3(32, 8)>>>(W2, w2_hi, DFF, DD);
    // 3. QKV projection -> fp16
    hmma_gemm_kernel<3><<<dim3(3 * DD / 128, MM / 128), 256, DSM_B>>>(
        a_hi, wqkv_hi, DD, 3 * DD, nullptr, qkv_hi, nullptr, nullptr);
    // 4. HMMA flash attention + residual -> x1
    attn_hmma_kernel<<<dim3(TT / 128, BB * HH), 256, AT_DSM>>>(qkv_hi, x, x1);
    // 5. LN2 -> fp16
    ln_f16_kernel<<<MM, 256>>>(x1, gamma2, beta2, a_hi);
    // 6. FFN1: relu(h2 @ W1 + b1) -> fp16
    hmma_gemm_kernel<1><<<dim3(DFF / 128, MM / 128), 256, DSM_B>>>(
        a_hi, w1_hi, DD, DFF, nullptr, f_hi, b1, nullptr);
    // 7. FFN2: ff1 @ W2 + b2 + x1 -> out
    hmma_gemm_kernel<2><<<dim3(DD / 128, MM / 128), 256, DSM_B>>>(
        f_hi, w2_hi, DFF, DD, out, nullptr, b2, x1);
}

// round 11
// speedup vs baseline: 6.8479x; 1.0854x over previous
#include <cuda_runtime.h>
#include <cuda_fp16.h>
#include <cstdint>

// Problem constants
#define DD    1024
#define HH    16
#define DHD   64
#define DFF   4096
#define TT    2048
#define BB    2
#define MM    4096   // B*T

// ---------------- scratch (device globals; no allocation) ----------------
__device__ __half g_a_hi[MM * DD];                           // LN out (reused LN1/LN2)
__device__ __half g_wqkv_hi[3 * DD * DD];                    // [N=3072,K=1024]
__device__ __half g_w1_hi[DFF * DD];                         // [N=4096,K=1024]
__device__ __half g_w2_hi[DD * DFF];                         // [N=1024,K=4096]
__device__ __half g_ff1_hi[(size_t)MM * DFF];
__device__ __half g_qkv_hi[(size_t)MM * 3 * DD];
__device__ float g_x1 [MM * DD];

// ---------------- helpers ----------------
static __device__ __forceinline__ uint32_t su32(const void* p) {
    uint32_t a;
    asm("{ .reg .u64 t; cvta.to.shared.u64 t, %1; cvt.u32.u64 %0, t; }" : "=r"(a) : "l"(p));
    return a;
}
static __device__ __forceinline__ uint32_t sw128(uint32_t off) {
    return off ^ ((off >> 3) & 0x70);
}
static __device__ __forceinline__ void cpasync16(uint32_t dst, const void* src) {
    asm volatile("cp.async.cg.shared.global [%0], [%1], 16;" :: "r"(dst), "l"(src));
}
#define CP_COMMIT()  asm volatile("cp.async.commit_group;" ::: "memory")
#define CP_WAIT(n)   asm volatile("cp.async.wait_group %0;" :: "n"(n) : "memory")

static __device__ __forceinline__ void ldm_x4(uint32_t* r, uint32_t addr) {
    asm volatile("ldmatrix.sync.aligned.m8n8.x4.shared.b16 {%0,%1,%2,%3}, [%4];"
                 : "=r"(r[0]), "=r"(r[1]), "=r"(r[2]), "=r"(r[3]) : "r"(addr));
}
static __device__ __forceinline__ void ldm_x4t(uint32_t* r, uint32_t addr) {
    asm volatile("ldmatrix.sync.aligned.m8n8.x4.trans.shared.b16 {%0,%1,%2,%3}, [%4];"
                 : "=r"(r[0]), "=r"(r[1]), "=r"(r[2]), "=r"(r[3]) : "r"(addr));
}
static __device__ __forceinline__ void mma16816(float* d, const uint32_t* a, const uint32_t* b) {
    asm volatile(
        "mma.sync.aligned.m16n8k16.row.col.f32.f16.f16.f32 "
        "{%0,%1,%2,%3}, {%4,%5,%6,%7}, {%8,%9}, {%0,%1,%2,%3};"
        : "+f"(d[0]), "+f"(d[1]), "+f"(d[2]), "+f"(d[3])
        : "r"(a[0]), "r"(a[1]), "r"(a[2]), "r"(a[3]), "r"(b[0]), "r"(b[1]));
}
static __device__ __forceinline__ uint32_t packh(float a, float b) {
    __half2 t = __halves2half2(__float2half_rn(a), __float2half_rn(b));
    return *reinterpret_cast<uint32_t*>(&t);
}

// ---------------- LayerNorm (ddof=1), fp16 output ----------------
__global__ __launch_bounds__(256) void ln_f16_kernel(const float* __restrict__ x,
                                                     const float* __restrict__ g,
                                                     const float* __restrict__ bta,
                                                     __half* __restrict__ ohi) {
    int row = blockIdx.x;
    int tid = threadIdx.x;
    const float4* xr = (const float4*)(x + (size_t)row * DD);
    float4 v = xr[tid];
    float s  = v.x + v.y + v.z + v.w;
    float sq = v.x * v.x + v.y * v.y + v.z * v.z + v.w * v.w;
#pragma unroll
    for (int o = 16; o; o >>= 1) {
        s  += __shfl_xor_sync(0xffffffffu, s,  o);
        sq += __shfl_xor_sync(0xffffffffu, sq, o);
    }
    __shared__ float ss[8], sqs[8];
    int w = tid >> 5, ln = tid & 31;
    if (ln == 0) { ss[w] = s; sqs[w] = sq; }
    __syncthreads();
    s = 0.f; sq = 0.f;
#pragma unroll
    for (int i = 0; i < 8; i++) { s += ss[i]; sq += sqs[i]; }
    float mean = s * (1.f / 1024.f);
    float var  = (sq - 1024.f * mean * mean) * (1.f / 1023.f);
    float r    = rsqrtf(var + 1e-5f);
    float4 gv = ((const float4*)g)[tid];
    float4 bv = ((const float4*)bta)[tid];
    float o0 = gv.x * (v.x - mean) * r + bv.x;
    float o1 = gv.y * (v.y - mean) * r + bv.y;
    float o2 = gv.z * (v.z - mean) * r + bv.z;
    float o3 = gv.w * (v.w - mean) * r + bv.w;
    __half2* hp = (__half2*)(ohi + (size_t)row * DD);
    hp[tid * 2]     = __halves2half2(__float2half_rn(o0), __float2half_rn(o1));
    hp[tid * 2 + 1] = __halves2half2(__float2half_rn(o2), __float2half_rn(o3));
}

// ---------------- repack Wq/Wk/Wv [H,D,DH] -> [N=3072, K=1024] fp16 (tiled transpose) ----------------
// Per (w,h): out[e][k] = W[k][e], a 1024x64 transpose done in 32x32 tiles.
__global__ __launch_bounds__(256) void repack_qkv_kernel(const float* __restrict__ Wq,
                                                         const float* __restrict__ Wk,
                                                         const float* __restrict__ Wv,
                                                         __half* __restrict__ ohi) {
    __shared__ float t[32][33];
    int wh = blockIdx.z;          // 0..47: w*16+h
    int w = wh >> 4, h = wh & 15;
    int et = blockIdx.x * 32;     // 0 or 32
    int kt = blockIdx.y * 32;     // 0..992
    int tx = threadIdx.x, ty = threadIdx.y;   // 32 x 8
    const float* W = (w == 0) ? Wq : ((w == 1) ? Wk : Wv);
    const float* Wh = W + h * (DD * DHD);
#pragma unroll
    for (int i = 0; i < 32; i += 8)
        t[ty + i][tx] = Wh[(size_t)(kt + ty + i) * DHD + et + tx];   // coalesced over e
    __syncthreads();
    int nbase = w * 1024 + h * 64 + et;
#pragma unroll
    for (int i = 0; i < 32; i += 8) {
        size_t o = (size_t)(nbase + ty + i) * DD + kt + tx;          // coalesced over k
        ohi[o] = __float2half_rn(t[tx][ty + i]);
    }
}

// ---------------- tiled transpose+convert: in [Kd, Nd] fp32 -> out [Nd, Kd] fp16 ----------------
__global__ __launch_bounds__(256) void transpose_f16_kernel(const float* __restrict__ in,
                                                            __half* __restrict__ ohi,
                                                            int Kd, int Nd) {
    __shared__ float t[32][33];
    int nt = blockIdx.x * 32, kt = blockIdx.y * 32;
    int tx = threadIdx.x, ty = threadIdx.y;   // 32 x 8
#pragma unroll
    for (int i = 0; i < 32; i += 8)
        t[ty + i][tx] = in[(size_t)(kt + ty + i) * Nd + nt + tx];
    __syncthreads();
#pragma unroll
    for (int i = 0; i < 32; i += 8) {
        size_t o = (size_t)(nt + ty + i) * Kd + kt + tx;
        ohi[o] = __float2half_rn(t[tx][ty + i]);
    }
}

// ---------------- HMMA fp16 GEMM: C[M,N] = A[M,K] * B'[N,K]^T ----------------
// Tile: (64*MI) x 128, 8 warps as 4(M) x 2(N). K chunks of 64, double-buffered.
// EPI: 1 = relu(+bias)->fp16  2 = +bias+residual->fp32  3 = fp16
template <int MI, int EPI>
__global__ __launch_bounds__(256, 2) void hmma_gemm_kernel(const __half* __restrict__ Ahi,
                                                           const __half* __restrict__ Bhi,
                                                           int K, int N,
                                                           float* __restrict__ Cf,
                                                           __half* __restrict__ Chi,
                                                           const float* __restrict__ bias,
                                                           const float* __restrict__ res) {
    constexpr int TILE_A  = MI * 64 * 128;          // A tile bytes
    constexpr int TILE_Bb = 16384;                  // B tile bytes (128 rows)
    constexpr int STAGE   = TILE_A + TILE_Bb;

    extern __shared__ __align__(16) char dsm[];
    int tid  = threadIdx.x;
    int wid  = tid >> 5;
    int lane = tid & 31;
    int wm = wid & 3;
    int wn = wid >> 2;

    uint32_t b32 = su32(dsm);
    uint32_t pad = (1024u - (b32 & 1023u)) & 1023u;
    b32 += pad;

    const int m0 = blockIdx.y * (64 * MI);
    const int n0 = blockIdx.x * 128;
    const int nch = K >> 6;

    const __half* srcA = Ahi + (size_t)m0 * K;
    const __half* srcB = Bhi + (size_t)n0 * K;

#define STAGE_CHUNK(c)                                                            \
    do {                                                                          \
        uint32_t stg = b32 + ((c) & 1) * STAGE;                                   \
        int koff = (c) * 64;                                                      \
        _Pragma("unroll")                                                         \
        for (int i = 0; i < 2 * MI; i++) {                                        \
            int idx = i * 256 + tid;                                              \
            int row = idx >> 3, col = idx & 7;                                    \
            uint32_t so = sw128((uint32_t)(row * 128 + col * 16));                \
            cpasync16(stg + so, srcA + (size_t)row * K + koff + col * 8);         \
        }                                                                         \
        _Pragma("unroll")                                                         \
        for (int i = 0; i < 4; i++) {                                             \
            int idx = i * 256 + tid;                                              \
            int row = idx >> 3, col = idx & 7;                                    \
            uint32_t so = sw128((uint32_t)(row * 128 + col * 16));                \
            cpasync16(stg + TILE_A + so, srcB + (size_t)row * K + koff + col * 8);\
        }                                                                         \
        CP_COMMIT();                                                              \
    } while (0)

    float acc[MI][8][4];
#pragma unroll
    for (int mi = 0; mi < MI; mi++)
#pragma unroll
        for (int t = 0; t < 8; t++)
#pragma unroll
            for (int q = 0; q < 4; q++) acc[mi][t][q] = 0.f;

    int g  = lane >> 3;
    int li = lane & 7;
    int a_row0 = wm * (16 * MI) + (g & 1) * 8 + li;
    int a_kb   = (g >> 1) * 16;
    int b_row0 = wn * 64 + (g >> 1) * 8 + li;
    int b_kb   = (g & 1) * 16;

    STAGE_CHUNK(0);

    for (int c = 0; c < nch; c++) {
        if (c + 1 < nch) { STAGE_CHUNK(c + 1); CP_WAIT(1); }
        else             { CP_WAIT(0); }
        __syncthreads();

        uint32_t stg = b32 + (c & 1) * STAGE;
        uint32_t aB = stg, bB = stg + TILE_A;

#pragma unroll
        for (int ks = 0; ks < 4; ks++) {
            uint32_t ah[MI][4], bb[4][4];
#pragma unroll
            for (int mi = 0; mi < MI; mi++) {
                uint32_t off = sw128((uint32_t)((a_row0 + mi * 16) * 128 + ks * 32 + a_kb));
                ldm_x4(ah[mi], aB + off);
            }
#pragma unroll
            for (int j = 0; j < 4; j++) {
                uint32_t off = sw128((uint32_t)((b_row0 + j * 16) * 128 + ks * 32 + b_kb));
                ldm_x4(bb[j], bB + off);
            }
#pragma unroll
            for (int mi = 0; mi < MI; mi++)
#pragma unroll
                for (int t = 0; t < 8; t++)
                    mma16816(acc[mi][t], ah[mi], &bb[t >> 1][(t & 1) * 2]);
        }
        __syncthreads();
    }

    int r_base = m0 + wm * (16 * MI) + (lane >> 2);
    int n_base = n0 + wn * 64 + (lane & 3) * 2;
#pragma unroll
    for (int mi = 0; mi < MI; mi++) {
#pragma unroll
        for (int t = 0; t < 8; t++) {
            int r = r_base + mi * 16;
            int n = n_base + t * 8;
            float c0 = acc[mi][t][0], c1 = acc[mi][t][1];
            float c2 = acc[mi][t][2], c3 = acc[mi][t][3];
            if (EPI == 1 || EPI == 3) {
                float v0 = c0, v1 = c1, v2 = c2, v3 = c3;
                if (EPI == 1) {
                    float bi0 = bias[n], bi1 = bias[n + 1];
                    v0 = fmaxf(v0 + bi0, 0.f); v1 = fmaxf(v1 + bi1, 0.f);
                    v2 = fmaxf(v2 + bi0, 0.f); v3 = fmaxf(v3 + bi1, 0.f);
                }
                *(__half2*)(Chi + (size_t)r * N + n) =
                    __halves2half2(__float2half_rn(v0), __float2half_rn(v1));
                *(__half2*)(Chi + (size_t)(r + 8) * N + n) =
                    __halves2half2(__float2half_rn(v2), __float2half_rn(v3));
            } else {
                float bi0 = bias[n], bi1 = bias[n + 1];
                float2 r0 = *(const float2*)(res + (size_t)r * N + n);
                float2 r1 = *(const float2*)(res + (size_t)(r + 8) * N + n);
                float2 v0 = { c0 + bi0 + r0.x, c1 + bi1 + r0.y };
                float2 v1 = { c2 + bi0 + r1.x, c3 + bi1 + r1.y };
                *(float2*)(Cf + (size_t)r * N + n)       = v0;
                *(float2*)(Cf + (size_t)(r + 8) * N + n) = v1;
            }
        }
    }
#undef STAGE_CHUNK
}

// ---------------- HMMA flash attention (causal), pure fp16 ----------------
// 128-query CTA tile, 64-key tiles. QK: Qhi*Khi. PV: Phi*Vhi.
// smem stage: Khi[8K] | Vhi[8K] = 16KB, double-buffered.
#define AT_STAGE 16384
#define AT_DSM   (2 * AT_STAGE + 1024)

__global__ __launch_bounds__(256, 2) void attn_hmma_kernel(const __half* __restrict__ qkv_hi,
                                                           const float* __restrict__ x,
                                                           float* __restrict__ x1) {
    extern __shared__ __align__(16) char dsm[];
    int tid  = threadIdx.x;
    int wid  = tid >> 5;
    int lane = tid & 31;
    int g  = lane >> 3;
    int li = lane & 7;
    int gr = lane >> 2;
    int gc = lane & 3;

    uint32_t b32 = su32(dsm);
    uint32_t pad = (1024u - (b32 & 1023u)) & 1023u;
    b32 += pad;

    int qt = gridDim.x - 1 - blockIdx.x;     // big tiles first
    int bh = blockIdx.y;
    int b = bh >> 4, h = bh & 15;
    int qbase = qt * 128;

    const __half* qh_g = qkv_hi + (size_t)b * TT * 3072;

    // ---- stage Q, ldmatrix to regs ----
#pragma unroll
    for (int i = 0; i < 4; i++) {
        int idx = i * 256 + tid;
        int row = idx >> 3;
        int col = idx & 7;
        uint32_t so = sw128((uint32_t)(row * 128 + col * 16));
        size_t go = (size_t)(qbase + row) * 3072 + h * 64 + col * 8;
        cpasync16(b32 + so, qh_g + go);
    }
    CP_COMMIT();
    CP_WAIT(0);
    __syncthreads();

    uint32_t qfh[4][4];
    {
        int a_row = wid * 16 + (g & 1) * 8 + li;
        int a_kb  = (g >> 1) * 16;
#pragma unroll
        for (int ks = 0; ks < 4; ks++) {
            uint32_t off = sw128((uint32_t)(a_row * 128 + ks * 32 + a_kb));
            ldm_x4(qfh[ks], b32 + off);
        }
    }
    __syncthreads();   // Q regs done; smem free for K/V stages

    float m0f = -1e30f, m1f = -1e30f, l0f = 0.f, l1f = 0.f;
    float acc_o[8][4];
#pragma unroll
    for (int t = 0; t < 8; t++)
#pragma unroll
        for (int q = 0; q < 4; q++) acc_o[t][q] = 0.f;

    const int kts = 2 * qt + 2;
    const int wrow_min = qbase + wid * 16;
    const int wrow_max = wrow_min + 15;
    const int b_row = (g >> 1) * 8 + li;
    const int b_kb  = (g & 1) * 16;

#define STAGE_KV(c)                                                                     \
    do {                                                                                \
        uint32_t stg = b32 + ((c) & 1) * AT_STAGE;                                      \
        const __half* kh_g = qh_g + (size_t)((c) * 64) * 3072 + 1024 + h * 64;          \
        _Pragma("unroll")                                                               \
        for (int i = 0; i < 2; i++) {                                                   \
            int idx = i * 256 + tid;                                                    \
            int row = idx >> 3;                                                         \
            int col = idx & 7;                                                          \
            uint32_t so = sw128((uint32_t)(row * 128 + col * 16));                      \
            size_t go = (size_t)row * 3072 + col * 8;                                   \
            cpasync16(stg + so,         kh_g + go);                                     \
            cpasync16(stg + 8192 + so,  kh_g + 1024 + go);                              \
        }                                                                               \
        CP_COMMIT();                                                                    \
    } while (0)

    STAGE_KV(0);

    for (int kt = 0; kt < kts; kt++) {
        if (kt + 1 < kts) { STAGE_KV(kt + 1); CP_WAIT(1); }
        else              { CP_WAIT(0); }
        __syncthreads();

        if (kt * 64 <= wrow_max) {
            uint32_t stg = b32 + (kt & 1) * AT_STAGE;
            uint32_t khB = stg, vhB = stg + 8192;

            float sacc[8][4];
#pragma unroll
            for (int t = 0; t < 8; t++)
#pragma unroll
                for (int q = 0; q < 4; q++) sacc[t][q] = 0.f;

#pragma unroll
            for (int ks = 0; ks < 4; ks++) {
#pragma unroll
                for (int j = 0; j < 4; j++) {
                    uint32_t off = sw128((uint32_t)((j * 16 + b_row) * 128 + ks * 32 + b_kb));
                    uint32_t kb[4];
                    ldm_x4(kb, khB + off);
                    mma16816(sacc[2 * j],     qfh[ks], kb);
                    mma16816(sacc[2 * j + 1], qfh[ks], kb + 2);
                }
            }

            // scale + causal mask
            int row0 = wrow_min + gr;
            bool domask = (kt * 64 + 63) > wrow_min;
#pragma unroll
            for (int t = 0; t < 8; t++) {
                int colb = kt * 64 + t * 8 + gc * 2;
#pragma unroll
                for (int q = 0; q < 4; q++) {
                    float s = sacc[t][q] * 0.03125f;
                    if (domask) {
                        int col = colb + (q & 1);
                        int row = row0 + ((q >> 1) << 3);
                        if (col > row) s = -1e30f;
                    }
                    sacc[t][q] = s;
                }
            }
            // row max
            float tm0 = -1e30f, tm1 = -1e30f;
#pragma unroll
            for (int t = 0; t < 8; t++) {
                tm0 = fmaxf(tm0, fmaxf(sacc[t][0], sacc[t][1]));
                tm1 = fmaxf(tm1, fmaxf(sacc[t][2], sacc[t][3]));
            }
#pragma unroll
            for (int o = 1; o <= 2; o <<= 1) {
                tm0 = fmaxf(tm0, __shfl_xor_sync(0xffffffffu, tm0, o));
                tm1 = fmaxf(tm1, __shfl_xor_sync(0xffffffffu, tm1, o));
            }
            float mn0 = fmaxf(m0f, tm0), mn1 = fmaxf(m1f, tm1);
            float sc0 = __expf(m0f - mn0), sc1 = __expf(m1f - mn1);
            m0f = mn0; m1f = mn1;
            // exp + row sum
            float ls0 = 0.f, ls1 = 0.f;
#pragma unroll
            for (int t = 0; t < 8; t++) {
                float p0 = __expf(sacc[t][0] - mn0);
                float p1 = __expf(sacc[t][1] - mn0);
                float p2 = __expf(sacc[t][2] - mn1);
                float p3 = __expf(sacc[t][3] - mn1);
                sacc[t][0] = p0; sacc[t][1] = p1; sacc[t][2] = p2; sacc[t][3] = p3;
                ls0 += p0 + p1; ls1 += p2 + p3;
            }
#pragma unroll
            for (int o = 1; o <= 2; o <<= 1) {
                ls0 += __shfl_xor_sync(0xffffffffu, ls0, o);
                ls1 += __shfl_xor_sync(0xffffffffu, ls1, o);
            }
            l0f = l0f * sc0 + ls0;
            l1f = l1f * sc1 + ls1;
#pragma unroll
            for (int t = 0; t < 8; t++) {
                acc_o[t][0] *= sc0; acc_o[t][1] *= sc0;
                acc_o[t][2] *= sc1; acc_o[t][3] *= sc1;
            }
            // PV: Phi * Vhi
#pragma unroll
            for (int ks = 0; ks < 4; ks++) {
                float* p0 = sacc[2 * ks];
                float* p1 = sacc[2 * ks + 1];
                uint32_t ah[4];
                ah[0] = packh(p0[0], p0[1]);
                ah[1] = packh(p0[2], p0[3]);
                ah[2] = packh(p1[0], p1[1]);
                ah[3] = packh(p1[2], p1[3]);
#pragma unroll
                for (int dj = 0; dj < 4; dj++) {
                    // V trans ldmatrix: 16k x 16d
                    int krow = ks * 16 + (g & 1) * 8 + li;
                    int dcol = dj * 16 + (g >> 1) * 8;
                    uint32_t off = sw128((uint32_t)(krow * 128 + dcol * 2));
                    uint32_t vb[4];
                    ldm_x4t(vb, vhB + off);
                    mma16816(acc_o[2 * dj],     ah, vb);
                    mma16816(acc_o[2 * dj + 1], ah, vb + 2);
                }
            }
        }
        __syncthreads();
    }

    // epilogue: out = x + O/l
    float inv0 = 1.f / l0f, inv1 = 1.f / l1f;
    int r0 = b * TT + wrow_min + gr;
    int r1 = r0 + 8;
    int cb = h * 64 + gc * 2;
#pragma unroll
    for (int dj = 0; dj < 8; dj++) {
        int col = cb + dj * 8;
        float2 x0 = *(const float2*)(x + (size_t)r0 * DD + col);
        float2 x1v = *(const float2*)(x + (size_t)r1 * DD + col);
        float2 o0 = { acc_o[dj][0] * inv0 + x0.x,  acc_o[dj][1] * inv0 + x0.y };
        float2 o1 = { acc_o[dj][2] * inv1 + x1v.x, acc_o[dj][3] * inv1 + x1v.y };
        *(float2*)(x1 + (size_t)r0 * DD + col) = o0;
        *(float2*)(x1 + (size_t)r1 * DD + col) = o1;
    }
#undef STAGE_KV
}

// ---------------- launch ----------------
#define DSM_MI2  (2 * (2 * 64 * 128 + 16384) + 1024)   // 66560
#define DSM_MI1  (2 * (1 * 64 * 128 + 16384) + 1024)   // 50176

extern "C" void kernel_launch(void* const* d_in, const int* in_sizes, int n_in,
                              void* d_out, int out_size) {
    const float* x      = (const float*)d_in[0];
    const float* Wq     = (const float*)d_in[1];
    const float* Wk     = (const float*)d_in[2];
    const float* Wv     = (const float*)d_in[3];
    const float* W1     = (const float*)d_in[4];
    const float* b1     = (const float*)d_in[5];
    const float* W2     = (const float*)d_in[6];
    const float* b2     = (const float*)d_in[7];
    const float* gamma1 = (const float*)d_in[8];
    const float* beta1  = (const float*)d_in[9];
    const float* gamma2 = (const float*)d_in[10];
    const float* beta2  = (const float*)d_in[11];
    float* out = (float*)d_out;

    __half *a_hi, *wqkv_hi, *w1_hi, *w2_hi, *f_hi, *qkv_hi;
    float *x1;
    cudaGetSymbolAddress((void**)&a_hi, g_a_hi);
    cudaGetSymbolAddress((void**)&wqkv_hi, g_wqkv_hi);
    cudaGetSymbolAddress((void**)&w1_hi, g_w1_hi);
    cudaGetSymbolAddress((void**)&w2_hi, g_w2_hi);
    cudaGetSymbolAddress((void**)&f_hi, g_ff1_hi);
    cudaGetSymbolAddress((void**)&qkv_hi, g_qkv_hi);
    cudaGetSymbolAddress((void**)&x1, g_x1);

    cudaFuncSetAttribute((hmma_gemm_kernel<2, 3>), cudaFuncAttributeMaxDynamicSharedMemorySize, DSM_MI2);
    cudaFuncSetAttribute((hmma_gemm_kernel<2, 1>), cudaFuncAttributeMaxDynamicSharedMemorySize, DSM_MI2);
    cudaFuncSetAttribute((hmma_gemm_kernel<1, 2>), cudaFuncAttributeMaxDynamicSharedMemorySize, DSM_MI1);
    cudaFuncSetAttribute(attn_hmma_kernel, cudaFuncAttributeMaxDynamicSharedMemorySize, AT_DSM);

    // 1. LN1 -> fp16
    ln_f16_kernel<<<MM, 256>>>(x, gamma1, beta1, a_hi);
    // 2. weight repacks (all coalesced tiled transposes)
    repack_qkv_kernel<<<dim3(2, 32, 48), dim3(32, 8)>>>(Wq, Wk, Wv, wqkv_hi);
    transpose_f16_kernel<<<dim3(DFF / 32, DD / 32), dim3(32, 8)>>>(W1, w1_hi, DD, DFF);
    transpose_f16_kernel<<<dim3(DD / 32, DFF / 32), dim3(32, 8)>>>(W2, w2_hi, DFF, DD);
    // 3. QKV projection -> fp16 (128x128 tiles)
    hmma_gemm_kernel<2, 3><<<dim3(3 * DD / 128, MM / 128), 256, DSM_MI2>>>(
        a_hi, wqkv_hi, DD, 3 * DD, nullptr, qkv_hi, nullptr, nullptr);
    // 4. HMMA flash attention + residual -> x1
    attn_hmma_kernel<<<dim3(TT / 128, BB * HH), 256, AT_DSM>>>(qkv_hi, x, x1);
    // 5. LN2 -> fp16
    ln_f16_kernel<<<MM, 256>>>(x1, gamma2, beta2, a_hi);
    // 6. FFN1: relu(h2 @ W1 + b1) -> fp16 (128x128 tiles)
    hmma_gemm_kernel<2, 1><<<dim3(DFF / 128, MM / 128), 256, DSM_MI2>>>(
        a_hi, w1_hi, DD, DFF, nullptr, f_hi, b1, nullptr);
    // 7. FFN2: ff1 @ W2 + b2 + x1 -> out (64x128 tiles, 512 CTAs for tail smoothing)
    hmma_gemm_kernel<1, 2><<<dim3(DD / 128, MM / 64), 256, DSM_MI1>>>(
        f_hi, w2_hi, DFF, DD, out, nullptr, b2, x1);
}

// round 12
// speedup vs baseline: 7.0325x; 1.0269x over previous
#include <cuda_runtime.h>
#include <cuda_fp16.h>
#include <cstdint>

// Problem constants
#define DD    1024
#define HH    16
#define DHD   64
#define DFF   4096
#define TT    2048
#define BB    2
#define MM    4096   // B*T

// ---------------- scratch (device globals; no allocation) ----------------
__device__ __half g_a_hi[MM * DD];                           // LN out (reused LN1/LN2)
__device__ __half g_wqkv_hi[3 * DD * DD];                    // [N=3072,K=1024]
__device__ __half g_w1_hi[DFF * DD];                         // [N=4096,K=1024]
__device__ __half g_w2_hi[DD * DFF];                         // [N=1024,K=4096]
__device__ __half g_ff1_hi[(size_t)MM * DFF];
__device__ __half g_qkv_hi[(size_t)MM * 3 * DD];
__device__ float g_x1 [MM * DD];

// ---------------- helpers ----------------
static __device__ __forceinline__ uint32_t su32(const void* p) {
    uint32_t a;
    asm("{ .reg .u64 t; cvta.to.shared.u64 t, %1; cvt.u32.u64 %0, t; }" : "=r"(a) : "l"(p));
    return a;
}
static __device__ __forceinline__ uint32_t sw128(uint32_t off) {
    return off ^ ((off >> 3) & 0x70);
}
static __device__ __forceinline__ void cpasync16(uint32_t dst, const void* src) {
    asm volatile("cp.async.cg.shared.global [%0], [%1], 16;" :: "r"(dst), "l"(src));
}
#define CP_COMMIT()  asm volatile("cp.async.commit_group;" ::: "memory")
#define CP_WAIT(n)   asm volatile("cp.async.wait_group %0;" :: "n"(n) : "memory")

static __device__ __forceinline__ void ldm_x4(uint32_t* r, uint32_t addr) {
    asm volatile("ldmatrix.sync.aligned.m8n8.x4.shared.b16 {%0,%1,%2,%3}, [%4];"
                 : "=r"(r[0]), "=r"(r[1]), "=r"(r[2]), "=r"(r[3]) : "r"(addr));
}
static __device__ __forceinline__ void ldm_x4t(uint32_t* r, uint32_t addr) {
    asm volatile("ldmatrix.sync.aligned.m8n8.x4.trans.shared.b16 {%0,%1,%2,%3}, [%4];"
                 : "=r"(r[0]), "=r"(r[1]), "=r"(r[2]), "=r"(r[3]) : "r"(addr));
}
static __device__ __forceinline__ void mma16816(float* d, const uint32_t* a, const uint32_t* b) {
    asm volatile(
        "mma.sync.aligned.m16n8k16.row.col.f32.f16.f16.f32 "
        "{%0,%1,%2,%3}, {%4,%5,%6,%7}, {%8,%9}, {%0,%1,%2,%3};"
        : "+f"(d[0]), "+f"(d[1]), "+f"(d[2]), "+f"(d[3])
        : "r"(a[0]), "r"(a[1]), "r"(a[2]), "r"(a[3]), "r"(b[0]), "r"(b[1]));
}
static __device__ __forceinline__ uint32_t packh(float a, float b) {
    __half2 t = __halves2half2(__float2half_rn(a), __float2half_rn(b));
    return *reinterpret_cast<uint32_t*>(&t);
}

// ---------------- LayerNorm (ddof=1), fp16 output ----------------
__global__ __launch_bounds__(256) void ln_f16_kernel(const float* __restrict__ x,
                                                     const float* __restrict__ g,
                                                     const float* __restrict__ bta,
                                                     __half* __restrict__ ohi) {
    int row = blockIdx.x;
    int tid = threadIdx.x;
    const float4* xr = (const float4*)(x + (size_t)row * DD);
    float4 v = xr[tid];
    float s  = v.x + v.y + v.z + v.w;
    float sq = v.x * v.x + v.y * v.y + v.z * v.z + v.w * v.w;
#pragma unroll
    for (int o = 16; o; o >>= 1) {
        s  += __shfl_xor_sync(0xffffffffu, s,  o);
        sq += __shfl_xor_sync(0xffffffffu, sq, o);
    }
    __shared__ float ss[8], sqs[8];
    int w = tid >> 5, ln = tid & 31;
    if (ln == 0) { ss[w] = s; sqs[w] = sq; }
    __syncthreads();
    s = 0.f; sq = 0.f;
#pragma unroll
    for (int i = 0; i < 8; i++) { s += ss[i]; sq += sqs[i]; }
    float mean = s * (1.f / 1024.f);
    float var  = (sq - 1024.f * mean * mean) * (1.f / 1023.f);
    float r    = rsqrtf(var + 1e-5f);
    float4 gv = ((const float4*)g)[tid];
    float4 bv = ((const float4*)bta)[tid];
    float o0 = gv.x * (v.x - mean) * r + bv.x;
    float o1 = gv.y * (v.y - mean) * r + bv.y;
    float o2 = gv.z * (v.z - mean) * r + bv.z;
    float o3 = gv.w * (v.w - mean) * r + bv.w;
    __half2* hp = (__half2*)(ohi + (size_t)row * DD);
    hp[tid * 2]     = __halves2half2(__float2half_rn(o0), __float2half_rn(o1));
    hp[tid * 2 + 1] = __halves2half2(__float2half_rn(o2), __float2half_rn(o3));
}

// ---------------- repack Wq/Wk/Wv [H,D,DH] -> [N=3072, K=1024] fp16 ----------------
// Tile: 64 k-rows x 32 e-cols; half2 stores (coalesced 128B both sides).
__global__ __launch_bounds__(256) void repack_qkv_kernel(const float* __restrict__ Wq,
                                                         const float* __restrict__ Wk,
                                                         const float* __restrict__ Wv,
                                                         __half* __restrict__ ohi) {
    __shared__ float t[64][33];
    int wh = blockIdx.z;          // 0..47: w*16+h
    int w = wh >> 4, h = wh & 15;
    int et = blockIdx.x * 32;     // 0 or 32
    int kt = blockIdx.y * 64;     // 0..960
    int tx = threadIdx.x, ty = threadIdx.y;   // 32 x 8
    const float* W = (w == 0) ? Wq : ((w == 1) ? Wk : Wv);
    const float* Wh = W + h * (DD * DHD);
#pragma unroll
    for (int i = 0; i < 64; i += 8)
        t[ty + i][tx] = Wh[(size_t)(kt + ty + i) * DHD + et + tx];   // coalesced over e
    __syncthreads();
    int nbase = w * 1024 + h * 64 + et;
#pragma unroll
    for (int i = 0; i < 32; i += 8) {
        int n = ty + i;
        __half2 v = __halves2half2(__float2half_rn(t[2 * tx][n]),
                                   __float2half_rn(t[2 * tx + 1][n]));
        *(__half2*)(ohi + (size_t)(nbase + n) * DD + kt + 2 * tx) = v;  // coalesced over k
    }
}

// ---------------- tiled transpose+convert: in [Kd, Nd] fp32 -> out [Nd, Kd] fp16 ----------------
// Tile: 64 k-rows x 32 n-cols; half2 stores.
__global__ __launch_bounds__(256) void transpose_f16_kernel(const float* __restrict__ in,
                                                            __half* __restrict__ ohi,
                                                            int Kd, int Nd) {
    __shared__ float t[64][33];
    int nt = blockIdx.x * 32, kt = blockIdx.y * 64;
    int tx = threadIdx.x, ty = threadIdx.y;   // 32 x 8
#pragma unroll
    for (int i = 0; i < 64; i += 8)
        t[ty + i][tx] = in[(size_t)(kt + ty + i) * Nd + nt + tx];
    __syncthreads();
#pragma unroll
    for (int i = 0; i < 32; i += 8) {
        int n = ty + i;
        __half2 v = __halves2half2(__float2half_rn(t[2 * tx][n]),
                                   __float2half_rn(t[2 * tx + 1][n]));
        *(__half2*)(ohi + (size_t)(nt + n) * Kd + kt + 2 * tx) = v;
    }
}

// ---------------- HMMA fp16 GEMM: C[M,N] = A[M,K] * B'[N,K]^T ----------------
// Tile: (64*MI) x 128, 8 warps as 4(M) x 2(N). K chunks of 64, double-buffered.
// EPI: 1 = relu(+bias)->fp16  2 = +bias+residual->fp32  3 = fp16
template <int MI, int EPI, int OCC>
__global__ __launch_bounds__(256, OCC) void hmma_gemm_kernel(const __half* __restrict__ Ahi,
                                                             const __half* __restrict__ Bhi,
                                                             int K, int N,
                                                             float* __restrict__ Cf,
                                                             __half* __restrict__ Chi,
                                                             const float* __restrict__ bias,
                                                             const float* __restrict__ res) {
    constexpr int TILE_A  = MI * 64 * 128;          // A tile bytes
    constexpr int TILE_Bb = 16384;                  // B tile bytes (128 rows)
    constexpr int STAGE   = TILE_A + TILE_Bb;

    extern __shared__ __align__(16) char dsm[];
    int tid  = threadIdx.x;
    int wid  = tid >> 5;
    int lane = tid & 31;
    int wm = wid & 3;
    int wn = wid >> 2;

    uint32_t b32 = su32(dsm);
    uint32_t pad = (1024u - (b32 & 1023u)) & 1023u;
    b32 += pad;

    const int m0 = blockIdx.y * (64 * MI);
    const int n0 = blockIdx.x * 128;
    const int nch = K >> 6;

    const __half* srcA = Ahi + (size_t)m0 * K;
    const __half* srcB = Bhi + (size_t)n0 * K;

#define STAGE_CHUNK(c)                                                            \
    do {                                                                          \
        uint32_t stg = b32 + ((c) & 1) * STAGE;                                   \
        int koff = (c) * 64;                                                      \
        _Pragma("unroll")                                                         \
        for (int i = 0; i < 2 * MI; i++) {                                        \
            int idx = i * 256 + tid;                                              \
            int row = idx >> 3, col = idx & 7;                                    \
            uint32_t so = sw128((uint32_t)(row * 128 + col * 16));                \
            cpasync16(stg + so, srcA + (size_t)row * K + koff + col * 8);         \
        }                                                                         \
        _Pragma("unroll")                                                         \
        for (int i = 0; i < 4; i++) {                                             \
            int idx = i * 256 + tid;                                              \
            int row = idx >> 3, col = idx & 7;                                    \
            uint32_t so = sw128((uint32_t)(row * 128 + col * 16));                \
            cpasync16(stg + TILE_A + so, srcB + (size_t)row * K + koff + col * 8);\
        }                                                                         \
        CP_COMMIT();                                                              \
    } while (0)

    float acc[MI][8][4];
#pragma unroll
    for (int mi = 0; mi < MI; mi++)
#pragma unroll
        for (int t = 0; t < 8; t++)
#pragma unroll
            for (int q = 0; q < 4; q++) acc[mi][t][q] = 0.f;

    int g  = lane >> 3;
    int li = lane & 7;
    int a_row0 = wm * (16 * MI) + (g & 1) * 8 + li;
    int a_kb   = (g >> 1) * 16;
    int b_row0 = wn * 64 + (g >> 1) * 8 + li;
    int b_kb   = (g & 1) * 16;

    STAGE_CHUNK(0);

    for (int c = 0; c < nch; c++) {
        if (c + 1 < nch) { STAGE_CHUNK(c + 1); CP_WAIT(1); }
        else             { CP_WAIT(0); }
        __syncthreads();

        uint32_t stg = b32 + (c & 1) * STAGE;
        uint32_t aB = stg, bB = stg + TILE_A;

#pragma unroll
        for (int ks = 0; ks < 4; ks++) {
            uint32_t ah[MI][4], bb[4][4];
#pragma unroll
            for (int mi = 0; mi < MI; mi++) {
                uint32_t off = sw128((uint32_t)((a_row0 + mi * 16) * 128 + ks * 32 + a_kb));
                ldm_x4(ah[mi], aB + off);
            }
#pragma unroll
            for (int j = 0; j < 4; j++) {
                uint32_t off = sw128((uint32_t)((b_row0 + j * 16) * 128 + ks * 32 + b_kb));
                ldm_x4(bb[j], bB + off);
            }
#pragma unroll
            for (int mi = 0; mi < MI; mi++)
#pragma unroll
                for (int t = 0; t < 8; t++)
                    mma16816(acc[mi][t], ah[mi], &bb[t >> 1][(t & 1) * 2]);
        }
        __syncthreads();
    }

    int r_base = m0 + wm * (16 * MI) + (lane >> 2);
    int n_base = n0 + wn * 64 + (lane & 3) * 2;
#pragma unroll
    for (int mi = 0; mi < MI; mi++) {
#pragma unroll
        for (int t = 0; t < 8; t++) {
            int r = r_base + mi * 16;
            int n = n_base + t * 8;
            float c0 = acc[mi][t][0], c1 = acc[mi][t][1];
            float c2 = acc[mi][t][2], c3 = acc[mi][t][3];
            if (EPI == 1 || EPI == 3) {
                float v0 = c0, v1 = c1, v2 = c2, v3 = c3;
                if (EPI == 1) {
                    float bi0 = bias[n], bi1 = bias[n + 1];
                    v0 = fmaxf(v0 + bi0, 0.f); v1 = fmaxf(v1 + bi1, 0.f);
                    v2 = fmaxf(v2 + bi0, 0.f); v3 = fmaxf(v3 + bi1, 0.f);
                }
                *(__half2*)(Chi + (size_t)r * N + n) =
                    __halves2half2(__float2half_rn(v0), __float2half_rn(v1));
                *(__half2*)(Chi + (size_t)(r + 8) * N + n) =
                    __halves2half2(__float2half_rn(v2), __float2half_rn(v3));
            } else {
                float bi0 = bias[n], bi1 = bias[n + 1];
                float2 r0 = *(const float2*)(res + (size_t)r * N + n);
                float2 r1 = *(const float2*)(res + (size_t)(r + 8) * N + n);
                float2 v0 = { c0 + bi0 + r0.x, c1 + bi1 + r0.y };
                float2 v1 = { c2 + bi0 + r1.x, c3 + bi1 + r1.y };
                *(float2*)(Cf + (size_t)r * N + n)       = v0;
                *(float2*)(Cf + (size_t)(r + 8) * N + n) = v1;
            }
        }
    }
#undef STAGE_CHUNK
}

// ---------------- HMMA flash attention (causal), pure fp16 ----------------
// 128-query CTA tile, 64-key tiles. QK: Qhi*Khi. PV: Phi*Vhi.
// smem stage: Khi[8K] | Vhi[8K] = 16KB, double-buffered.
#define AT_STAGE 16384
#define AT_DSM   (2 * AT_STAGE + 1024)

__global__ __launch_bounds__(256, 2) void attn_hmma_kernel(const __half* __restrict__ qkv_hi,
                                                           const float* __restrict__ x,
                                                           float* __restrict__ x1) {
    extern __shared__ __align__(16) char dsm[];
    int tid  = threadIdx.x;
    int wid  = tid >> 5;
    int lane = tid & 31;
    int g  = lane >> 3;
    int li = lane & 7;
    int gr = lane >> 2;
    int gc = lane & 3;

    uint32_t b32 = su32(dsm);
    uint32_t pad = (1024u - (b32 & 1023u)) & 1023u;
    b32 += pad;

    int qt = gridDim.x - 1 - blockIdx.x;     // big tiles first
    int bh = blockIdx.y;
    int b = bh >> 4, h = bh & 15;
    int qbase = qt * 128;

    const __half* qh_g = qkv_hi + (size_t)b * TT * 3072;

    // ---- stage Q, ldmatrix to regs ----
#pragma unroll
    for (int i = 0; i < 4; i++) {
        int idx = i * 256 + tid;
        int row = idx >> 3;
        int col = idx & 7;
        uint32_t so = sw128((uint32_t)(row * 128 + col * 16));
        size_t go = (size_t)(qbase + row) * 3072 + h * 64 + col * 8;
        cpasync16(b32 + so, qh_g + go);
    }
    CP_COMMIT();
    CP_WAIT(0);
    __syncthreads();

    uint32_t qfh[4][4];
    {
        int a_row = wid * 16 + (g & 1) * 8 + li;
        int a_kb  = (g >> 1) * 16;
#pragma unroll
        for (int ks = 0; ks < 4; ks++) {
            uint32_t off = sw128((uint32_t)(a_row * 128 + ks * 32 + a_kb));
            ldm_x4(qfh[ks], b32 + off);
        }
    }
    __syncthreads();   // Q regs done; smem free for K/V stages

    float m0f = -1e30f, m1f = -1e30f, l0f = 0.f, l1f = 0.f;
    float acc_o[8][4];
#pragma unroll
    for (int t = 0; t < 8; t++)
#pragma unroll
        for (int q = 0; q < 4; q++) acc_o[t][q] = 0.f;

    const int kts = 2 * qt + 2;
    const int wrow_min = qbase + wid * 16;
    const int wrow_max = wrow_min + 15;
    const int b_row = (g >> 1) * 8 + li;
    const int b_kb  = (g & 1) * 16;

#define STAGE_KV(c)                                                                     \
    do {                                                                                \
        uint32_t stg = b32 + ((c) & 1) * AT_STAGE;                                      \
        const __half* kh_g = qh_g + (size_t)((c) * 64) * 3072 + 1024 + h * 64;          \
        _Pragma("unroll")                                                               \
        for (int i = 0; i < 2; i++) {                                                   \
            int idx = i * 256 + tid;                                                    \
            int row = idx >> 3;                                                         \
            int col = idx & 7;                                                          \
            uint32_t so = sw128((uint32_t)(row * 128 + col * 16));                      \
            size_t go = (size_t)row * 3072 + col * 8;                                   \
            cpasync16(stg + so,         kh_g + go);                                     \
            cpasync16(stg + 8192 + so,  kh_g + 1024 + go);                              \
        }                                                                               \
        CP_COMMIT();                                                                    \
    } while (0)

    STAGE_KV(0);

    for (int kt = 0; kt < kts; kt++) {
        if (kt + 1 < kts) { STAGE_KV(kt + 1); CP_WAIT(1); }
        else              { CP_WAIT(0); }
        __syncthreads();

        if (kt * 64 <= wrow_max) {
            uint32_t stg = b32 + (kt & 1) * AT_STAGE;
            uint32_t khB = stg, vhB = stg + 8192;

            float sacc[8][4];
#pragma unroll
            for (int t = 0; t < 8; t++)
#pragma unroll
                for (int q = 0; q < 4; q++) sacc[t][q] = 0.f;

#pragma unroll
            for (int ks = 0; ks < 4; ks++) {
#pragma unroll
                for (int j = 0; j < 4; j++) {
                    uint32_t off = sw128((uint32_t)((j * 16 + b_row) * 128 + ks * 32 + b_kb));
                    uint32_t kb[4];
                    ldm_x4(kb, khB + off);
                    mma16816(sacc[2 * j],     qfh[ks], kb);
                    mma16816(sacc[2 * j + 1], qfh[ks], kb + 2);
                }
            }

            // scale + causal mask
            int row0 = wrow_min + gr;
            bool domask = (kt * 64 + 63) > wrow_min;
#pragma unroll
            for (int t = 0; t < 8; t++) {
                int colb = kt * 64 + t * 8 + gc * 2;
#pragma unroll
                for (int q = 0; q < 4; q++) {
                    float s = sacc[t][q] * 0.03125f;
                    if (domask) {
                        int col = colb + (q & 1);
                        int row = row0 + ((q >> 1) << 3);
                        if (col > row) s = -1e30f;
                    }
                    sacc[t][q] = s;
                }
            }
            // row max
            float tm0 = -1e30f, tm1 = -1e30f;
#pragma unroll
            for (int t = 0; t < 8; t++) {
                tm0 = fmaxf(tm0, fmaxf(sacc[t][0], sacc[t][1]));
                tm1 = fmaxf(tm1, fmaxf(sacc[t][2], sacc[t][3]));
            }
#pragma unroll
            for (int o = 1; o <= 2; o <<= 1) {
                tm0 = fmaxf(tm0, __shfl_xor_sync(0xffffffffu, tm0, o));
                tm1 = fmaxf(tm1, __shfl_xor_sync(0xffffffffu, tm1, o));
            }
            float mn0 = fmaxf(m0f, tm0), mn1 = fmaxf(m1f, tm1);
            float sc0 = __expf(m0f - mn0), sc1 = __expf(m1f - mn1);
            m0f = mn0; m1f = mn1;
            // exp + row sum
            float ls0 = 0.f, ls1 = 0.f;
#pragma unroll
            for (int t = 0; t < 8; t++) {
                float p0 = __expf(sacc[t][0] - mn0);
                float p1 = __expf(sacc[t][1] - mn0);
                float p2 = __expf(sacc[t][2] - mn1);
                float p3 = __expf(sacc[t][3] - mn1);
                sacc[t][0] = p0; sacc[t][1] = p1; sacc[t][2] = p2; sacc[t][3] = p3;
                ls0 += p0 + p1; ls1 += p2 + p3;
            }
#pragma unroll
            for (int o = 1; o <= 2; o <<= 1) {
                ls0 += __shfl_xor_sync(0xffffffffu, ls0, o);
                ls1 += __shfl_xor_sync(0xffffffffu, ls1, o);
            }
            l0f = l0f * sc0 + ls0;
            l1f = l1f * sc1 + ls1;
#pragma unroll
            for (int t = 0; t < 8; t++) {
                acc_o[t][0] *= sc0; acc_o[t][1] *= sc0;
                acc_o[t][2] *= sc1; acc_o[t][3] *= sc1;
            }
            // PV: Phi * Vhi
#pragma unroll
            for (int ks = 0; ks < 4; ks++) {
                float* p0 = sacc[2 * ks];
                float* p1 = sacc[2 * ks + 1];
                uint32_t ah[4];
                ah[0] = packh(p0[0], p0[1]);
                ah[1] = packh(p0[2], p0[3]);
                ah[2] = packh(p1[0], p1[1]);
                ah[3] = packh(p1[2], p1[3]);
#pragma unroll
                for (int dj = 0; dj < 4; dj++) {
                    // V trans ldmatrix: 16k x 16d
                    int krow = ks * 16 + (g & 1) * 8 + li;
                    int dcol = dj * 16 + (g >> 1) * 8;
                    uint32_t off = sw128((uint32_t)(krow * 128 + dcol * 2));
                    uint32_t vb[4];
                    ldm_x4t(vb, vhB + off);
                    mma16816(acc_o[2 * dj],     ah, vb);
                    mma16816(acc_o[2 * dj + 1], ah, vb + 2);
                }
            }
        }
        __syncthreads();
    }

    // epilogue: out = x + O/l
    float inv0 = 1.f / l0f, inv1 = 1.f / l1f;
    int r0 = b * TT + wrow_min + gr;
    int r1 = r0 + 8;
    int cb = h * 64 + gc * 2;
#pragma unroll
    for (int dj = 0; dj < 8; dj++) {
        int col = cb + dj * 8;
        float2 x0 = *(const float2*)(x + (size_t)r0 * DD + col);
        float2 x1v = *(const float2*)(x + (size_t)r1 * DD + col);
        float2 o0 = { acc_o[dj][0] * inv0 + x0.x,  acc_o[dj][1] * inv0 + x0.y };
        float2 o1 = { acc_o[dj][2] * inv1 + x1v.x, acc_o[dj][3] * inv1 + x1v.y };
        *(float2*)(x1 + (size_t)r0 * DD + col) = o0;
        *(float2*)(x1 + (size_t)r1 * DD + col) = o1;
    }
#undef STAGE_KV
}

// ---------------- launch ----------------
#define DSM_MI2  (2 * (2 * 64 * 128 + 16384) + 1024)   // 66560
#define DSM_MI1  (2 * (1 * 64 * 128 + 16384) + 1024)   // 50176

extern "C" void kernel_launch(void* const* d_in, const int* in_sizes, int n_in,
                              void* d_out, int out_size) {
    const float* x      = (const float*)d_in[0];
    const float* Wq     = (const float*)d_in[1];
    const float* Wk     = (const float*)d_in[2];
    const float* Wv     = (const float*)d_in[3];
    const float* W1     = (const float*)d_in[4];
    const float* b1     = (const float*)d_in[5];
    const float* W2     = (const float*)d_in[6];
    const float* b2     = (const float*)d_in[7];
    const float* gamma1 = (const float*)d_in[8];
    const float* beta1  = (const float*)d_in[9];
    const float* gamma2 = (const float*)d_in[10];
    const float* beta2  = (const float*)d_in[11];
    float* out = (float*)d_out;

    __half *a_hi, *wqkv_hi, *w1_hi, *w2_hi, *f_hi, *qkv_hi;
    float *x1;
    cudaGetSymbolAddress((void**)&a_hi, g_a_hi);
    cudaGetSymbolAddress((void**)&wqkv_hi, g_wqkv_hi);
    cudaGetSymbolAddress((void**)&w1_hi, g_w1_hi);
    cudaGetSymbolAddress((void**)&w2_hi, g_w2_hi);
    cudaGetSymbolAddress((void**)&f_hi, g_ff1_hi);
    cudaGetSymbolAddress((void**)&qkv_hi, g_qkv_hi);
    cudaGetSymbolAddress((void**)&x1, g_x1);

    cudaFuncSetAttribute((hmma_gemm_kernel<2, 3, 2>), cudaFuncAttributeMaxDynamicSharedMemorySize, DSM_MI2);
    cudaFuncSetAttribute((hmma_gemm_kernel<2, 1, 2>), cudaFuncAttributeMaxDynamicSharedMemorySize, DSM_MI2);
    cudaFuncSetAttribute((hmma_gemm_kernel<1, 2, 3>), cudaFuncAttributeMaxDynamicSharedMemorySize, DSM_MI1);
    cudaFuncSetAttribute(attn_hmma_kernel, cudaFuncAttributeMaxDynamicSharedMemorySize, AT_DSM);

    // 1. LN1 -> fp16
    ln_f16_kernel<<<MM, 256>>>(x, gamma1, beta1, a_hi);
    // 2. weight repacks (coalesced tiled transposes, half2 stores)
    repack_qkv_kernel<<<dim3(2, 16, 48), dim3(32, 8)>>>(Wq, Wk, Wv, wqkv_hi);
    transpose_f16_kernel<<<dim3(DFF / 32, DD / 64), dim3(32, 8)>>>(W1, w1_hi, DD, DFF);
    transpose_f16_kernel<<<dim3(DD / 32, DFF / 64), dim3(32, 8)>>>(W2, w2_hi, DFF, DD);
    // 3. QKV projection -> fp16 (128x128 tiles)
    hmma_gemm_kernel<2, 3, 2><<<dim3(3 * DD / 128, MM / 128), 256, DSM_MI2>>>(
        a_hi, wqkv_hi, DD, 3 * DD, nullptr, qkv_hi, nullptr, nullptr);
    // 4. HMMA flash attention + residual -> x1
    attn_hmma_kernel<<<dim3(TT / 128, BB * HH), 256, AT_DSM>>>(qkv_hi, x, x1);
    // 5. LN2 -> fp16
    ln_f16_kernel<<<MM, 256>>>(x1, gamma2, beta2, a_hi);
    // 6. FFN1: relu(h2 @ W1 + b1) -> fp16 (128x128 tiles)
    hmma_gemm_kernel<2, 1, 2><<<dim3(DFF / 128, MM / 128), 256, DSM_MI2>>>(
        a_hi, w1_hi, DD, DFF, nullptr, f_hi, b1, nullptr);
    // 7. FFN2: ff1 @ W2 + b2 + x1 -> out (64x128 tiles, occ 3 for tail smoothing)
    hmma_gemm_kernel<1, 2, 3><<<dim3(DD / 128, MM / 64), 256, DSM_MI1>>>(
        f_hi, w2_hi, DFF, DD, out, nullptr, b2, x1);
}

// round 13
// speedup vs baseline: 7.1461x; 1.0162x over previous
#include <cuda_runtime.h>
#include <cuda_fp16.h>
#include <cstdint>

// Problem constants
#define DD    1024
#define HH    16
#define DHD   64
#define DFF   4096
#define TT    2048
#define BB    2
#define MM    4096   // B*T

// Q pre-scale: (1/sqrt(1024)) * log2(e)  -> scores become base-2 logits
#define QSCALE 0.045084235f

// ---------------- scratch (device globals; no allocation) ----------------
__device__ __half g_a_hi[MM * DD];                           // LN out (reused LN1/LN2)
__device__ __half g_wqkv_hi[3 * DD * DD];                    // [N=3072,K=1024]
__device__ __half g_w1_hi[DFF * DD];                         // [N=4096,K=1024]
__device__ __half g_w2_hi[DD * DFF];                         // [N=1024,K=4096]
__device__ __half g_ff1_hi[(size_t)MM * DFF];
__device__ __half g_qkv_hi[(size_t)MM * 3 * DD];
__device__ float g_x1 [MM * DD];

// ---------------- helpers ----------------
static __device__ __forceinline__ uint32_t su32(const void* p) {
    uint32_t a;
    asm("{ .reg .u64 t; cvta.to.shared.u64 t, %1; cvt.u32.u64 %0, t; }" : "=r"(a) : "l"(p));
    return a;
}
static __device__ __forceinline__ uint32_t sw128(uint32_t off) {
    return off ^ ((off >> 3) & 0x70);
}
static __device__ __forceinline__ void cpasync16(uint32_t dst, const void* src) {
    asm volatile("cp.async.cg.shared.global [%0], [%1], 16;" :: "r"(dst), "l"(src));
}
#define CP_COMMIT()  asm volatile("cp.async.commit_group;" ::: "memory")
#define CP_WAIT(n)   asm volatile("cp.async.wait_group %0;" :: "n"(n) : "memory")

static __device__ __forceinline__ void ldm_x4(uint32_t* r, uint32_t addr) {
    asm volatile("ldmatrix.sync.aligned.m8n8.x4.shared.b16 {%0,%1,%2,%3}, [%4];"
                 : "=r"(r[0]), "=r"(r[1]), "=r"(r[2]), "=r"(r[3]) : "r"(addr));
}
static __device__ __forceinline__ void ldm_x4t(uint32_t* r, uint32_t addr) {
    asm volatile("ldmatrix.sync.aligned.m8n8.x4.trans.shared.b16 {%0,%1,%2,%3}, [%4];"
                 : "=r"(r[0]), "=r"(r[1]), "=r"(r[2]), "=r"(r[3]) : "r"(addr));
}
static __device__ __forceinline__ void mma16816(float* d, const uint32_t* a, const uint32_t* b) {
    asm volatile(
        "mma.sync.aligned.m16n8k16.row.col.f32.f16.f16.f32 "
        "{%0,%1,%2,%3}, {%4,%5,%6,%7}, {%8,%9}, {%0,%1,%2,%3};"
        : "+f"(d[0]), "+f"(d[1]), "+f"(d[2]), "+f"(d[3])
        : "r"(a[0]), "r"(a[1]), "r"(a[2]), "r"(a[3]), "r"(b[0]), "r"(b[1]));
}
// fp16-accumulator variant (2x rate on HMMA)
static __device__ __forceinline__ void mma16816h(uint32_t* d, const uint32_t* a, const uint32_t* b) {
    asm volatile(
        "mma.sync.aligned.m16n8k16.row.col.f16.f16.f16.f16 "
        "{%0,%1}, {%2,%3,%4,%5}, {%6,%7}, {%0,%1};"
        : "+r"(d[0]), "+r"(d[1])
        : "r"(a[0]), "r"(a[1]), "r"(a[2]), "r"(a[3]), "r"(b[0]), "r"(b[1]));
}
static __device__ __forceinline__ uint32_t packh(float a, float b) {
    __half2 t = __halves2half2(__float2half_rn(a), __float2half_rn(b));
    return *reinterpret_cast<uint32_t*>(&t);
}
static __device__ __forceinline__ float ex2(float x) {
    float r;
    asm("ex2.approx.f32 %0, %1;" : "=f"(r) : "f"(x));
    return r;
}

// ---------------- LayerNorm body (ddof=1), fp16 output ----------------
static __device__ __forceinline__ void ln_body(const float* __restrict__ x,
                                               const float* __restrict__ g,
                                               const float* __restrict__ bta,
                                               __half* __restrict__ ohi,
                                               int row, int tid, float* sred) {
    const float4* xr = (const float4*)(x + (size_t)row * DD);
    float4 v = xr[tid];
    float s  = v.x + v.y + v.z + v.w;
    float sq = v.x * v.x + v.y * v.y + v.z * v.z + v.w * v.w;
#pragma unroll
    for (int o = 16; o; o >>= 1) {
        s  += __shfl_xor_sync(0xffffffffu, s,  o);
        sq += __shfl_xor_sync(0xffffffffu, sq, o);
    }
    int w = tid >> 5, ln = tid & 31;
    if (ln == 0) { sred[w] = s; sred[8 + w] = sq; }
    __syncthreads();
    s = 0.f; sq = 0.f;
#pragma unroll
    for (int i = 0; i < 8; i++) { s += sred[i]; sq += sred[8 + i]; }
    float mean = s * (1.f / 1024.f);
    float var  = (sq - 1024.f * mean * mean) * (1.f / 1023.f);
    float r    = rsqrtf(var + 1e-5f);
    float4 gv = ((const float4*)g)[tid];
    float4 bv = ((const float4*)bta)[tid];
    float o0 = gv.x * (v.x - mean) * r + bv.x;
    float o1 = gv.y * (v.y - mean) * r + bv.y;
    float o2 = gv.z * (v.z - mean) * r + bv.z;
    float o3 = gv.w * (v.w - mean) * r + bv.w;
    __half2* hp = (__half2*)(ohi + (size_t)row * DD);
    hp[tid * 2]     = __halves2half2(__float2half_rn(o0), __float2half_rn(o1));
    hp[tid * 2 + 1] = __halves2half2(__float2half_rn(o2), __float2half_rn(o3));
}

// ---------------- standalone LN (for LN2) ----------------
__global__ __launch_bounds__(256) void ln_f16_kernel(const float* __restrict__ x,
                                                     const float* __restrict__ g,
                                                     const float* __restrict__ bta,
                                                     __half* __restrict__ ohi) {
    __shared__ float sred[16];
    ln_body(x, g, bta, ohi, blockIdx.x, threadIdx.x, sred);
}

// ---------------- PROLOGUE megakernel: LN1 + qkv repack + W1/W2 transposes ----------------
// blocks [0,4096): LN1 rows
// blocks [4096,5632): repack_qkv (1536 = 48 wh * 16 kt * 2 et)
// blocks [5632,7680): W1 transpose (2048 = 128 nt * 16 kt)
// blocks [7680,9728): W2 transpose (2048 = 32 nt * 64 kt)
__global__ __launch_bounds__(256) void prologue_kernel(const float* __restrict__ x,
                                                       const float* __restrict__ gamma1,
                                                       const float* __restrict__ beta1,
                                                       __half* __restrict__ a_hi,
                                                       const float* __restrict__ Wq,
                                                       const float* __restrict__ Wk,
                                                       const float* __restrict__ Wv,
                                                       __half* __restrict__ wqkv,
                                                       const float* __restrict__ W1,
                                                       __half* __restrict__ w1o,
                                                       const float* __restrict__ W2,
                                                       __half* __restrict__ w2o) {
    __shared__ float t[64][33];
    int bid = blockIdx.x;
    int tid = threadIdx.x;
    if (bid < MM) {
        ln_body(x, gamma1, beta1, a_hi, bid, tid, &t[0][0]);
        return;
    }
    bid -= MM;
    int tx = tid & 31, ty = tid >> 5;
    const float* in;
    __half* outp;
    int Kd, srcStride, nbase, et, kt;
    if (bid < 1536) {
        // repack qkv
        et = (bid & 1) * 32;
        kt = ((bid >> 1) & 15) * 64;
        int wh = bid >> 5;               // 0..47
        int w = wh >> 4, h = wh & 15;
        const float* W = (w == 0) ? Wq : ((w == 1) ? Wk : Wv);
        in = W + h * (DD * DHD);
        srcStride = DHD;
        outp = wqkv;
        Kd = DD;
        nbase = w * 1024 + h * 64 + et;
    } else if (bid < 1536 + 2048) {
        int idx = bid - 1536;
        et = (idx & 127) * 32;           // nt over DFF
        kt = (idx >> 7) * 64;            // kt over DD
        in = W1;
        srcStride = DFF;
        outp = w1o;
        Kd = DD;
        nbase = et;
    } else {
        int idx = bid - (1536 + 2048);
        et = (idx & 31) * 32;            // nt over DD
        kt = (idx >> 5) * 64;            // kt over DFF
        in = W2;
        srcStride = DD;
        outp = w2o;
        Kd = DFF;
        nbase = et;
    }
#pragma unroll
    for (int i = 0; i < 64; i += 8)
        t[ty + i][tx] = in[(size_t)(kt + ty + i) * srcStride + et + tx];
    __syncthreads();
#pragma unroll
    for (int i = 0; i < 32; i += 8) {
        int n = ty + i;
        __half2 v = __halves2half2(__float2half_rn(t[2 * tx][n]),
                                   __float2half_rn(t[2 * tx + 1][n]));
        *(__half2*)(outp + (size_t)(nbase + n) * Kd + kt + 2 * tx) = v;
    }
}

// ---------------- HMMA fp16 GEMM: C[M,N] = A[M,K] * B'[N,K]^T ----------------
// Tile: (64*MI) x 128, 8 warps as 4(M) x 2(N). K chunks of 64, double-buffered.
// EPI: 1 = relu(+bias)->fp16  2 = +bias+residual->fp32  3 = fp16 (Q cols pre-scaled by QSCALE)
template <int MI, int EPI, int OCC>
__global__ __launch_bounds__(256, OCC) void hmma_gemm_kernel(const __half* __restrict__ Ahi,
                                                             const __half* __restrict__ Bhi,
                                                             int K, int N,
                                                             float* __restrict__ Cf,
                                                             __half* __restrict__ Chi,
                                                             const float* __restrict__ bias,
                                                             const float* __restrict__ res) {
    constexpr int TILE_A  = MI * 64 * 128;          // A tile bytes
    constexpr int TILE_Bb = 16384;                  // B tile bytes (128 rows)
    constexpr int STAGE   = TILE_A + TILE_Bb;

    extern __shared__ __align__(16) char dsm[];
    int tid  = threadIdx.x;
    int wid  = tid >> 5;
    int lane = tid & 31;
    int wm = wid & 3;
    int wn = wid >> 2;

    uint32_t b32 = su32(dsm);
    uint32_t pad = (1024u - (b32 & 1023u)) & 1023u;
    b32 += pad;

    const int m0 = blockIdx.y * (64 * MI);
    const int n0 = blockIdx.x * 128;
    const int nch = K >> 6;

    const __half* srcA = Ahi + (size_t)m0 * K;
    const __half* srcB = Bhi + (size_t)n0 * K;

#define STAGE_CHUNK(c)                                                            \
    do {                                                                          \
        uint32_t stg = b32 + ((c) & 1) * STAGE;                                   \
        int koff = (c) * 64;                                                      \
        _Pragma("unroll")                                                         \
        for (int i = 0; i < 2 * MI; i++) {                                        \
            int idx = i * 256 + tid;                                              \
            int row = idx >> 3, col = idx & 7;                                    \
            uint32_t so = sw128((uint32_t)(row * 128 + col * 16));                \
            cpasync16(stg + so, srcA + (size_t)row * K + koff + col * 8);         \
        }                                                                         \
        _Pragma("unroll")                                                         \
        for (int i = 0; i < 4; i++) {                                             \
            int idx = i * 256 + tid;                                              \
            int row = idx >> 3, col = idx & 7;                                    \
            uint32_t so = sw128((uint32_t)(row * 128 + col * 16));                \
            cpasync16(stg + TILE_A + so, srcB + (size_t)row * K + koff + col * 8);\
        }                                                                         \
        CP_COMMIT();                                                              \
    } while (0)

    float acc[MI][8][4];
#pragma unroll
    for (int mi = 0; mi < MI; mi++)
#pragma unroll
        for (int t = 0; t < 8; t++)
#pragma unroll
            for (int q = 0; q < 4; q++) acc[mi][t][q] = 0.f;

    int g  = lane >> 3;
    int li = lane & 7;
    int a_row0 = wm * (16 * MI) + (g & 1) * 8 + li;
    int a_kb   = (g >> 1) * 16;
    int b_row0 = wn * 64 + (g >> 1) * 8 + li;
    int b_kb   = (g & 1) * 16;

    STAGE_CHUNK(0);

    for (int c = 0; c < nch; c++) {
        if (c + 1 < nch) { STAGE_CHUNK(c + 1); CP_WAIT(1); }
        else             { CP_WAIT(0); }
        __syncthreads();

        uint32_t stg = b32 + (c & 1) * STAGE;
        uint32_t aB = stg, bB = stg + TILE_A;

#pragma unroll
        for (int ks = 0; ks < 4; ks++) {
            uint32_t ah[MI][4], bb[4][4];
#pragma unroll
            for (int mi = 0; mi < MI; mi++) {
                uint32_t off = sw128((uint32_t)((a_row0 + mi * 16) * 128 + ks * 32 + a_kb));
                ldm_x4(ah[mi], aB + off);
            }
#pragma unroll
            for (int j = 0; j < 4; j++) {
                uint32_t off = sw128((uint32_t)((b_row0 + j * 16) * 128 + ks * 32 + b_kb));
                ldm_x4(bb[j], bB + off);
            }
#pragma unroll
            for (int mi = 0; mi < MI; mi++)
#pragma unroll
                for (int t = 0; t < 8; t++)
                    mma16816(acc[mi][t], ah[mi], &bb[t >> 1][(t & 1) * 2]);
        }
        __syncthreads();
    }

    int r_base = m0 + wm * (16 * MI) + (lane >> 2);
    int n_base = n0 + wn * 64 + (lane & 3) * 2;
#pragma unroll
    for (int mi = 0; mi < MI; mi++) {
#pragma unroll
        for (int t = 0; t < 8; t++) {
            int r = r_base + mi * 16;
            int n = n_base + t * 8;
            float c0 = acc[mi][t][0], c1 = acc[mi][t][1];
            float c2 = acc[mi][t][2], c3 = acc[mi][t][3];
            if (EPI == 1 || EPI == 3) {
                float v0 = c0, v1 = c1, v2 = c2, v3 = c3;
                if (EPI == 1) {
                    float bi0 = bias[n], bi1 = bias[n + 1];
                    v0 = fmaxf(v0 + bi0, 0.f); v1 = fmaxf(v1 + bi1, 0.f);
                    v2 = fmaxf(v2 + bi0, 0.f); v3 = fmaxf(v3 + bi1, 0.f);
                }
                if (EPI == 3 && n < DD) {   // Q columns: fold softmax scale * log2e
                    v0 *= QSCALE; v1 *= QSCALE; v2 *= QSCALE; v3 *= QSCALE;
                }
                *(__half2*)(Chi + (size_t)r * N + n) =
                    __halves2half2(__float2half_rn(v0), __float2half_rn(v1));
                *(__half2*)(Chi + (size_t)(r + 8) * N + n) =
                    __halves2half2(__float2half_rn(v2), __float2half_rn(v3));
            } else {
                float bi0 = bias[n], bi1 = bias[n + 1];
                float2 r0 = *(const float2*)(res + (size_t)r * N + n);
                float2 r1 = *(const float2*)(res + (size_t)(r + 8) * N + n);
                float2 v0 = { c0 + bi0 + r0.x, c1 + bi1 + r0.y };
                float2 v1 = { c2 + bi0 + r1.x, c3 + bi1 + r1.y };
                *(float2*)(Cf + (size_t)r * N + n)       = v0;
                *(float2*)(Cf + (size_t)(r + 8) * N + n) = v1;
            }
        }
    }
#undef STAGE_CHUNK
}

// ---------------- HMMA flash attention (causal), pure fp16 ----------------
// 128-query CTA tile, 64-key tiles. QK: fp16-accum (Q pre-scaled, base-2 logits).
// PV: fp32-accum. smem stage: Khi[8K] | Vhi[8K] = 16KB, double-buffered.
#define AT_STAGE 16384
#define AT_DSM   (2 * AT_STAGE + 1024)

__global__ __launch_bounds__(256, 2) void attn_hmma_kernel(const __half* __restrict__ qkv_hi,
                                                           const float* __restrict__ x,
                                                           float* __restrict__ x1) {
    extern __shared__ __align__(16) char dsm[];
    int tid  = threadIdx.x;
    int wid  = tid >> 5;
    int lane = tid & 31;
    int g  = lane >> 3;
    int li = lane & 7;
    int gr = lane >> 2;
    int gc = lane & 3;

    uint32_t b32 = su32(dsm);
    uint32_t pad = (1024u - (b32 & 1023u)) & 1023u;
    b32 += pad;

    int qt = gridDim.x - 1 - blockIdx.x;     // big tiles first
    int bh = blockIdx.y;
    int b = bh >> 4, h = bh & 15;
    int qbase = qt * 128;

    const __half* qh_g = qkv_hi + (size_t)b * TT * 3072;

    // ---- stage Q, ldmatrix to regs ----
#pragma unroll
    for (int i = 0; i < 4; i++) {
        int idx = i * 256 + tid;
        int row = idx >> 3;
        int col = idx & 7;
        uint32_t so = sw128((uint32_t)(row * 128 + col * 16));
        size_t go = (size_t)(qbase + row) * 3072 + h * 64 + col * 8;
        cpasync16(b32 + so, qh_g + go);
    }
    CP_COMMIT();
    CP_WAIT(0);
    __syncthreads();

    uint32_t qfh[4][4];
    {
        int a_row = wid * 16 + (g & 1) * 8 + li;
        int a_kb  = (g >> 1) * 16;
#pragma unroll
        for (int ks = 0; ks < 4; ks++) {
            uint32_t off = sw128((uint32_t)(a_row * 128 + ks * 32 + a_kb));
            ldm_x4(qfh[ks], b32 + off);
        }
    }
    __syncthreads();   // Q regs done; smem free for K/V stages

    float m0f = -1e30f, m1f = -1e30f, l0f = 0.f, l1f = 0.f;
    float acc_o[8][4];
#pragma unroll
    for (int t = 0; t < 8; t++)
#pragma unroll
        for (int q = 0; q < 4; q++) acc_o[t][q] = 0.f;

    const int kts = 2 * qt + 2;
    const int wrow_min = qbase + wid * 16;
    const int wrow_max = wrow_min + 15;
    const int b_row = (g >> 1) * 8 + li;
    const int b_kb  = (g & 1) * 16;

#define STAGE_KV(c)                                                                     \
    do {                                                                                \
        uint32_t stg = b32 + ((c) & 1) * AT_STAGE;                                      \
        const __half* kh_g = qh_g + (size_t)((c) * 64) * 3072 + 1024 + h * 64;          \
        _Pragma("unroll")                                                               \
        for (int i = 0; i < 2; i++) {                                                   \
            int idx = i * 256 + tid;                                                    \
            int row = idx >> 3;                                                         \
            int col = idx & 7;                                                          \
            uint32_t so = sw128((uint32_t)(row * 128 + col * 16));                      \
            size_t go = (size_t)row * 3072 + col * 8;                                   \
            cpasync16(stg + so,         kh_g + go);                                     \
            cpasync16(stg + 8192 + so,  kh_g + 1024 + go);                              \
        }                                                                               \
        CP_COMMIT();                                                                    \
    } while (0)

    STAGE_KV(0);

    for (int kt = 0; kt < kts; kt++) {
        if (kt + 1 < kts) { STAGE_KV(kt + 1); CP_WAIT(1); }
        else              { CP_WAIT(0); }
        __syncthreads();

        if (kt * 64 <= wrow_max) {
            uint32_t stg = b32 + (kt & 1) * AT_STAGE;
            uint32_t khB = stg, vhB = stg + 8192;

            // QK with fp16 accumulators (2x HMMA rate)
            uint32_t sacch[8][2];
#pragma unroll
            for (int t = 0; t < 8; t++) { sacch[t][0] = 0u; sacch[t][1] = 0u; }

#pragma unroll
            for (int ks = 0; ks < 4; ks++) {
#pragma unroll
                for (int j = 0; j < 4; j++) {
                    uint32_t off = sw128((uint32_t)((j * 16 + b_row) * 128 + ks * 32 + b_kb));
                    uint32_t kb[4];
                    ldm_x4(kb, khB + off);
                    mma16816h(sacch[2 * j],     qfh[ks], kb);
                    mma16816h(sacch[2 * j + 1], qfh[ks], kb + 2);
                }
            }

            // unpack to fp32 + causal mask (scores already base-2 logits)
            float sacc[8][4];
            int row0 = wrow_min + gr;
            bool domask = (kt * 64 + 63) > wrow_min;
#pragma unroll
            for (int t = 0; t < 8; t++) {
                float2 u0 = __half22float2(*reinterpret_cast<__half2*>(&sacch[t][0]));
                float2 u1 = __half22float2(*reinterpret_cast<__half2*>(&sacch[t][1]));
                sacc[t][0] = u0.x; sacc[t][1] = u0.y;
                sacc[t][2] = u1.x; sacc[t][3] = u1.y;
                if (domask) {
                    int colb = kt * 64 + t * 8 + gc * 2;
#pragma unroll
                    for (int q = 0; q < 4; q++) {
                        int col = colb + (q & 1);
                        int row = row0 + ((q >> 1) << 3);
                        if (col > row) sacc[t][q] = -1e30f;
                    }
                }
            }
            // row max
            float tm0 = -1e30f, tm1 = -1e30f;
#pragma unroll
            for (int t = 0; t < 8; t++) {
                tm0 = fmaxf(tm0, fmaxf(sacc[t][0], sacc[t][1]));
                tm1 = fmaxf(tm1, fmaxf(sacc[t][2], sacc[t][3]));
            }
#pragma unroll
            for (int o = 1; o <= 2; o <<= 1) {
                tm0 = fmaxf(tm0, __shfl_xor_sync(0xffffffffu, tm0, o));
                tm1 = fmaxf(tm1, __shfl_xor_sync(0xffffffffu, tm1, o));
            }
            float mn0 = fmaxf(m0f, tm0), mn1 = fmaxf(m1f, tm1);
            float sc0 = ex2(m0f - mn0), sc1 = ex2(m1f - mn1);
            m0f = mn0; m1f = mn1;
            // exp2 + row sum
            float ls0 = 0.f, ls1 = 0.f;
#pragma unroll
            for (int t = 0; t < 8; t++) {
                float p0 = ex2(sacc[t][0] - mn0);
                float p1 = ex2(sacc[t][1] - mn0);
                float p2 = ex2(sacc[t][2] - mn1);
                float p3 = ex2(sacc[t][3] - mn1);
                sacc[t][0] = p0; sacc[t][1] = p1; sacc[t][2] = p2; sacc[t][3] = p3;
                ls0 += p0 + p1; ls1 += p2 + p3;
            }
#pragma unroll
            for (int o = 1; o <= 2; o <<= 1) {
                ls0 += __shfl_xor_sync(0xffffffffu, ls0, o);
                ls1 += __shfl_xor_sync(0xffffffffu, ls1, o);
            }
            l0f = l0f * sc0 + ls0;
            l1f = l1f * sc1 + ls1;
#pragma unroll
            for (int t = 0; t < 8; t++) {
                acc_o[t][0] *= sc0; acc_o[t][1] *= sc0;
                acc_o[t][2] *= sc1; acc_o[t][3] *= sc1;
            }
            // PV: Phi * Vhi (fp32 accum)
#pragma unroll
            for (int ks = 0; ks < 4; ks++) {
                float* p0 = sacc[2 * ks];
                float* p1 = sacc[2 * ks + 1];
                uint32_t ah[4];
                ah[0] = packh(p0[0], p0[1]);
                ah[1] = packh(p0[2], p0[3]);
                ah[2] = packh(p1[0], p1[1]);
                ah[3] = packh(p1[2], p1[3]);
#pragma unroll
                for (int dj = 0; dj < 4; dj++) {
                    // V trans ldmatrix: 16k x 16d
                    int krow = ks * 16 + (g & 1) * 8 + li;
                    int dcol = dj * 16 + (g >> 1) * 8;
                    uint32_t off = sw128((uint32_t)(krow * 128 + dcol * 2));
                    uint32_t vb[4];
                    ldm_x4t(vb, vhB + off);
                    mma16816(acc_o[2 * dj],     ah, vb);
                    mma16816(acc_o[2 * dj + 1], ah, vb + 2);
                }
            }
        }
        __syncthreads();
    }

    // epilogue: out = x + O/l
    float inv0 = 1.f / l0f, inv1 = 1.f / l1f;
    int r0 = b * TT + wrow_min + gr;
    int r1 = r0 + 8;
    int cb = h * 64 + gc * 2;
#pragma unroll
    for (int dj = 0; dj < 8; dj++) {
        int col = cb + dj * 8;
        float2 x0 = *(const float2*)(x + (size_t)r0 * DD + col);
        float2 x1v = *(const float2*)(x + (size_t)r1 * DD + col);
        float2 o0 = { acc_o[dj][0] * inv0 + x0.x,  acc_o[dj][1] * inv0 + x0.y };
        float2 o1 = { acc_o[dj][2] * inv1 + x1v.x, acc_o[dj][3] * inv1 + x1v.y };
        *(float2*)(x1 + (size_t)r0 * DD + col) = o0;
        *(float2*)(x1 + (size_t)r1 * DD + col) = o1;
    }
#undef STAGE_KV
}

// ---------------- launch ----------------
#define DSM_MI2  (2 * (2 * 64 * 128 + 16384) + 1024)   // 66560
#define DSM_MI1  (2 * (1 * 64 * 128 + 16384) + 1024)   // 50176

extern "C" void kernel_launch(void* const* d_in, const int* in_sizes, int n_in,
                              void* d_out, int out_size) {
    const float* x      = (const float*)d_in[0];
    const float* Wq     = (const float*)d_in[1];
    const float* Wk     = (const float*)d_in[2];
    const float* Wv     = (const float*)d_in[3];
    const float* W1     = (const float*)d_in[4];
    const float* b1     = (const float*)d_in[5];
    const float* W2     = (const float*)d_in[6];
    const float* b2     = (const float*)d_in[7];
    const float* gamma1 = (const float*)d_in[8];
    const float* beta1  = (const float*)d_in[9];
    const float* gamma2 = (const float*)d_in[10];
    const float* beta2  = (const float*)d_in[11];
    float* out = (float*)d_out;

    __half *a_hi, *wqkv_hi, *w1_hi, *w2_hi, *f_hi, *qkv_hi;
    float *x1;
    cudaGetSymbolAddress((void**)&a_hi, g_a_hi);
    cudaGetSymbolAddress((void**)&wqkv_hi, g_wqkv_hi);
    cudaGetSymbolAddress((void**)&w1_hi, g_w1_hi);
    cudaGetSymbolAddress((void**)&w2_hi, g_w2_hi);
    cudaGetSymbolAddress((void**)&f_hi, g_ff1_hi);
    cudaGetSymbolAddress((void**)&qkv_hi, g_qkv_hi);
    cudaGetSymbolAddress((void**)&x1, g_x1);

    cudaFuncSetAttribute((hmma_gemm_kernel<2, 3, 2>), cudaFuncAttributeMaxDynamicSharedMemorySize, DSM_MI2);
    cudaFuncSetAttribute((hmma_gemm_kernel<2, 1, 2>), cudaFuncAttributeMaxDynamicSharedMemorySize, DSM_MI2);
    cudaFuncSetAttribute((hmma_gemm_kernel<1, 2, 3>), cudaFuncAttributeMaxDynamicSharedMemorySize, DSM_MI1);
    cudaFuncSetAttribute(attn_hmma_kernel, cudaFuncAttributeMaxDynamicSharedMemorySize, AT_DSM);

    // 1. Prologue: LN1 + all weight repacks in ONE launch
    prologue_kernel<<<MM + 1536 + 2048 + 2048, 256>>>(
        x, gamma1, beta1, a_hi, Wq, Wk, Wv, wqkv_hi, W1, w1_hi, W2, w2_hi);
    // 2. QKV projection -> fp16 (Q cols pre-scaled by QSCALE)
    hmma_gemm_kernel<2, 3, 2><<<dim3(3 * DD / 128, MM / 128), 256, DSM_MI2>>>(
        a_hi, wqkv_hi, DD, 3 * DD, nullptr, qkv_hi, nullptr, nullptr);
    // 3. HMMA flash attention + residual -> x1
    attn_hmma_kernel<<<dim3(TT / 128, BB * HH), 256, AT_DSM>>>(qkv_hi, x, x1);
    // 4. LN2 -> fp16
    ln_f16_kernel<<<MM, 256>>>(x1, gamma2, beta2, a_hi);
    // 5. FFN1: relu(h2 @ W1 + b1) -> fp16 (128x128 tiles)
    hmma_gemm_kernel<2, 1, 2><<<dim3(DFF / 128, MM / 128), 256, DSM_MI2>>>(
        a_hi, w1_hi, DD, DFF, nullptr, f_hi, b1, nullptr);
    // 6. FFN2: ff1 @ W2 + b2 + x1 -> out (64x128 tiles, occ 3 for tail smoothing)
    hmma_gemm_kernel<1, 2, 3><<<dim3(DD / 128, MM / 64), 256, DSM_MI1>>>(
        f_hi, w2_hi, DFF, DD, out, nullptr, b2, x1);
}

// round 14
// speedup vs baseline: 7.1837x; 1.0053x over previous
#include <cuda_runtime.h>
#include <cuda_fp16.h>
#include <cstdint>

// Problem constants
#define DD    1024
#define HH    16
#define DHD   64
#define DFF   4096
#define TT    2048
#define BB    2
#define MM    4096   // B*T

// Q pre-scale: (1/sqrt(1024)) * log2(e)  -> scores become base-2 logits
#define QSCALE 0.045084235f

// ---------------- scratch (device globals; no allocation) ----------------
__device__ __half g_a_hi[MM * DD];                           // LN1 out
__device__ __half g_wqkv_hi[3 * DD * DD];                    // [N=3072,K=1024]
__device__ __half g_w1_hi[DFF * DD];                         // gamma2-folded W1' [N=4096,K=1024]
__device__ __half g_w2_hi[DD * DFF];                         // [N=1024,K=4096]
__device__ __half g_ff1_hi[(size_t)MM * DFF];
__device__ __half g_qkv_hi[(size_t)MM * 3 * DD];
__device__ float  g_x1 [MM * DD];                            // x + attn (fp32, for final residual)
__device__ __half g_x1h[MM * DD];                            // x + attn (fp16, FFN1 A input)
__device__ float2 g_stats[MM];                               // per-row {mean, rsqrt}
__device__ float  g_c1[DFF];                                 // sum_d gamma2_d W1[d,n]
__device__ float  g_cb[DFF];                                 // sum_d beta2_d W1[d,n] + b1[n]

// ---------------- helpers ----------------
static __device__ __forceinline__ uint32_t su32(const void* p) {
    uint32_t a;
    asm("{ .reg .u64 t; cvta.to.shared.u64 t, %1; cvt.u32.u64 %0, t; }" : "=r"(a) : "l"(p));
    return a;
}
static __device__ __forceinline__ uint32_t sw128(uint32_t off) {
    return off ^ ((off >> 3) & 0x70);
}
static __device__ __forceinline__ void cpasync16(uint32_t dst, const void* src) {
    asm volatile("cp.async.cg.shared.global [%0], [%1], 16;" :: "r"(dst), "l"(src));
}
#define CP_COMMIT()  asm volatile("cp.async.commit_group;" ::: "memory")
#define CP_WAIT(n)   asm volatile("cp.async.wait_group %0;" :: "n"(n) : "memory")

static __device__ __forceinline__ void ldm_x4(uint32_t* r, uint32_t addr) {
    asm volatile("ldmatrix.sync.aligned.m8n8.x4.shared.b16 {%0,%1,%2,%3}, [%4];"
                 : "=r"(r[0]), "=r"(r[1]), "=r"(r[2]), "=r"(r[3]) : "r"(addr));
}
static __device__ __forceinline__ void ldm_x4t(uint32_t* r, uint32_t addr) {
    asm volatile("ldmatrix.sync.aligned.m8n8.x4.trans.shared.b16 {%0,%1,%2,%3}, [%4];"
                 : "=r"(r[0]), "=r"(r[1]), "=r"(r[2]), "=r"(r[3]) : "r"(addr));
}
static __device__ __forceinline__ void mma16816(float* d, const uint32_t* a, const uint32_t* b) {
    asm volatile(
        "mma.sync.aligned.m16n8k16.row.col.f32.f16.f16.f32 "
        "{%0,%1,%2,%3}, {%4,%5,%6,%7}, {%8,%9}, {%0,%1,%2,%3};"
        : "+f"(d[0]), "+f"(d[1]), "+f"(d[2]), "+f"(d[3])
        : "r"(a[0]), "r"(a[1]), "r"(a[2]), "r"(a[3]), "r"(b[0]), "r"(b[1]));
}
// fp16-accumulator variant
static __device__ __forceinline__ void mma16816h(uint32_t* d, const uint32_t* a, const uint32_t* b) {
    asm volatile(
        "mma.sync.aligned.m16n8k16.row.col.f16.f16.f16.f16 "
        "{%0,%1}, {%2,%3,%4,%5}, {%6,%7}, {%0,%1};"
        : "+r"(d[0]), "+r"(d[1])
        : "r"(a[0]), "r"(a[1]), "r"(a[2]), "r"(a[3]), "r"(b[0]), "r"(b[1]));
}
static __device__ __forceinline__ uint32_t packh(float a, float b) {
    __half2 t = __halves2half2(__float2half_rn(a), __float2half_rn(b));
    return *reinterpret_cast<uint32_t*>(&t);
}
static __device__ __forceinline__ float ex2(float x) {
    float r;
    asm("ex2.approx.f32 %0, %1;" : "=f"(r) : "f"(x));
    return r;
}

// ---------------- LayerNorm body (ddof=1), fp16 output ----------------
static __device__ __forceinline__ void ln_body(const float* __restrict__ x,
                                               const float* __restrict__ g,
                                               const float* __restrict__ bta,
                                               __half* __restrict__ ohi,
                                               int row, int tid, float* sred) {
    const float4* xr = (const float4*)(x + (size_t)row * DD);
    float4 v = xr[tid];
    float s  = v.x + v.y + v.z + v.w;
    float sq = v.x * v.x + v.y * v.y + v.z * v.z + v.w * v.w;
#pragma unroll
    for (int o = 16; o; o >>= 1) {
        s  += __shfl_xor_sync(0xffffffffu, s,  o);
        sq += __shfl_xor_sync(0xffffffffu, sq, o);
    }
    int w = tid >> 5, ln = tid & 31;
    if (ln == 0) { sred[w] = s; sred[8 + w] = sq; }
    __syncthreads();
    s = 0.f; sq = 0.f;
#pragma unroll
    for (int i = 0; i < 8; i++) { s += sred[i]; sq += sred[8 + i]; }
    float mean = s * (1.f / 1024.f);
    float var  = (sq - 1024.f * mean * mean) * (1.f / 1023.f);
    float r    = rsqrtf(var + 1e-5f);
    float4 gv = ((const float4*)g)[tid];
    float4 bv = ((const float4*)bta)[tid];
    float o0 = gv.x * (v.x - mean) * r + bv.x;
    float o1 = gv.y * (v.y - mean) * r + bv.y;
    float o2 = gv.z * (v.z - mean) * r + bv.z;
    float o3 = gv.w * (v.w - mean) * r + bv.w;
    __half2* hp = (__half2*)(ohi + (size_t)row * DD);
    hp[tid * 2]     = __halves2half2(__float2half_rn(o0), __float2half_rn(o1));
    hp[tid * 2 + 1] = __halves2half2(__float2half_rn(o2), __float2half_rn(o3));
}

// ---------------- row stats (ddof=1) from fp16 x1 ----------------
__global__ __launch_bounds__(256) void stats_kernel(const __half* __restrict__ xh,
                                                    float2* __restrict__ st) {
    __shared__ float sred[16];
    int row = blockIdx.x;
    int tid = threadIdx.x;
    const __half2* xr = (const __half2*)(xh + (size_t)row * DD);
    float2 a = __half22float2(xr[tid * 2]);
    float2 b = __half22float2(xr[tid * 2 + 1]);
    float s  = a.x + a.y + b.x + b.y;
    float sq = a.x * a.x + a.y * a.y + b.x * b.x + b.y * b.y;
#pragma unroll
    for (int o = 16; o; o >>= 1) {
        s  += __shfl_xor_sync(0xffffffffu, s,  o);
        sq += __shfl_xor_sync(0xffffffffu, sq, o);
    }
    int w = tid >> 5, ln = tid & 31;
    if (ln == 0) { sred[w] = s; sred[8 + w] = sq; }
    __syncthreads();
    if (tid == 0) {
        s = 0.f; sq = 0.f;
#pragma unroll
        for (int i = 0; i < 8; i++) { s += sred[i]; sq += sred[8 + i]; }
        float mean = s * (1.f / 1024.f);
        float var  = (sq - 1024.f * mean * mean) * (1.f / 1023.f);
        st[row] = make_float2(mean, rsqrtf(var + 1e-5f));
    }
}

// ---------------- PROLOGUE megakernel ----------------
// [0,4096): LN1 rows
// [4096,5632): qkv repack (1536)
// [5632,7680): W1 transpose, gamma2-folded (2048)
// [7680,9728): W2 transpose (2048)
// [9728,10752): zero out (1024)
// [10752,10880): c1/cb columns (128)
#define NB_LN   4096
#define NB_QKV  1536
#define NB_W1   2048
#define NB_W2   2048
#define NB_ZERO 1024
#define NB_C    128
#define NB_TOT  (NB_LN + NB_QKV + NB_W1 + NB_W2 + NB_ZERO + NB_C)

__global__ __launch_bounds__(256) void prologue_kernel(const float* __restrict__ x,
                                                       const float* __restrict__ gamma1,
                                                       const float* __restrict__ beta1,
                                                       __half* __restrict__ a_hi,
                                                       const float* __restrict__ Wq,
                                                       const float* __restrict__ Wk,
                                                       const float* __restrict__ Wv,
                                                       __half* __restrict__ wqkv,
                                                       const float* __restrict__ W1,
                                                       __half* __restrict__ w1o,
                                                       const float* __restrict__ W2,
                                                       __half* __restrict__ w2o,
                                                       const float* __restrict__ gamma2,
                                                       const float* __restrict__ beta2,
                                                       const float* __restrict__ b1,
                                                       float* __restrict__ c1,
                                                       float* __restrict__ cb,
                                                       float* __restrict__ outz) {
    __shared__ float t[64][33];
    int bid = blockIdx.x;
    int tid = threadIdx.x;
    if (bid < NB_LN) {
        ln_body(x, gamma1, beta1, a_hi, bid, tid, &t[0][0]);
        return;
    }
    bid -= NB_LN;
    if (bid >= NB_QKV + NB_W1 + NB_W2) {
        bid -= NB_QKV + NB_W1 + NB_W2;
        if (bid < NB_ZERO) {
            // zero the output buffer (for split-K atomics)
            float4 z = { 0.f, 0.f, 0.f, 0.f };
            float4* o = (float4*)outz + (size_t)bid * 1024;
#pragma unroll
            for (int i = 0; i < 4; i++) o[i * 256 + tid] = z;
        } else {
            // c1/cb: 128 blocks x 32 n-cols each
            int nt = (bid - NB_ZERO) * 32;
            int col = tid & 31, dg = tid >> 5;
            float s1 = 0.f, s2 = 0.f;
            for (int d = dg * 128; d < dg * 128 + 128; d++) {
                float w = W1[(size_t)d * DFF + nt + col];
                s1 += gamma2[d] * w;
                s2 += beta2[d] * w;
            }
            float* red = &t[0][0];
            red[dg * 32 + col] = s1;
            red[256 + dg * 32 + col] = s2;
            __syncthreads();
            if (dg == 0) {
                float a = 0.f, b = 0.f;
#pragma unroll
                for (int i = 0; i < 8; i++) { a += red[i * 32 + col]; b += red[256 + i * 32 + col]; }
                c1[nt + col] = a;
                cb[nt + col] = b + b1[nt + col];
            }
        }
        return;
    }
    // transpose-style blocks
    int tx = tid & 31, ty = tid >> 5;
    const float* in;
    __half* outp;
    int Kd, srcStride, nbase, et, kt;
    bool foldG = false;
    if (bid < NB_QKV) {
        et = (bid & 1) * 32;
        kt = ((bid >> 1) & 15) * 64;
        int wh = bid >> 5;               // 0..47
        int w = wh >> 4, h = wh & 15;
        const float* W = (w == 0) ? Wq : ((w == 1) ? Wk : Wv);
        in = W + h * (DD * DHD);
        srcStride = DHD;
        outp = wqkv;
        Kd = DD;
        nbase = w * 1024 + h * 64 + et;
    } else if (bid < NB_QKV + NB_W1) {
        int idx = bid - NB_QKV;
        et = (idx & 127) * 32;           // nt over DFF
        kt = (idx >> 7) * 64;            // kt over DD
        in = W1;
        srcStride = DFF;
        outp = w1o;
        Kd = DD;
        nbase = et;
        foldG = true;
    } else {
        int idx = bid - (NB_QKV + NB_W1);
        et = (idx & 31) * 32;            // nt over DD
        kt = (idx >> 5) * 64;            // kt over DFF
        in = W2;
        srcStride = DD;
        outp = w2o;
        Kd = DFF;
        nbase = et;
    }
#pragma unroll
    for (int i = 0; i < 64; i += 8) {
        float v = in[(size_t)(kt + ty + i) * srcStride + et + tx];
        if (foldG) v *= gamma2[kt + ty + i];
        t[ty + i][tx] = v;
    }
    __syncthreads();
#pragma unroll
    for (int i = 0; i < 32; i += 8) {
        int n = ty + i;
        __half2 v = __halves2half2(__float2half_rn(t[2 * tx][n]),
                                   __float2half_rn(t[2 * tx + 1][n]));
        *(__half2*)(outp + (size_t)(nbase + n) * Kd + kt + 2 * tx) = v;
    }
}

// ---------------- HMMA fp16 GEMM: C[M,N] = A[M,K] * B'[N,K]^T ----------------
// EPI: 3 = fp16 (Q cols pre-scaled)  4 = folded-LN relu -> fp16  5 = split-K atomic (+bias+res on slice0)
template <int MI, int EPI, int OCC>
__global__ __launch_bounds__(256, OCC) void hmma_gemm_kernel(const __half* __restrict__ Ahi,
                                                             const __half* __restrict__ Bhi,
                                                             int K, int N,
                                                             float* __restrict__ Cf,
                                                             __half* __restrict__ Chi,
                                                             const float* __restrict__ bias,
                                                             const float* __restrict__ res,
                                                             const float2* __restrict__ stats,
                                                             const float* __restrict__ c1,
                                                             const float* __restrict__ cb) {
    constexpr int TILE_A  = MI * 64 * 128;          // A tile bytes
    constexpr int TILE_Bb = 16384;                  // B tile bytes (128 rows)
    constexpr int STAGE   = TILE_A + TILE_Bb;

    extern __shared__ __align__(16) char dsm[];
    int tid  = threadIdx.x;
    int wid  = tid >> 5;
    int lane = tid & 31;
    int wm = wid & 3;
    int wn = wid >> 2;

    uint32_t b32 = su32(dsm);
    uint32_t pad = (1024u - (b32 & 1023u)) & 1023u;
    b32 += pad;

    const int m0 = blockIdx.y * (64 * MI);
    const int n0 = blockIdx.x * 128;
    const int nchTot = K >> 6;
    int cbeg = 0, cend = nchTot;
    int kslice = 0;
    if (EPI == 5) {
        kslice = blockIdx.z;
        int half = nchTot >> 1;
        cbeg = kslice * half;
        cend = cbeg + half;
    }

    const __half* srcA = Ahi + (size_t)m0 * K;
    const __half* srcB = Bhi + (size_t)n0 * K;

#define STAGE_CHUNK(c)                                                            \
    do {                                                                          \
        uint32_t stg = b32 + ((c) & 1) * STAGE;                                   \
        int koff = (c) * 64;                                                      \
        _Pragma("unroll")                                                         \
        for (int i = 0; i < 2 * MI; i++) {                                        \
            int idx = i * 256 + tid;                                              \
            int row = idx >> 3, col = idx & 7;                                    \
            uint32_t so = sw128((uint32_t)(row * 128 + col * 16));                \
            cpasync16(stg + so, srcA + (size_t)row * K + koff + col * 8);         \
        }                                                                         \
        _Pragma("unroll")                                                         \
        for (int i = 0; i < 4; i++) {                                             \
            int idx = i * 256 + tid;                                              \
            int row = idx >> 3, col = idx & 7;                                    \
            uint32_t so = sw128((uint32_t)(row * 128 + col * 16));                \
            cpasync16(stg + TILE_A + so, srcB + (size_t)row * K + koff + col * 8);\
        }                                                                         \
        CP_COMMIT();                                                              \
    } while (0)

    float acc[MI][8][4];
#pragma unroll
    for (int mi = 0; mi < MI; mi++)
#pragma unroll
        for (int t = 0; t < 8; t++)
#pragma unroll
            for (int q = 0; q < 4; q++) acc[mi][t][q] = 0.f;

    int g  = lane >> 3;
    int li = lane & 7;
    int a_row0 = wm * (16 * MI) + (g & 1) * 8 + li;
    int a_kb   = (g >> 1) * 16;
    int b_row0 = wn * 64 + (g >> 1) * 8 + li;
    int b_kb   = (g & 1) * 16;

    STAGE_CHUNK(cbeg);

    for (int c = cbeg; c < cend; c++) {
        if (c + 1 < cend) { STAGE_CHUNK(c + 1); CP_WAIT(1); }
        else              { CP_WAIT(0); }
        __syncthreads();

        uint32_t stg = b32 + (c & 1) * STAGE;
        uint32_t aB = stg, bB = stg + TILE_A;

#pragma unroll
        for (int ks = 0; ks < 4; ks++) {
            uint32_t ah[MI][4], bb[4][4];
#pragma unroll
            for (int mi = 0; mi < MI; mi++) {
                uint32_t off = sw128((uint32_t)((a_row0 + mi * 16) * 128 + ks * 32 + a_kb));
                ldm_x4(ah[mi], aB + off);
            }
#pragma unroll
            for (int j = 0; j < 4; j++) {
                uint32_t off = sw128((uint32_t)((b_row0 + j * 16) * 128 + ks * 32 + b_kb));
                ldm_x4(bb[j], bB + off);
            }
#pragma unroll
            for (int mi = 0; mi < MI; mi++)
#pragma unroll
                for (int t = 0; t < 8; t++)
                    mma16816(acc[mi][t], ah[mi], &bb[t >> 1][(t & 1) * 2]);
        }
        __syncthreads();
    }

    int r_base = m0 + wm * (16 * MI) + (lane >> 2);
    int n_base = n0 + wn * 64 + (lane & 3) * 2;
#pragma unroll
    for (int mi = 0; mi < MI; mi++) {
        int rr = r_base + mi * 16;
        float2 stA, stB;
        if (EPI == 4) { stA = stats[rr]; stB = stats[rr + 8]; }
#pragma unroll
        for (int t = 0; t < 8; t++) {
            int r = rr;
            int n = n_base + t * 8;
            float c0 = acc[mi][t][0], c1v_ = acc[mi][t][1];
            float c2 = acc[mi][t][2], c3 = acc[mi][t][3];
            if (EPI == 3) {
                float v0 = c0, v1 = c1v_, v2 = c2, v3 = c3;
                if (n < DD) {   // Q columns: fold softmax scale * log2e
                    v0 *= QSCALE; v1 *= QSCALE; v2 *= QSCALE; v3 *= QSCALE;
                }
                *(__half2*)(Chi + (size_t)r * N + n) =
                    __halves2half2(__float2half_rn(v0), __float2half_rn(v1));
                *(__half2*)(Chi + (size_t)(r + 8) * N + n) =
                    __halves2half2(__float2half_rn(v2), __float2half_rn(v3));
            } else if (EPI == 4) {
                float2 cv = *(const float2*)(c1 + n);
                float2 bv = *(const float2*)(cb + n);
                float v0 = fmaxf((c0   - stA.x * cv.x) * stA.y + bv.x, 0.f);
                float v1 = fmaxf((c1v_ - stA.x * cv.y) * stA.y + bv.y, 0.f);
                float v2 = fmaxf((c2   - stB.x * cv.x) * stB.y + bv.x, 0.f);
                float v3 = fmaxf((c3   - stB.x * cv.y) * stB.y + bv.y, 0.f);
                *(__half2*)(Chi + (size_t)r * N + n) =
                    __halves2half2(__float2half_rn(v0), __float2half_rn(v1));
                *(__half2*)(Chi + (size_t)(r + 8) * N + n) =
                    __halves2half2(__float2half_rn(v2), __float2half_rn(v3));
            } else {  // EPI == 5: split-K atomic accumulate
                float a0 = c0, a1 = c1v_, a2 = c2, a3 = c3;
                if (kslice == 0) {
                    float bi0 = bias[n], bi1 = bias[n + 1];
                    float2 r0v = *(const float2*)(res + (size_t)r * N + n);
                    float2 r1v = *(const float2*)(res + (size_t)(r + 8) * N + n);
                    a0 += bi0 + r0v.x; a1 += bi1 + r0v.y;
                    a2 += bi0 + r1v.x; a3 += bi1 + r1v.y;
                }
                atomicAdd(Cf + (size_t)r * N + n,           a0);
                atomicAdd(Cf + (size_t)r * N + n + 1,       a1);
                atomicAdd(Cf + (size_t)(r + 8) * N + n,     a2);
                atomicAdd(Cf + (size_t)(r + 8) * N + n + 1, a3);
            }
        }
    }
#undef STAGE_CHUNK
}

// ---------------- HMMA flash attention (causal), pure fp16 ----------------
#define AT_STAGE 16384
#define AT_DSM   (2 * AT_STAGE + 1024)

__global__ __launch_bounds__(256, 2) void attn_hmma_kernel(const __half* __restrict__ qkv_hi,
                                                           const float* __restrict__ x,
                                                           float* __restrict__ x1,
                                                           __half* __restrict__ x1h) {
    extern __shared__ __align__(16) char dsm[];
    int tid  = threadIdx.x;
    int wid  = tid >> 5;
    int lane = tid & 31;
    int g  = lane >> 3;
    int li = lane & 7;
    int gr = lane >> 2;
    int gc = lane & 3;

    uint32_t b32 = su32(dsm);
    uint32_t pad = (1024u - (b32 & 1023u)) & 1023u;
    b32 += pad;

    int qt = gridDim.x - 1 - blockIdx.x;     // big tiles first
    int bh = blockIdx.y;
    int b = bh >> 4, h = bh & 15;
    int qbase = qt * 128;

    const __half* qh_g = qkv_hi + (size_t)b * TT * 3072;

    // ---- stage Q, ldmatrix to regs ----
#pragma unroll
    for (int i = 0; i < 4; i++) {
        int idx = i * 256 + tid;
        int row = idx >> 3;
        int col = idx & 7;
        uint32_t so = sw128((uint32_t)(row * 128 + col * 16));
        size_t go = (size_t)(qbase + row) * 3072 + h * 64 + col * 8;
        cpasync16(b32 + so, qh_g + go);
    }
    CP_COMMIT();
    CP_WAIT(0);
    __syncthreads();

    uint32_t qfh[4][4];
    {
        int a_row = wid * 16 + (g & 1) * 8 + li;
        int a_kb  = (g >> 1) * 16;
#pragma unroll
        for (int ks = 0; ks < 4; ks++) {
            uint32_t off = sw128((uint32_t)(a_row * 128 + ks * 32 + a_kb));
            ldm_x4(qfh[ks], b32 + off);
        }
    }
    __syncthreads();

    float m0f = -1e30f, m1f = -1e30f, l0f = 0.f, l1f = 0.f;
    float acc_o[8][4];
#pragma unroll
    for (int t = 0; t < 8; t++)
#pragma unroll
        for (int q = 0; q < 4; q++) acc_o[t][q] = 0.f;

    const int kts = 2 * qt + 2;
    const int wrow_min = qbase + wid * 16;
    const int wrow_max = wrow_min + 15;
    const int b_row = (g >> 1) * 8 + li;
    const int b_kb  = (g & 1) * 16;

#define STAGE_KV(c)                                                                     \
    do {                                                                                \
        uint32_t stg = b32 + ((c) & 1) * AT_STAGE;                                      \
        const __half* kh_g = qh_g + (size_t)((c) * 64) * 3072 + 1024 + h * 64;          \
        _Pragma("unroll")                                                               \
        for (int i = 0; i < 2; i++) {                                                   \
            int idx = i * 256 + tid;                                                    \
            int row = idx >> 3;                                                         \
            int col = idx & 7;                                                          \
            uint32_t so = sw128((uint32_t)(row * 128 + col * 16));                      \
            size_t go = (size_t)row * 3072 + col * 8;                                   \
            cpasync16(stg + so,         kh_g + go);                                     \
            cpasync16(stg + 8192 + so,  kh_g + 1024 + go);                              \
        }                                                                               \
        CP_COMMIT();                                                                    \
    } while (0)

    STAGE_KV(0);

    for (int kt = 0; kt < kts; kt++) {
        if (kt + 1 < kts) { STAGE_KV(kt + 1); CP_WAIT(1); }
        else              { CP_WAIT(0); }
        __syncthreads();

        if (kt * 64 <= wrow_max) {
            uint32_t stg = b32 + (kt & 1) * AT_STAGE;
            uint32_t khB = stg, vhB = stg + 8192;

            uint32_t sacch[8][2];
#pragma unroll
            for (int t = 0; t < 8; t++) { sacch[t][0] = 0u; sacch[t][1] = 0u; }

#pragma unroll
            for (int ks = 0; ks < 4; ks++) {
#pragma unroll
                for (int j = 0; j < 4; j++) {
                    uint32_t off = sw128((uint32_t)((j * 16 + b_row) * 128 + ks * 32 + b_kb));
                    uint32_t kb[4];
                    ldm_x4(kb, khB + off);
                    mma16816h(sacch[2 * j],     qfh[ks], kb);
                    mma16816h(sacch[2 * j + 1], qfh[ks], kb + 2);
                }
            }

            float sacc[8][4];
            int row0 = wrow_min + gr;
            bool domask = (kt * 64 + 63) > wrow_min;
#pragma unroll
            for (int t = 0; t < 8; t++) {
                float2 u0 = __half22float2(*reinterpret_cast<__half2*>(&sacch[t][0]));
                float2 u1 = __half22float2(*reinterpret_cast<__half2*>(&sacch[t][1]));
                sacc[t][0] = u0.x; sacc[t][1] = u0.y;
                sacc[t][2] = u1.x; sacc[t][3] = u1.y;
                if (domask) {
                    int colb = kt * 64 + t * 8 + gc * 2;
#pragma unroll
                    for (int q = 0; q < 4; q++) {
                        int col = colb + (q & 1);
                        int row = row0 + ((q >> 1) << 3);
                        if (col > row) sacc[t][q] = -1e30f;
                    }
                }
            }
            float tm0 = -1e30f, tm1 = -1e30f;
#pragma unroll
            for (int t = 0; t < 8; t++) {
                tm0 = fmaxf(tm0, fmaxf(sacc[t][0], sacc[t][1]));
                tm1 = fmaxf(tm1, fmaxf(sacc[t][2], sacc[t][3]));
            }
#pragma unroll
            for (int o = 1; o <= 2; o <<= 1) {
                tm0 = fmaxf(tm0, __shfl_xor_sync(0xffffffffu, tm0, o));
                tm1 = fmaxf(tm1, __shfl_xor_sync(0xffffffffu, tm1, o));
            }
            float mn0 = fmaxf(m0f, tm0), mn1 = fmaxf(m1f, tm1);
            float sc0 = ex2(m0f - mn0), sc1 = ex2(m1f - mn1);
            m0f = mn0; m1f = mn1;
            float ls0 = 0.f, ls1 = 0.f;
#pragma unroll
            for (int t = 0; t < 8; t++) {
                float p0 = ex2(sacc[t][0] - mn0);
                float p1 = ex2(sacc[t][1] - mn0);
                float p2 = ex2(sacc[t][2] - mn1);
                float p3 = ex2(sacc[t][3] - mn1);
                sacc[t][0] = p0; sacc[t][1] = p1; sacc[t][2] = p2; sacc[t][3] = p3;
                ls0 += p0 + p1; ls1 += p2 + p3;
            }
#pragma unroll
            for (int o = 1; o <= 2; o <<= 1) {
                ls0 += __shfl_xor_sync(0xffffffffu, ls0, o);
                ls1 += __shfl_xor_sync(0xffffffffu, ls1, o);
            }
            l0f = l0f * sc0 + ls0;
            l1f = l1f * sc1 + ls1;
#pragma unroll
            for (int t = 0; t < 8; t++) {
                acc_o[t][0] *= sc0; acc_o[t][1] *= sc0;
                acc_o[t][2] *= sc1; acc_o[t][3] *= sc1;
            }
#pragma unroll
            for (int ks = 0; ks < 4; ks++) {
                float* p0 = sacc[2 * ks];
                float* p1 = sacc[2 * ks + 1];
                uint32_t ah[4];
                ah[0] = packh(p0[0], p0[1]);
                ah[1] = packh(p0[2], p0[3]);
                ah[2] = packh(p1[0], p1[1]);
                ah[3] = packh(p1[2], p1[3]);
#pragma unroll
                for (int dj = 0; dj < 4; dj++) {
                    int krow = ks * 16 + (g & 1) * 8 + li;
                    int dcol = dj * 16 + (g >> 1) * 8;
                    uint32_t off = sw128((uint32_t)(krow * 128 + dcol * 2));
                    uint32_t vb[4];
                    ldm_x4t(vb, vhB + off);
                    mma16816(acc_o[2 * dj],     ah, vb);
                    mma16816(acc_o[2 * dj + 1], ah, vb + 2);
                }
            }
        }
        __syncthreads();
    }

    // epilogue: x1 = x + O/l (fp32 + fp16 copy)
    float inv0 = 1.f / l0f, inv1 = 1.f / l1f;
    int r0 = b * TT + wrow_min + gr;
    int r1 = r0 + 8;
    int cb = h * 64 + gc * 2;
#pragma unroll
    for (int dj = 0; dj < 8; dj++) {
        int col = cb + dj * 8;
        float2 x0 = *(const float2*)(x + (size_t)r0 * DD + col);
        float2 x1v = *(const float2*)(x + (size_t)r1 * DD + col);
        float2 o0 = { acc_o[dj][0] * inv0 + x0.x,  acc_o[dj][1] * inv0 + x0.y };
        float2 o1 = { acc_o[dj][2] * inv1 + x1v.x, acc_o[dj][3] * inv1 + x1v.y };
        *(float2*)(x1 + (size_t)r0 * DD + col) = o0;
        *(float2*)(x1 + (size_t)r1 * DD + col) = o1;
        *(__half2*)(x1h + (size_t)r0 * DD + col) =
            __halves2half2(__float2half_rn(o0.x), __float2half_rn(o0.y));
        *(__half2*)(x1h + (size_t)r1 * DD + col) =
            __halves2half2(__float2half_rn(o1.x), __float2half_rn(o1.y));
    }
#undef STAGE_KV
}

// ---------------- launch ----------------
#define DSM_MI2  (2 * (2 * 64 * 128 + 16384) + 1024)   // 66560
#define DSM_MI1  (2 * (1 * 64 * 128 + 16384) + 1024)   // 50176

extern "C" void kernel_launch(void* const* d_in, const int* in_sizes, int n_in,
                              void* d_out, int out_size) {
    const float* x      = (const float*)d_in[0];
    const float* Wq     = (const float*)d_in[1];
    const float* Wk     = (const float*)d_in[2];
    const float* Wv     = (const float*)d_in[3];
    const float* W1     = (const float*)d_in[4];
    const float* b1     = (const float*)d_in[5];
    const float* W2     = (const float*)d_in[6];
    const float* b2     = (const float*)d_in[7];
    const float* gamma1 = (const float*)d_in[8];
    const float* beta1  = (const float*)d_in[9];
    const float* gamma2 = (const float*)d_in[10];
    const float* beta2  = (const float*)d_in[11];
    float* out = (float*)d_out;

    __half *a_hi, *wqkv_hi, *w1_hi, *w2_hi, *f_hi, *qkv_hi, *x1h;
    float *x1, *c1, *cb;
    float2* stats;
    cudaGetSymbolAddress((void**)&a_hi, g_a_hi);
    cudaGetSymbolAddress((void**)&wqkv_hi, g_wqkv_hi);
    cudaGetSymbolAddress((void**)&w1_hi, g_w1_hi);
    cudaGetSymbolAddress((void**)&w2_hi, g_w2_hi);
    cudaGetSymbolAddress((void**)&f_hi, g_ff1_hi);
    cudaGetSymbolAddress((void**)&qkv_hi, g_qkv_hi);
    cudaGetSymbolAddress((void**)&x1, g_x1);
    cudaGetSymbolAddress((void**)&x1h, g_x1h);
    cudaGetSymbolAddress((void**)&stats, g_stats);
    cudaGetSymbolAddress((void**)&c1, g_c1);
    cudaGetSymbolAddress((void**)&cb, g_cb);

    cudaFuncSetAttribute((hmma_gemm_kernel<2, 3, 2>), cudaFuncAttributeMaxDynamicSharedMemorySize, DSM_MI2);
    cudaFuncSetAttribute((hmma_gemm_kernel<2, 4, 2>), cudaFuncAttributeMaxDynamicSharedMemorySize, DSM_MI2);
    cudaFuncSetAttribute((hmma_gemm_kernel<1, 5, 3>), cudaFuncAttributeMaxDynamicSharedMemorySize, DSM_MI1);
    cudaFuncSetAttribute(attn_hmma_kernel, cudaFuncAttributeMaxDynamicSharedMemorySize, AT_DSM);

    // 1. Prologue: LN1 + weight repacks + out zeroing + c1/cb, ONE launch
    prologue_kernel<<<NB_TOT, 256>>>(
        x, gamma1, beta1, a_hi, Wq, Wk, Wv, wqkv_hi, W1, w1_hi, W2, w2_hi,
        gamma2, beta2, b1, c1, cb, out);
    // 2. QKV projection -> fp16 (Q cols pre-scaled by QSCALE)
    hmma_gemm_kernel<2, 3, 2><<<dim3(3 * DD / 128, MM / 128), 256, DSM_MI2>>>(
        a_hi, wqkv_hi, DD, 3 * DD, nullptr, qkv_hi, nullptr, nullptr, nullptr, nullptr, nullptr);
    // 3. HMMA flash attention + residual -> x1 (fp32) + x1h (fp16)
    attn_hmma_kernel<<<dim3(TT / 128, BB * HH), 256, AT_DSM>>>(qkv_hi, x, x1, x1h);
    // 4. per-row LN2 stats
    stats_kernel<<<MM, 256>>>(x1h, stats);
    // 5. FFN1 with folded LN2: relu(r*(x1h @ (g2*W1) - mu*c1) + cb) -> fp16
    hmma_gemm_kernel<2, 4, 2><<<dim3(DFF / 128, MM / 128), 256, DSM_MI2>>>(
        x1h, w1_hi, DD, DFF, nullptr, f_hi, nullptr, nullptr, stats, c1, cb);
    // 6. FFN2 split-K=2: atomic accumulate into zeroed out (+bias+res on slice 0)
    hmma_gemm_kernel<1, 5, 3><<<dim3(DD / 128, MM / 64, 2), 256, DSM_MI1>>>(
        f_hi, w2_hi, DFF, DD, out, nullptr, b2, x1, nullptr, nullptr, nullptr);
}

// round 15
// speedup vs baseline: 7.2037x; 1.0028x over previous
#include <cuda_runtime.h>
#include <cuda_fp16.h>
#include <cstdint>

// Problem constants
#define DD    1024
#define HH    16
#define DHD   64
#define DFF   4096
#define TT    2048
#define BB    2
#define MM    4096   // B*T

// Q pre-scale: (1/sqrt(1024)) * log2(e)  -> scores become base-2 logits
#define QSCALE 0.045084235f

// ---------------- scratch (device globals; no allocation) ----------------
__device__ __half g_a_hi[MM * DD];                           // LN1 out
__device__ __half g_wqkv_hi[3 * DD * DD];                    // [N=3072,K=1024]
__device__ __half g_w1_hi[DFF * DD];                         // gamma2-folded W1' [N=4096,K=1024]
__device__ __half g_w2_hi[DD * DFF];                         // [N=1024,K=4096]
__device__ __half g_ff1_hi[(size_t)MM * DFF];
__device__ __half g_qkv_hi[(size_t)MM * 3 * DD];
__device__ float  g_x1 [MM * DD];                            // x + attn (fp32, for final residual)
__device__ __half g_x1h[MM * DD];                            // x + attn (fp16, FFN1 A input)
__device__ float2 g_stats[MM];                               // per-row {mean, rsqrt}
__device__ float  g_c1[DFF];                                 // sum_d gamma2_d W1[d,n]
__device__ float  g_cb[DFF];                                 // sum_d beta2_d W1[d,n] + b1[n]

// ---------------- helpers ----------------
static __device__ __forceinline__ uint32_t su32(const void* p) {
    uint32_t a;
    asm("{ .reg .u64 t; cvta.to.shared.u64 t, %1; cvt.u32.u64 %0, t; }" : "=r"(a) : "l"(p));
    return a;
}
static __device__ __forceinline__ uint32_t sw128(uint32_t off) {
    return off ^ ((off >> 3) & 0x70);
}
static __device__ __forceinline__ void cpasync16(uint32_t dst, const void* src) {
    asm volatile("cp.async.cg.shared.global [%0], [%1], 16;" :: "r"(dst), "l"(src));
}
#define CP_COMMIT()  asm volatile("cp.async.commit_group;" ::: "memory")
#define CP_WAIT(n)   asm volatile("cp.async.wait_group %0;" :: "n"(n) : "memory")

static __device__ __forceinline__ void ldm_x4(uint32_t* r, uint32_t addr) {
    asm volatile("ldmatrix.sync.aligned.m8n8.x4.shared.b16 {%0,%1,%2,%3}, [%4];"
                 : "=r"(r[0]), "=r"(r[1]), "=r"(r[2]), "=r"(r[3]) : "r"(addr));
}
static __device__ __forceinline__ void ldm_x4t(uint32_t* r, uint32_t addr) {
    asm volatile("ldmatrix.sync.aligned.m8n8.x4.trans.shared.b16 {%0,%1,%2,%3}, [%4];"
                 : "=r"(r[0]), "=r"(r[1]), "=r"(r[2]), "=r"(r[3]) : "r"(addr));
}
static __device__ __forceinline__ void mma16816(float* d, const uint32_t* a, const uint32_t* b) {
    asm volatile(
        "mma.sync.aligned.m16n8k16.row.col.f32.f16.f16.f32 "
        "{%0,%1,%2,%3}, {%4,%5,%6,%7}, {%8,%9}, {%0,%1,%2,%3};"
        : "+f"(d[0]), "+f"(d[1]), "+f"(d[2]), "+f"(d[3])
        : "r"(a[0]), "r"(a[1]), "r"(a[2]), "r"(a[3]), "r"(b[0]), "r"(b[1]));
}
// fp16-accumulator variant
static __device__ __forceinline__ void mma16816h(uint32_t* d, const uint32_t* a, const uint32_t* b) {
    asm volatile(
        "mma.sync.aligned.m16n8k16.row.col.f16.f16.f16.f16 "
        "{%0,%1}, {%2,%3,%4,%5}, {%6,%7}, {%0,%1};"
        : "+r"(d[0]), "+r"(d[1])
        : "r"(a[0]), "r"(a[1]), "r"(a[2]), "r"(a[3]), "r"(b[0]), "r"(b[1]));
}
static __device__ __forceinline__ uint32_t packh(float a, float b) {
    __half2 t = __halves2half2(__float2half_rn(a), __float2half_rn(b));
    return *reinterpret_cast<uint32_t*>(&t);
}
static __device__ __forceinline__ float ex2(float x) {
    float r;
    asm("ex2.approx.f32 %0, %1;" : "=f"(r) : "f"(x));
    return r;
}

// ---------------- LayerNorm body (ddof=1), fp16 output ----------------
static __device__ __forceinline__ void ln_body(const float* __restrict__ x,
                                               const float* __restrict__ g,
                                               const float* __restrict__ bta,
                                               __half* __restrict__ ohi,
                                               int row, int tid, float* sred) {
    const float4* xr = (const float4*)(x + (size_t)row * DD);
    float4 v = xr[tid];
    float s  = v.x + v.y + v.z + v.w;
    float sq = v.x * v.x + v.y * v.y + v.z * v.z + v.w * v.w;
#pragma unroll
    for (int o = 16; o; o >>= 1) {
        s  += __shfl_xor_sync(0xffffffffu, s,  o);
        sq += __shfl_xor_sync(0xffffffffu, sq, o);
    }
    int w = tid >> 5, ln = tid & 31;
    if (ln == 0) { sred[w] = s; sred[8 + w] = sq; }
    __syncthreads();
    s = 0.f; sq = 0.f;
#pragma unroll
    for (int i = 0; i < 8; i++) { s += sred[i]; sq += sred[8 + i]; }
    float mean = s * (1.f / 1024.f);
    float var  = (sq - 1024.f * mean * mean) * (1.f / 1023.f);
    float r    = rsqrtf(var + 1e-5f);
    float4 gv = ((const float4*)g)[tid];
    float4 bv = ((const float4*)bta)[tid];
    float o0 = gv.x * (v.x - mean) * r + bv.x;
    float o1 = gv.y * (v.y - mean) * r + bv.y;
    float o2 = gv.z * (v.z - mean) * r + bv.z;
    float o3 = gv.w * (v.w - mean) * r + bv.w;
    __half2* hp = (__half2*)(ohi + (size_t)row * DD);
    hp[tid * 2]     = __halves2half2(__float2half_rn(o0), __float2half_rn(o1));
    hp[tid * 2 + 1] = __halves2half2(__float2half_rn(o2), __float2half_rn(o3));
}

// ---------------- row stats (ddof=1), warp-per-row ----------------
__global__ __launch_bounds__(256) void stats_kernel(const __half* __restrict__ xh,
                                                    float2* __restrict__ st) {
    int wid = threadIdx.x >> 5, lane = threadIdx.x & 31;
    int row = blockIdx.x * 8 + wid;
    const uint4* xr = (const uint4*)(xh + (size_t)row * DD);
    float s = 0.f, sq = 0.f;
#pragma unroll
    for (int i = 0; i < 4; i++) {
        uint4 u = xr[lane + i * 32];
        const __half2* h = (const __half2*)&u;
#pragma unroll
        for (int j = 0; j < 4; j++) {
            float2 f = __half22float2(h[j]);
            s  += f.x + f.y;
            sq += f.x * f.x + f.y * f.y;
        }
    }
#pragma unroll
    for (int o = 16; o; o >>= 1) {
        s  += __shfl_xor_sync(0xffffffffu, s,  o);
        sq += __shfl_xor_sync(0xffffffffu, sq, o);
    }
    if (lane == 0) {
        float mean = s * (1.f / 1024.f);
        float var  = (sq - 1024.f * mean * mean) * (1.f / 1023.f);
        st[row] = make_float2(mean, rsqrtf(var + 1e-5f));
    }
}

// ---------------- PROLOGUE megakernel ----------------
#define NB_LN   4096
#define NB_QKV  1536
#define NB_W1   2048
#define NB_W2   2048
#define NB_ZERO 1024
#define NB_C    128
#define NB_TOT  (NB_LN + NB_QKV + NB_W1 + NB_W2 + NB_ZERO + NB_C)

__global__ __launch_bounds__(256) void prologue_kernel(const float* __restrict__ x,
                                                       const float* __restrict__ gamma1,
                                                       const float* __restrict__ beta1,
                                                       __half* __restrict__ a_hi,
                                                       const float* __restrict__ Wq,
                                                       const float* __restrict__ Wk,
                                                       const float* __restrict__ Wv,
                                                       __half* __restrict__ wqkv,
                                                       const float* __restrict__ W1,
                                                       __half* __restrict__ w1o,
                                                       const float* __restrict__ W2,
                                                       __half* __restrict__ w2o,
                                                       const float* __restrict__ gamma2,
                                                       const float* __restrict__ beta2,
                                                       const float* __restrict__ b1,
                                                       float* __restrict__ c1,
                                                       float* __restrict__ cb,
                                                       float* __restrict__ outz) {
    __shared__ float t[64][33];
    int bid = blockIdx.x;
    int tid = threadIdx.x;
    if (bid < NB_LN) {
        ln_body(x, gamma1, beta1, a_hi, bid, tid, &t[0][0]);
        return;
    }
    bid -= NB_LN;
    if (bid >= NB_QKV + NB_W1 + NB_W2) {
        bid -= NB_QKV + NB_W1 + NB_W2;
        if (bid < NB_ZERO) {
            float4 z = { 0.f, 0.f, 0.f, 0.f };
            float4* o = (float4*)outz + (size_t)bid * 1024;
#pragma unroll
            for (int i = 0; i < 4; i++) o[i * 256 + tid] = z;
        } else {
            int nt = (bid - NB_ZERO) * 32;
            int col = tid & 31, dg = tid >> 5;
            float s1 = 0.f, s2 = 0.f;
            for (int d = dg * 128; d < dg * 128 + 128; d++) {
                float w = W1[(size_t)d * DFF + nt + col];
                s1 += gamma2[d] * w;
                s2 += beta2[d] * w;
            }
            float* red = &t[0][0];
            red[dg * 32 + col] = s1;
            red[256 + dg * 32 + col] = s2;
            __syncthreads();
            if (dg == 0) {
                float a = 0.f, b = 0.f;
#pragma unroll
                for (int i = 0; i < 8; i++) { a += red[i * 32 + col]; b += red[256 + i * 32 + col]; }
                c1[nt + col] = a;
                cb[nt + col] = b + b1[nt + col];
            }
        }
        return;
    }
    int tx = tid & 31, ty = tid >> 5;
    const float* in;
    __half* outp;
    int Kd, srcStride, nbase, et, kt;
    bool foldG = false;
    if (bid < NB_QKV) {
        et = (bid & 1) * 32;
        kt = ((bid >> 1) & 15) * 64;
        int wh = bid >> 5;               // 0..47
        int w = wh >> 4, h = wh & 15;
        const float* W = (w == 0) ? Wq : ((w == 1) ? Wk : Wv);
        in = W + h * (DD * DHD);
        srcStride = DHD;
        outp = wqkv;
        Kd = DD;
        nbase = w * 1024 + h * 64 + et;
    } else if (bid < NB_QKV + NB_W1) {
        int idx = bid - NB_QKV;
        et = (idx & 127) * 32;           // nt over DFF
        kt = (idx >> 7) * 64;            // kt over DD
        in = W1;
        srcStride = DFF;
        outp = w1o;
        Kd = DD;
        nbase = et;
        foldG = true;
    } else {
        int idx = bid - (NB_QKV + NB_W1);
        et = (idx & 31) * 32;            // nt over DD
        kt = (idx >> 5) * 64;            // kt over DFF
        in = W2;
        srcStride = DD;
        outp = w2o;
        Kd = DFF;
        nbase = et;
    }
#pragma unroll
    for (int i = 0; i < 64; i += 8) {
        float v = in[(size_t)(kt + ty + i) * srcStride + et + tx];
        if (foldG) v *= gamma2[kt + ty + i];
        t[ty + i][tx] = v;
    }
    __syncthreads();
#pragma unroll
    for (int i = 0; i < 32; i += 8) {
        int n = ty + i;
        __half2 v = __halves2half2(__float2half_rn(t[2 * tx][n]),
                                   __float2half_rn(t[2 * tx + 1][n]));
        *(__half2*)(outp + (size_t)(nbase + n) * Kd + kt + 2 * tx) = v;
    }
}

// ---------------- HMMA fp16 GEMM: C[M,N] = A[M,K] * B'[N,K]^T ----------------
// 3-stage cp.async pipeline. Tile: (64*MI) x 128, 8 warps as 4(M) x 2(N).
// EPI: 3 = fp16 (Q cols pre-scaled)  4 = folded-LN relu -> fp16  5 = split-K atomic (+bias+res on slice0)
template <int MI, int EPI, int OCC>
__global__ __launch_bounds__(256, OCC) void hmma_gemm_kernel(const __half* __restrict__ Ahi,
                                                             const __half* __restrict__ Bhi,
                                                             int K, int N,
                                                             float* __restrict__ Cf,
                                                             __half* __restrict__ Chi,
                                                             const float* __restrict__ bias,
                                                             const float* __restrict__ res,
                                                             const float2* __restrict__ stats,
                                                             const float* __restrict__ c1,
                                                             const float* __restrict__ cb) {
    constexpr int TILE_A  = MI * 64 * 128;          // A tile bytes
    constexpr int TILE_Bb = 16384;                  // B tile bytes (128 rows)
    constexpr int STAGE   = TILE_A + TILE_Bb;

    extern __shared__ __align__(16) char dsm[];
    int tid  = threadIdx.x;
    int wid  = tid >> 5;
    int lane = tid & 31;
    int wm = wid & 3;
    int wn = wid >> 2;

    uint32_t b32 = su32(dsm);
    uint32_t pad = (1024u - (b32 & 1023u)) & 1023u;
    b32 += pad;

    const int m0 = blockIdx.y * (64 * MI);
    const int n0 = blockIdx.x * 128;
    const int nchTot = K >> 6;
    int cbeg = 0, cend = nchTot;
    int kslice = 0;
    if (EPI == 5) {
        kslice = blockIdx.z;
        int half = nchTot >> 1;
        cbeg = kslice * half;
        cend = cbeg + half;
    }

    const __half* srcA = Ahi + (size_t)m0 * K;
    const __half* srcB = Bhi + (size_t)n0 * K;

#define STAGE_CHUNK(c)                                                            \
    do {                                                                          \
        uint32_t stg = b32 + (uint32_t)((c) % 3) * STAGE;                         \
        int koff = (c) * 64;                                                      \
        _Pragma("unroll")                                                         \
        for (int i = 0; i < 2 * MI; i++) {                                        \
            int idx = i * 256 + tid;                                              \
            int row = idx >> 3, col = idx & 7;                                    \
            uint32_t so = sw128((uint32_t)(row * 128 + col * 16));                \
            cpasync16(stg + so, srcA + (size_t)row * K + koff + col * 8);         \
        }                                                                         \
        _Pragma("unroll")                                                         \
        for (int i = 0; i < 4; i++) {                                             \
            int idx = i * 256 + tid;                                              \
            int row = idx >> 3, col = idx & 7;                                    \
            uint32_t so = sw128((uint32_t)(row * 128 + col * 16));                \
            cpasync16(stg + TILE_A + so, srcB + (size_t)row * K + koff + col * 8);\
        }                                                                         \
        CP_COMMIT();                                                              \
    } while (0)

    float acc[MI][8][4];
#pragma unroll
    for (int mi = 0; mi < MI; mi++)
#pragma unroll
        for (int t = 0; t < 8; t++)
#pragma unroll
            for (int q = 0; q < 4; q++) acc[mi][t][q] = 0.f;

    int g  = lane >> 3;
    int li = lane & 7;
    int a_row0 = wm * (16 * MI) + (g & 1) * 8 + li;
    int a_kb   = (g >> 1) * 16;
    int b_row0 = wn * 64 + (g >> 1) * 8 + li;
    int b_kb   = (g & 1) * 16;

    STAGE_CHUNK(cbeg);
    if (cbeg + 1 < cend) STAGE_CHUNK(cbeg + 1);

    for (int c = cbeg; c < cend; c++) {
        if (c + 2 < cend)      { STAGE_CHUNK(c + 2); CP_WAIT(2); }
        else if (c + 1 < cend) { CP_WAIT(1); }
        else                   { CP_WAIT(0); }
        __syncthreads();

        uint32_t stg = b32 + (uint32_t)(c % 3) * STAGE;
        uint32_t aB = stg, bB = stg + TILE_A;

#pragma unroll
        for (int ks = 0; ks < 4; ks++) {
            uint32_t ah[MI][4], bb[4][4];
#pragma unroll
            for (int mi = 0; mi < MI; mi++) {
                uint32_t off = sw128((uint32_t)((a_row0 + mi * 16) * 128 + ks * 32 + a_kb));
                ldm_x4(ah[mi], aB + off);
            }
#pragma unroll
            for (int j = 0; j < 4; j++) {
                uint32_t off = sw128((uint32_t)((b_row0 + j * 16) * 128 + ks * 32 + b_kb));
                ldm_x4(bb[j], bB + off);
            }
#pragma unroll
            for (int mi = 0; mi < MI; mi++)
#pragma unroll
                for (int t = 0; t < 8; t++)
                    mma16816(acc[mi][t], ah[mi], &bb[t >> 1][(t & 1) * 2]);
        }
        __syncthreads();
    }

    int r_base = m0 + wm * (16 * MI) + (lane >> 2);
    int n_base = n0 + wn * 64 + (lane & 3) * 2;
#pragma unroll
    for (int mi = 0; mi < MI; mi++) {
        int rr = r_base + mi * 16;
        float2 stA, stB;
        if (EPI == 4) { stA = stats[rr]; stB = stats[rr + 8]; }
#pragma unroll
        for (int t = 0; t < 8; t++) {
            int r = rr;
            int n = n_base + t * 8;
            float c0 = acc[mi][t][0], c1v_ = acc[mi][t][1];
            float c2 = acc[mi][t][2], c3 = acc[mi][t][3];
            if (EPI == 3) {
                float v0 = c0, v1 = c1v_, v2 = c2, v3 = c3;
                if (n < DD) {
                    v0 *= QSCALE; v1 *= QSCALE; v2 *= QSCALE; v3 *= QSCALE;
                }
                *(__half2*)(Chi + (size_t)r * N + n) =
                    __halves2half2(__float2half_rn(v0), __float2half_rn(v1));
                *(__half2*)(Chi + (size_t)(r + 8) * N + n) =
                    __halves2half2(__float2half_rn(v2), __float2half_rn(v3));
            } else if (EPI == 4) {
                float2 cv = *(const float2*)(c1 + n);
                float2 bv = *(const float2*)(cb + n);
                float v0 = fmaxf((c0   - stA.x * cv.x) * stA.y + bv.x, 0.f);
                float v1 = fmaxf((c1v_ - stA.x * cv.y) * stA.y + bv.y, 0.f);
                float v2 = fmaxf((c2   - stB.x * cv.x) * stB.y + bv.x, 0.f);
                float v3 = fmaxf((c3   - stB.x * cv.y) * stB.y + bv.y, 0.f);
                *(__half2*)(Chi + (size_t)r * N + n) =
                    __halves2half2(__float2half_rn(v0), __float2half_rn(v1));
                *(__half2*)(Chi + (size_t)(r + 8) * N + n) =
                    __halves2half2(__float2half_rn(v2), __float2half_rn(v3));
            } else {  // EPI == 5: split-K atomic accumulate
                float a0 = c0, a1 = c1v_, a2 = c2, a3 = c3;
                if (kslice == 0) {
                    float bi0 = bias[n], bi1 = bias[n + 1];
                    float2 r0v = *(const float2*)(res + (size_t)r * N + n);
                    float2 r1v = *(const float2*)(res + (size_t)(r + 8) * N + n);
                    a0 += bi0 + r0v.x; a1 += bi1 + r0v.y;
                    a2 += bi0 + r1v.x; a3 += bi1 + r1v.y;
                }
                atomicAdd(Cf + (size_t)r * N + n,           a0);
                atomicAdd(Cf + (size_t)r * N + n + 1,       a1);
                atomicAdd(Cf + (size_t)(r + 8) * N + n,     a2);
                atomicAdd(Cf + (size_t)(r + 8) * N + n + 1, a3);
            }
        }
    }
#undef STAGE_CHUNK
}

// ---------------- HMMA flash attention (causal), pure fp16 ----------------
// 128-query CTA tile; 128-key stages processed as 2x64-key halves.
// smem stage: K[16K] | V[16K] = 32KB, double-buffered.
#define AT_STAGE 32768
#define AT_DSM   (2 * AT_STAGE + 1024)

__global__ __launch_bounds__(256, 2) void attn_hmma_kernel(const __half* __restrict__ qkv_hi,
                                                           const float* __restrict__ x,
                                                           float* __restrict__ x1,
                                                           __half* __restrict__ x1h) {
    extern __shared__ __align__(16) char dsm[];
    int tid  = threadIdx.x;
    int wid  = tid >> 5;
    int lane = tid & 31;
    int g  = lane >> 3;
    int li = lane & 7;
    int gr = lane >> 2;
    int gc = lane & 3;

    uint32_t b32 = su32(dsm);
    uint32_t pad = (1024u - (b32 & 1023u)) & 1023u;
    b32 += pad;

    int qt = gridDim.x - 1 - blockIdx.x;     // big tiles first
    int bh = blockIdx.y;
    int b = bh >> 4, h = bh & 15;
    int qbase = qt * 128;

    const __half* qh_g = qkv_hi + (size_t)b * TT * 3072;

    // ---- stage Q, ldmatrix to regs ----
#pragma unroll
    for (int i = 0; i < 4; i++) {
        int idx = i * 256 + tid;
        int row = idx >> 3;
        int col = idx & 7;
        uint32_t so = sw128((uint32_t)(row * 128 + col * 16));
        size_t go = (size_t)(qbase + row) * 3072 + h * 64 + col * 8;
        cpasync16(b32 + so, qh_g + go);
    }
    CP_COMMIT();
    CP_WAIT(0);
    __syncthreads();

    uint32_t qfh[4][4];
    {
        int a_row = wid * 16 + (g & 1) * 8 + li;
        int a_kb  = (g >> 1) * 16;
#pragma unroll
        for (int ks = 0; ks < 4; ks++) {
            uint32_t off = sw128((uint32_t)(a_row * 128 + ks * 32 + a_kb));
            ldm_x4(qfh[ks], b32 + off);
        }
    }
    __syncthreads();

    float m0f = -1e30f, m1f = -1e30f, l0f = 0.f, l1f = 0.f;
    float acc_o[8][4];
#pragma unroll
    for (int t = 0; t < 8; t++)
#pragma unroll
        for (int q = 0; q < 4; q++) acc_o[t][q] = 0.f;

    const int kts = qt + 1;                  // 128-key tiles
    const int wrow_min = qbase + wid * 16;
    const int wrow_max = wrow_min + 15;
    const int b_row = (g >> 1) * 8 + li;
    const int b_kb  = (g & 1) * 16;

    // stage 128 K rows + 128 V rows
#define STAGE_KV(c)                                                                     \
    do {                                                                                \
        uint32_t stg = b32 + ((c) & 1) * AT_STAGE;                                      \
        const __half* kh_g = qh_g + (size_t)((c) * 128) * 3072 + 1024 + h * 64;         \
        _Pragma("unroll")                                                               \
        for (int i = 0; i < 4; i++) {                                                   \
            int idx = i * 256 + tid;                                                    \
            int row = idx >> 3;                                                         \
            int col = idx & 7;                                                          \
            uint32_t so = sw128((uint32_t)(row * 128 + col * 16));                      \
            size_t go = (size_t)row * 3072 + col * 8;                                   \
            cpasync16(stg + so,          kh_g + go);                                    \
            cpasync16(stg + 16384 + so,  kh_g + 1024 + go);                             \
        }                                                                               \
        CP_COMMIT();                                                                    \
    } while (0)

    STAGE_KV(0);

    for (int kt = 0; kt < kts; kt++) {
        if (kt + 1 < kts) { STAGE_KV(kt + 1); CP_WAIT(1); }
        else              { CP_WAIT(0); }
        __syncthreads();

        uint32_t stg = b32 + (kt & 1) * AT_STAGE;

#pragma unroll
        for (int half = 0; half < 2; half++) {
            int kb0 = kt * 128 + half * 64;
            if (kb0 > wrow_max) continue;
            uint32_t khB = stg + half * 8192;
            uint32_t vhB = stg + 16384 + half * 8192;

            uint32_t sacch[8][2];
#pragma unroll
            for (int t = 0; t < 8; t++) { sacch[t][0] = 0u; sacch[t][1] = 0u; }

#pragma unroll
            for (int ks = 0; ks < 4; ks++) {
#pragma unroll
                for (int j = 0; j < 4; j++) {
                    uint32_t off = sw128((uint32_t)((j * 16 + b_row) * 128 + ks * 32 + b_kb));
                    uint32_t kb[4];
                    ldm_x4(kb, khB + off);
                    mma16816h(sacch[2 * j],     qfh[ks], kb);
                    mma16816h(sacch[2 * j + 1], qfh[ks], kb + 2);
                }
            }

            float sacc[8][4];
            int row0 = wrow_min + gr;
            bool domask = (kb0 + 63) > wrow_min;
#pragma unroll
            for (int t = 0; t < 8; t++) {
                float2 u0 = __half22float2(*reinterpret_cast<__half2*>(&sacch[t][0]));
                float2 u1 = __half22float2(*reinterpret_cast<__half2*>(&sacch[t][1]));
                sacc[t][0] = u0.x; sacc[t][1] = u0.y;
                sacc[t][2] = u1.x; sacc[t][3] = u1.y;
                if (domask) {
                    int colb = kb0 + t * 8 + gc * 2;
#pragma unroll
                    for (int q = 0; q < 4; q++) {
                        int col = colb + (q & 1);
                        int row = row0 + ((q >> 1) << 3);
                        if (col > row) sacc[t][q] = -1e30f;
                    }
                }
            }
            float tm0 = -1e30f, tm1 = -1e30f;
#pragma unroll
            for (int t = 0; t < 8; t++) {
                tm0 = fmaxf(tm0, fmaxf(sacc[t][0], sacc[t][1]));
                tm1 = fmaxf(tm1, fmaxf(sacc[t][2], sacc[t][3]));
            }
#pragma unroll
            for (int o = 1; o <= 2; o <<= 1) {
                tm0 = fmaxf(tm0, __shfl_xor_sync(0xffffffffu, tm0, o));
                tm1 = fmaxf(tm1, __shfl_xor_sync(0xffffffffu, tm1, o));
            }
            float mn0 = fmaxf(m0f, tm0), mn1 = fmaxf(m1f, tm1);
            float sc0 = ex2(m0f - mn0), sc1 = ex2(m1f - mn1);
            m0f = mn0; m1f = mn1;
            float ls0 = 0.f, ls1 = 0.f;
#pragma unroll
            for (int t = 0; t < 8; t++) {
                float p0 = ex2(sacc[t][0] - mn0);
                float p1 = ex2(sacc[t][1] - mn0);
                float p2 = ex2(sacc[t][2] - mn1);
                float p3 = ex2(sacc[t][3] - mn1);
                sacc[t][0] = p0; sacc[t][1] = p1; sacc[t][2] = p2; sacc[t][3] = p3;
                ls0 += p0 + p1; ls1 += p2 + p3;
            }
#pragma unroll
            for (int o = 1; o <= 2; o <<= 1) {
                ls0 += __shfl_xor_sync(0xffffffffu, ls0, o);
                ls1 += __shfl_xor_sync(0xffffffffu, ls1, o);
            }
            l0f = l0f * sc0 + ls0;
            l1f = l1f * sc1 + ls1;
#pragma unroll
            for (int t = 0; t < 8; t++) {
                acc_o[t][0] *= sc0; acc_o[t][1] *= sc0;
                acc_o[t][2] *= sc1; acc_o[t][3] *= sc1;
            }
#pragma unroll
            for (int ks = 0; ks < 4; ks++) {
                float* p0 = sacc[2 * ks];
                float* p1 = sacc[2 * ks + 1];
                uint32_t ah[4];
                ah[0] = packh(p0[0], p0[1]);
                ah[1] = packh(p0[2], p0[3]);
                ah[2] = packh(p1[0], p1[1]);
                ah[3] = packh(p1[2], p1[3]);
#pragma unroll
                for (int dj = 0; dj < 4; dj++) {
                    int krow = ks * 16 + (g & 1) * 8 + li;
                    int dcol = dj * 16 + (g >> 1) * 8;
                    uint32_t off = sw128((uint32_t)(krow * 128 + dcol * 2));
                    uint32_t vb[4];
                    ldm_x4t(vb, vhB + off);
                    mma16816(acc_o[2 * dj],     ah, vb);
                    mma16816(acc_o[2 * dj + 1], ah, vb + 2);
                }
            }
        }
        __syncthreads();
    }

    // epilogue: x1 = x + O/l (fp32 + fp16 copy)
    float inv0 = 1.f / l0f, inv1 = 1.f / l1f;
    int r0 = b * TT + wrow_min + gr;
    int r1 = r0 + 8;
    int cb = h * 64 + gc * 2;
#pragma unroll
    for (int dj = 0; dj < 8; dj++) {
        int col = cb + dj * 8;
        float2 x0 = *(const float2*)(x + (size_t)r0 * DD + col);
        float2 x1v = *(const float2*)(x + (size_t)r1 * DD + col);
        float2 o0 = { acc_o[dj][0] * inv0 + x0.x,  acc_o[dj][1] * inv0 + x0.y };
        float2 o1 = { acc_o[dj][2] * inv1 + x1v.x, acc_o[dj][3] * inv1 + x1v.y };
        *(float2*)(x1 + (size_t)r0 * DD + col) = o0;
        *(float2*)(x1 + (size_t)r1 * DD + col) = o1;
        *(__half2*)(x1h + (size_t)r0 * DD + col) =
            __halves2half2(__float2half_rn(o0.x), __float2half_rn(o0.y));
        *(__half2*)(x1h + (size_t)r1 * DD + col) =
            __halves2half2(__float2half_rn(o1.x), __float2half_rn(o1.y));
    }
#undef STAGE_KV
}

// ---------------- launch ----------------
#define DSM_MI2  (3 * (2 * 64 * 128 + 16384) + 1024)   // 99328
#define DSM_MI1  (3 * (1 * 64 * 128 + 16384) + 1024)   // 74752

extern "C" void kernel_launch(void* const* d_in, const int* in_sizes, int n_in,
                              void* d_out, int out_size) {
    const float* x      = (const float*)d_in[0];
    const float* Wq     = (const float*)d_in[1];
    const float* Wk     = (const float*)d_in[2];
    const float* Wv     = (const float*)d_in[3];
    const float* W1     = (const float*)d_in[4];
    const float* b1     = (const float*)d_in[5];
    const float* W2     = (const float*)d_in[6];
    const float* b2     = (const float*)d_in[7];
    const float* gamma1 = (const float*)d_in[8];
    const float* beta1  = (const float*)d_in[9];
    const float* gamma2 = (const float*)d_in[10];
    const float* beta2  = (const float*)d_in[11];
    float* out = (float*)d_out;

    __half *a_hi, *wqkv_hi, *w1_hi, *w2_hi, *f_hi, *qkv_hi, *x1h;
    float *x1, *c1, *cb;
    float2* stats;
    cudaGetSymbolAddress((void**)&a_hi, g_a_hi);
    cudaGetSymbolAddress((void**)&wqkv_hi, g_wqkv_hi);
    cudaGetSymbolAddress((void**)&w1_hi, g_w1_hi);
    cudaGetSymbolAddress((void**)&w2_hi, g_w2_hi);
    cudaGetSymbolAddress((void**)&f_hi, g_ff1_hi);
    cudaGetSymbolAddress((void**)&qkv_hi, g_qkv_hi);
    cudaGetSymbolAddress((void**)&x1, g_x1);
    cudaGetSymbolAddress((void**)&x1h, g_x1h);
    cudaGetSymbolAddress((void**)&stats, g_stats);
    cudaGetSymbolAddress((void**)&c1, g_c1);
    cudaGetSymbolAddress((void**)&cb, g_cb);

    cudaFuncSetAttribute((hmma_gemm_kernel<2, 3, 2>), cudaFuncAttributeMaxDynamicSharedMemorySize, DSM_MI2);
    cudaFuncSetAttribute((hmma_gemm_kernel<2, 4, 2>), cudaFuncAttributeMaxDynamicSharedMemorySize, DSM_MI2);
    cudaFuncSetAttribute((hmma_gemm_kernel<1, 5, 3>), cudaFuncAttributeMaxDynamicSharedMemorySize, DSM_MI1);
    cudaFuncSetAttribute(attn_hmma_kernel, cudaFuncAttributeMaxDynamicSharedMemorySize, AT_DSM);

    // 1. Prologue: LN1 + weight repacks + out zeroing + c1/cb, ONE launch
    prologue_kernel<<<NB_TOT, 256>>>(
        x, gamma1, beta1, a_hi, Wq, Wk, Wv, wqkv_hi, W1, w1_hi, W2, w2_hi,
        gamma2, beta2, b1, c1, cb, out);
    // 2. QKV projection -> fp16 (Q cols pre-scaled by QSCALE)
    hmma_gemm_kernel<2, 3, 2><<<dim3(3 * DD / 128, MM / 128), 256, DSM_MI2>>>(
        a_hi, wqkv_hi, DD, 3 * DD, nullptr, qkv_hi, nullptr, nullptr, nullptr, nullptr, nullptr);
    // 3. HMMA flash attention + residual -> x1 (fp32) + x1h (fp16)
    attn_hmma_kernel<<<dim3(TT / 128, BB * HH), 256, AT_DSM>>>(qkv_hi, x, x1, x1h);
    // 4. per-row LN2 stats (warp-per-row)
    stats_kernel<<<MM / 8, 256>>>(x1h, stats);
    // 5. FFN1 with folded LN2: relu(r*(x1h @ (g2*W1) - mu*c1) + cb) -> fp16
    hmma_gemm_kernel<2, 4, 2><<<dim3(DFF / 128, MM / 128), 256, DSM_MI2>>>(
        x1h, w1_hi, DD, DFF, nullptr, f_hi, nullptr, nullptr, stats, c1, cb);
    // 6. FFN2 split-K=2: atomic accumulate into zeroed out (+bias+res on slice 0)
    hmma_gemm_kernel<1, 5, 3><<<dim3(DD / 128, MM / 64, 2), 256, DSM_MI1>>>(
        f_hi, w2_hi, DFF, DD, out, nullptr, b2, x1, nullptr, nullptr, nullptr);
}

// round 16
// speedup vs baseline: 7.2851x; 1.0113x over previous
#include <cuda_runtime.h>
#include <cuda_fp16.h>
#include <cstdint>

// Problem constants
#define DD    1024
#define HH    16
#define DHD   64
#define DFF   4096
#define TT    2048
#define BB    2
#define MM    4096   // B*T

// Q pre-scale: (1/sqrt(1024)) * log2(e)  -> scores become base-2 logits
#define QSCALE 0.045084235f

// ---------------- scratch (device globals; no allocation) ----------------
__device__ __half g_a_hi[MM * DD];                           // LN1 out
__device__ __half g_wqkv_hi[3 * DD * DD];                    // [N=3072,K=1024]
__device__ __half g_w1_hi[DFF * DD];                         // gamma2-folded W1' [N=4096,K=1024]
__device__ __half g_w2_hi[DD * DFF];                         // [N=1024,K=4096]
__device__ __half g_ff1_hi[(size_t)MM * DFF];
__device__ __half g_qkv_hi[(size_t)MM * 3 * DD];
__device__ __half g_x1h[MM * DD];                            // x + attn (fp16: FFN1 A + FFN2 residual)
__device__ float2 g_ssum[MM];                                // per-row {sum, sumsq} (atomic)
__device__ float  g_c1[DFF];                                 // sum_d gamma2_d W1[d,n]
__device__ float  g_cb[DFF];                                 // sum_d beta2_d W1[d,n] + b1[n]

// ---------------- helpers ----------------
static __device__ __forceinline__ uint32_t su32(const void* p) {
    uint32_t a;
    asm("{ .reg .u64 t; cvta.to.shared.u64 t, %1; cvt.u32.u64 %0, t; }" : "=r"(a) : "l"(p));
    return a;
}
static __device__ __forceinline__ uint32_t sw128(uint32_t off) {
    return off ^ ((off >> 3) & 0x70);
}
static __device__ __forceinline__ void cpasync16(uint32_t dst, const void* src) {
    asm volatile("cp.async.cg.shared.global [%0], [%1], 16;" :: "r"(dst), "l"(src));
}
#define CP_COMMIT()  asm volatile("cp.async.commit_group;" ::: "memory")
#define CP_WAIT(n)   asm volatile("cp.async.wait_group %0;" :: "n"(n) : "memory")

static __device__ __forceinline__ void ldm_x4(uint32_t* r, uint32_t addr) {
    asm volatile("ldmatrix.sync.aligned.m8n8.x4.shared.b16 {%0,%1,%2,%3}, [%4];"
                 : "=r"(r[0]), "=r"(r[1]), "=r"(r[2]), "=r"(r[3]) : "r"(addr));
}
static __device__ __forceinline__ void ldm_x4t(uint32_t* r, uint32_t addr) {
    asm volatile("ldmatrix.sync.aligned.m8n8.x4.trans.shared.b16 {%0,%1,%2,%3}, [%4];"
                 : "=r"(r[0]), "=r"(r[1]), "=r"(r[2]), "=r"(r[3]) : "r"(addr));
}
static __device__ __forceinline__ void mma16816(float* d, const uint32_t* a, const uint32_t* b) {
    asm volatile(
        "mma.sync.aligned.m16n8k16.row.col.f32.f16.f16.f32 "
        "{%0,%1,%2,%3}, {%4,%5,%6,%7}, {%8,%9}, {%0,%1,%2,%3};"
        : "+f"(d[0]), "+f"(d[1]), "+f"(d[2]), "+f"(d[3])
        : "r"(a[0]), "r"(a[1]), "r"(a[2]), "r"(a[3]), "r"(b[0]), "r"(b[1]));
}
// fp16-accumulator variant
static __device__ __forceinline__ void mma16816h(uint32_t* d, const uint32_t* a, const uint32_t* b) {
    asm volatile(
        "mma.sync.aligned.m16n8k16.row.col.f16.f16.f16.f16 "
        "{%0,%1}, {%2,%3,%4,%5}, {%6,%7}, {%0,%1};"
        : "+r"(d[0]), "+r"(d[1])
        : "r"(a[0]), "r"(a[1]), "r"(a[2]), "r"(a[3]), "r"(b[0]), "r"(b[1]));
}
static __device__ __forceinline__ uint32_t packh(float a, float b) {
    __half2 t = __halves2half2(__float2half_rn(a), __float2half_rn(b));
    return *reinterpret_cast<uint32_t*>(&t);
}
static __device__ __forceinline__ float ex2(float x) {
    float r;
    asm("ex2.approx.f32 %0, %1;" : "=f"(r) : "f"(x));
    return r;
}

// ---------------- LayerNorm body (ddof=1), fp16 output ----------------
static __device__ __forceinline__ void ln_body(const float* __restrict__ x,
                                               const float* __restrict__ g,
                                               const float* __restrict__ bta,
                                               __half* __restrict__ ohi,
                                               int row, int tid, float* sred) {
    const float4* xr = (const float4*)(x + (size_t)row * DD);
    float4 v = xr[tid];
    float s  = v.x + v.y + v.z + v.w;
    float sq = v.x * v.x + v.y * v.y + v.z * v.z + v.w * v.w;
#pragma unroll
    for (int o = 16; o; o >>= 1) {
        s  += __shfl_xor_sync(0xffffffffu, s,  o);
        sq += __shfl_xor_sync(0xffffffffu, sq, o);
    }
    int w = tid >> 5, ln = tid & 31;
    if (ln == 0) { sred[w] = s; sred[8 + w] = sq; }
    __syncthreads();
    s = 0.f; sq = 0.f;
#pragma unroll
    for (int i = 0; i < 8; i++) { s += sred[i]; sq += sred[8 + i]; }
    float mean = s * (1.f / 1024.f);
    float var  = (sq - 1024.f * mean * mean) * (1.f / 1023.f);
    float r    = rsqrtf(var + 1e-5f);
    float4 gv = ((const float4*)g)[tid];
    float4 bv = ((const float4*)bta)[tid];
    float o0 = gv.x * (v.x - mean) * r + bv.x;
    float o1 = gv.y * (v.y - mean) * r + bv.y;
    float o2 = gv.z * (v.z - mean) * r + bv.z;
    float o3 = gv.w * (v.w - mean) * r + bv.w;
    __half2* hp = (__half2*)(ohi + (size_t)row * DD);
    hp[tid * 2]     = __halves2half2(__float2half_rn(o0), __float2half_rn(o1));
    hp[tid * 2 + 1] = __halves2half2(__float2half_rn(o2), __float2half_rn(o3));
}

// ---------------- PROLOGUE megakernel ----------------
#define NB_LN   4096
#define NB_QKV  1536
#define NB_W1   2048
#define NB_W2   2048
#define NB_ZERO 1026    // 1024 blocks zero 'out' (16MB) + 2 blocks zero g_ssum (32KB)
#define NB_C    128
#define NB_TOT  (NB_LN + NB_QKV + NB_W1 + NB_W2 + NB_ZERO + NB_C)

__global__ __launch_bounds__(256) void prologue_kernel(const float* __restrict__ x,
                                                       const float* __restrict__ gamma1,
                                                       const float* __restrict__ beta1,
                                                       __half* __restrict__ a_hi,
                                                       const float* __restrict__ Wq,
                                                       const float* __restrict__ Wk,
                                                       const float* __restrict__ Wv,
                                                       __half* __restrict__ wqkv,
                                                       const float* __restrict__ W1,
                                                       __half* __restrict__ w1o,
                                                       const float* __restrict__ W2,
                                                       __half* __restrict__ w2o,
                                                       const float* __restrict__ gamma2,
                                                       const float* __restrict__ beta2,
                                                       const float* __restrict__ b1,
                                                       float* __restrict__ c1,
                                                       float* __restrict__ cb,
                                                       float* __restrict__ outz,
                                                       float* __restrict__ ssumz) {
    __shared__ float t[64][33];
    int bid = blockIdx.x;
    int tid = threadIdx.x;
    if (bid < NB_LN) {
        ln_body(x, gamma1, beta1, a_hi, bid, tid, &t[0][0]);
        return;
    }
    bid -= NB_LN;
    if (bid >= NB_QKV + NB_W1 + NB_W2) {
        bid -= NB_QKV + NB_W1 + NB_W2;
        if (bid < NB_ZERO) {
            float4 z = { 0.f, 0.f, 0.f, 0.f };
            float4* o = (bid < 1024) ? ((float4*)outz + (size_t)bid * 1024)
                                     : ((float4*)ssumz + (size_t)(bid - 1024) * 1024);
#pragma unroll
            for (int i = 0; i < 4; i++) o[i * 256 + tid] = z;
        } else {
            int nt = (bid - NB_ZERO) * 32;
            int col = tid & 31, dg = tid >> 5;
            float s1 = 0.f, s2 = 0.f;
            for (int d = dg * 128; d < dg * 128 + 128; d++) {
                float w = W1[(size_t)d * DFF + nt + col];
                s1 += gamma2[d] * w;
                s2 += beta2[d] * w;
            }
            float* red = &t[0][0];
            red[dg * 32 + col] = s1;
            red[256 + dg * 32 + col] = s2;
            __syncthreads();
            if (dg == 0) {
                float a = 0.f, b = 0.f;
#pragma unroll
                for (int i = 0; i < 8; i++) { a += red[i * 32 + col]; b += red[256 + i * 32 + col]; }
                c1[nt + col] = a;
                cb[nt + col] = b + b1[nt + col];
            }
        }
        return;
    }
    int tx = tid & 31, ty = tid >> 5;
    const float* in;
    __half* outp;
    int Kd, srcStride, nbase, et, kt;
    bool foldG = false;
    if (bid < NB_QKV) {
        et = (bid & 1) * 32;
        kt = ((bid >> 1) & 15) * 64;
        int wh = bid >> 5;               // 0..47
        int w = wh >> 4, h = wh & 15;
        const float* W = (w == 0) ? Wq : ((w == 1) ? Wk : Wv);
        in = W + h * (DD * DHD);
        srcStride = DHD;
        outp = wqkv;
        Kd = DD;
        nbase = w * 1024 + h * 64 + et;
    } else if (bid < NB_QKV + NB_W1) {
        int idx = bid - NB_QKV;
        et = (idx & 127) * 32;           // nt over DFF
        kt = (idx >> 7) * 64;            // kt over DD
        in = W1;
        srcStride = DFF;
        outp = w1o;
        Kd = DD;
        nbase = et;
        foldG = true;
    } else {
        int idx = bid - (NB_QKV + NB_W1);
        et = (idx & 31) * 32;            // nt over DD
        kt = (idx >> 5) * 64;            // kt over DFF
        in = W2;
        srcStride = DD;
        outp = w2o;
        Kd = DFF;
        nbase = et;
    }
#pragma unroll
    for (int i = 0; i < 64; i += 8) {
        float v = in[(size_t)(kt + ty + i) * srcStride + et + tx];
        if (foldG) v *= gamma2[kt + ty + i];
        t[ty + i][tx] = v;
    }
    __syncthreads();
#pragma unroll
    for (int i = 0; i < 32; i += 8) {
        int n = ty + i;
        __half2 v = __halves2half2(__float2half_rn(t[2 * tx][n]),
                                   __float2half_rn(t[2 * tx + 1][n]));
        *(__half2*)(outp + (size_t)(nbase + n) * Kd + kt + 2 * tx) = v;
    }
}

// ---------------- HMMA fp16 GEMM: C[M,N] = A[M,K] * B'[N,K]^T ----------------
// 3-stage cp.async pipeline. Tile: (64*MI) x 128, 8 warps as 4(M) x 2(N).
// EPI: 3 = fp16 (Q cols pre-scaled)  4 = folded-LN relu -> fp16 (stats from ssum)
//      5 = split-K atomic (+bias + fp16 residual on slice0)
template <int MI, int EPI, int OCC>
__global__ __launch_bounds__(256, OCC) void hmma_gemm_kernel(const __half* __restrict__ Ahi,
                                                             const __half* __restrict__ Bhi,
                                                             int K, int N,
                                                             float* __restrict__ Cf,
                                                             __half* __restrict__ Chi,
                                                             const float* __restrict__ bias,
                                                             const __half* __restrict__ resh,
                                                             const float2* __restrict__ ssum,
                                                             const float* __restrict__ c1,
                                                             const float* __restrict__ cb) {
    constexpr int TILE_A  = MI * 64 * 128;          // A tile bytes
    constexpr int TILE_Bb = 16384;                  // B tile bytes (128 rows)
    constexpr int STAGE   = TILE_A + TILE_Bb;

    extern __shared__ __align__(16) char dsm[];
    int tid  = threadIdx.x;
    int wid  = tid >> 5;
    int lane = tid & 31;
    int wm = wid & 3;
    int wn = wid >> 2;

    uint32_t b32 = su32(dsm);
    uint32_t pad = (1024u - (b32 & 1023u)) & 1023u;
    b32 += pad;

    const int m0 = blockIdx.y * (64 * MI);
    const int n0 = blockIdx.x * 128;
    const int nchTot = K >> 6;
    int cbeg = 0, cend = nchTot;
    int kslice = 0;
    if (EPI == 5) {
        kslice = blockIdx.z;
        int half = nchTot >> 1;
        cbeg = kslice * half;
        cend = cbeg + half;
    }

    const __half* srcA = Ahi + (size_t)m0 * K;
    const __half* srcB = Bhi + (size_t)n0 * K;

#define STAGE_CHUNK(c)                                                            \
    do {                                                                          \
        uint32_t stg = b32 + (uint32_t)((c) % 3) * STAGE;                         \
        int koff = (c) * 64;                                                      \
        _Pragma("unroll")                                                         \
        for (int i = 0; i < 2 * MI; i++) {                                        \
            int idx = i * 256 + tid;                                              \
            int row = idx >> 3, col = idx & 7;                                    \
            uint32_t so = sw128((uint32_t)(row * 128 + col * 16));                \
            cpasync16(stg + so, srcA + (size_t)row * K + koff + col * 8);         \
        }                                                                         \
        _Pragma("unroll")                                                         \
        for (int i = 0; i < 4; i++) {                                             \
            int idx = i * 256 + tid;                                              \
            int row = idx >> 3, col = idx & 7;                                    \
            uint32_t so = sw128((uint32_t)(row * 128 + col * 16));                \
            cpasync16(stg + TILE_A + so, srcB + (size_t)row * K + koff + col * 8);\
        }                                                                         \
        CP_COMMIT();                                                              \
    } while (0)

    float acc[MI][8][4];
#pragma unroll
    for (int mi = 0; mi < MI; mi++)
#pragma unroll
        for (int t = 0; t < 8; t++)
#pragma unroll
            for (int q = 0; q < 4; q++) acc[mi][t][q] = 0.f;

    int g  = lane >> 3;
    int li = lane & 7;
    int a_row0 = wm * (16 * MI) + (g & 1) * 8 + li;
    int a_kb   = (g >> 1) * 16;
    int b_row0 = wn * 64 + (g >> 1) * 8 + li;
    int b_kb   = (g & 1) * 16;

    STAGE_CHUNK(cbeg);
    if (cbeg + 1 < cend) STAGE_CHUNK(cbeg + 1);

    for (int c = cbeg; c < cend; c++) {
        if (c + 2 < cend)      { STAGE_CHUNK(c + 2); CP_WAIT(2); }
        else if (c + 1 < cend) { CP_WAIT(1); }
        else                   { CP_WAIT(0); }
        __syncthreads();

        uint32_t stg = b32 + (uint32_t)(c % 3) * STAGE;
        uint32_t aB = stg, bB = stg + TILE_A;

#pragma unroll
        for (int ks = 0; ks < 4; ks++) {
            uint32_t ah[MI][4], bb[4][4];
#pragma unroll
            for (int mi = 0; mi < MI; mi++) {
                uint32_t off = sw128((uint32_t)((a_row0 + mi * 16) * 128 + ks * 32 + a_kb));
                ldm_x4(ah[mi], aB + off);
            }
#pragma unroll
            for (int j = 0; j < 4; j++) {
                uint32_t off = sw128((uint32_t)((b_row0 + j * 16) * 128 + ks * 32 + b_kb));
                ldm_x4(bb[j], bB + off);
            }
#pragma unroll
            for (int mi = 0; mi < MI; mi++)
#pragma unroll
                for (int t = 0; t < 8; t++)
                    mma16816(acc[mi][t], ah[mi], &bb[t >> 1][(t & 1) * 2]);
        }
        __syncthreads();
    }

    int r_base = m0 + wm * (16 * MI) + (lane >> 2);
    int n_base = n0 + wn * 64 + (lane & 3) * 2;
#pragma unroll
    for (int mi = 0; mi < MI; mi++) {
        int rr = r_base + mi * 16;
        float muA, rsA, muB, rsB;
        if (EPI == 4) {
            float2 sA = ssum[rr];
            float2 sB = ssum[rr + 8];
            muA = sA.x * (1.f / 1024.f);
            rsA = rsqrtf((sA.y - 1024.f * muA * muA) * (1.f / 1023.f) + 1e-5f);
            muB = sB.x * (1.f / 1024.f);
            rsB = rsqrtf((sB.y - 1024.f * muB * muB) * (1.f / 1023.f) + 1e-5f);
        }
#pragma unroll
        for (int t = 0; t < 8; t++) {
            int r = rr;
            int n = n_base + t * 8;
            float c0 = acc[mi][t][0], c1v_ = acc[mi][t][1];
            float c2 = acc[mi][t][2], c3 = acc[mi][t][3];
            if (EPI == 3) {
                float v0 = c0, v1 = c1v_, v2 = c2, v3 = c3;
                if (n < DD) {
                    v0 *= QSCALE; v1 *= QSCALE; v2 *= QSCALE; v3 *= QSCALE;
                }
                *(__half2*)(Chi + (size_t)r * N + n) =
                    __halves2half2(__float2half_rn(v0), __float2half_rn(v1));
                *(__half2*)(Chi + (size_t)(r + 8) * N + n) =
                    __halves2half2(__float2half_rn(v2), __float2half_rn(v3));
            } else if (EPI == 4) {
                float2 cv = *(const float2*)(c1 + n);
                float2 bv = *(const float2*)(cb + n);
                float v0 = fmaxf((c0   - muA * cv.x) * rsA + bv.x, 0.f);
                float v1 = fmaxf((c1v_ - muA * cv.y) * rsA + bv.y, 0.f);
                float v2 = fmaxf((c2   - muB * cv.x) * rsB + bv.x, 0.f);
                float v3 = fmaxf((c3   - muB * cv.y) * rsB + bv.y, 0.f);
                *(__half2*)(Chi + (size_t)r * N + n) =
                    __halves2half2(__float2half_rn(v0), __float2half_rn(v1));
                *(__half2*)(Chi + (size_t)(r + 8) * N + n) =
                    __halves2half2(__float2half_rn(v2), __float2half_rn(v3));
            } else {  // EPI == 5: split-K atomic accumulate
                float a0 = c0, a1 = c1v_, a2 = c2, a3 = c3;
                if (kslice == 0) {
                    float bi0 = bias[n], bi1 = bias[n + 1];
                    float2 r0v = __half22float2(*(const __half2*)(resh + (size_t)r * N + n));
                    float2 r1v = __half22float2(*(const __half2*)(resh + (size_t)(r + 8) * N + n));
                    a0 += bi0 + r0v.x; a1 += bi1 + r0v.y;
                    a2 += bi0 + r1v.x; a3 += bi1 + r1v.y;
                }
                atomicAdd(Cf + (size_t)r * N + n,           a0);
                atomicAdd(Cf + (size_t)r * N + n + 1,       a1);
                atomicAdd(Cf + (size_t)(r + 8) * N + n,     a2);
                atomicAdd(Cf + (size_t)(r + 8) * N + n + 1, a3);
            }
        }
    }
#undef STAGE_CHUNK
}

// ---------------- HMMA flash attention (causal), pure fp16 ----------------
// 128-query CTA tile; 128-key stages processed as 2x64-key halves.
// Epilogue: x1h = fp16(x + O/l), plus per-row {sum,sumsq} atomics for LN2.
#define AT_STAGE 32768
#define AT_DSM   (2 * AT_STAGE + 1024)

__global__ __launch_bounds__(256, 2) void attn_hmma_kernel(const __half* __restrict__ qkv_hi,
                                                           const float* __restrict__ x,
                                                           __half* __restrict__ x1h,
                                                           float2* __restrict__ ssum) {
    extern __shared__ __align__(16) char dsm[];
    int tid  = threadIdx.x;
    int wid  = tid >> 5;
    int lane = tid & 31;
    int g  = lane >> 3;
    int li = lane & 7;
    int gr = lane >> 2;
    int gc = lane & 3;

    uint32_t b32 = su32(dsm);
    uint32_t pad = (1024u - (b32 & 1023u)) & 1023u;
    b32 += pad;

    int qt = gridDim.x - 1 - blockIdx.x;     // big tiles first
    int bh = blockIdx.y;
    int b = bh >> 4, h = bh & 15;
    int qbase = qt * 128;

    const __half* qh_g = qkv_hi + (size_t)b * TT * 3072;

    // ---- stage Q, ldmatrix to regs ----
#pragma unroll
    for (int i = 0; i < 4; i++) {
        int idx = i * 256 + tid;
        int row = idx >> 3;
        int col = idx & 7;
        uint32_t so = sw128((uint32_t)(row * 128 + col * 16));
        size_t go = (size_t)(qbase + row) * 3072 + h * 64 + col * 8;
        cpasync16(b32 + so, qh_g + go);
    }
    CP_COMMIT();
    CP_WAIT(0);
    __syncthreads();

    uint32_t qfh[4][4];
    {
        int a_row = wid * 16 + (g & 1) * 8 + li;
        int a_kb  = (g >> 1) * 16;
#pragma unroll
        for (int ks = 0; ks < 4; ks++) {
            uint32_t off = sw128((uint32_t)(a_row * 128 + ks * 32 + a_kb));
            ldm_x4(qfh[ks], b32 + off);
        }
    }
    __syncthreads();

    float m0f = -1e30f, m1f = -1e30f, l0f = 0.f, l1f = 0.f;
    float acc_o[8][4];
#pragma unroll
    for (int t = 0; t < 8; t++)
#pragma unroll
        for (int q = 0; q < 4; q++) acc_o[t][q] = 0.f;

    const int kts = qt + 1;                  // 128-key tiles
    const int wrow_min = qbase + wid * 16;
    const int wrow_max = wrow_min + 15;
    const int b_row = (g >> 1) * 8 + li;
    const int b_kb  = (g & 1) * 16;

#define STAGE_KV(c)                                                                     \
    do {                                                                                \
        uint32_t stg = b32 + ((c) & 1) * AT_STAGE;                                      \
        const __half* kh_g = qh_g + (size_t)((c) * 128) * 3072 + 1024 + h * 64;         \
        _Pragma("unroll")                                                               \
        for (int i = 0; i < 4; i++) {                                                   \
            int idx = i * 256 + tid;                                                    \
            int row = idx >> 3;                                                         \
            int col = idx & 7;                                                          \
            uint32_t so = sw128((uint32_t)(row * 128 + col * 16));                      \
            size_t go = (size_t)row * 3072 + col * 8;                                   \
            cpasync16(stg + so,          kh_g + go);                                    \
            cpasync16(stg + 16384 + so,  kh_g + 1024 + go);                             \
        }                                                                               \
        CP_COMMIT();                                                                    \
    } while (0)

    STAGE_KV(0);

    for (int kt = 0; kt < kts; kt++) {
        if (kt + 1 < kts) { STAGE_KV(kt + 1); CP_WAIT(1); }
        else              { CP_WAIT(0); }
        __syncthreads();

        uint32_t stg = b32 + (kt & 1) * AT_STAGE;

#pragma unroll
        for (int half = 0; half < 2; half++) {
            int kb0 = kt * 128 + half * 64;
            if (kb0 > wrow_max) continue;
            uint32_t khB = stg + half * 8192;
            uint32_t vhB = stg + 16384 + half * 8192;

            uint32_t sacch[8][2];
#pragma unroll
            for (int t = 0; t < 8; t++) { sacch[t][0] = 0u; sacch[t][1] = 0u; }

#pragma unroll
            for (int ks = 0; ks < 4; ks++) {
#pragma unroll
                for (int j = 0; j < 4; j++) {
                    uint32_t off = sw128((uint32_t)((j * 16 + b_row) * 128 + ks * 32 + b_kb));
                    uint32_t kb[4];
                    ldm_x4(kb, khB + off);
                    mma16816h(sacch[2 * j],     qfh[ks], kb);
                    mma16816h(sacch[2 * j + 1], qfh[ks], kb + 2);
                }
            }

            float sacc[8][4];
            int row0 = wrow_min + gr;
            bool domask = (kb0 + 63) > wrow_min;
#pragma unroll
            for (int t = 0; t < 8; t++) {
                float2 u0 = __half22float2(*reinterpret_cast<__half2*>(&sacch[t][0]));
                float2 u1 = __half22float2(*reinterpret_cast<__half2*>(&sacch[t][1]));
                sacc[t][0] = u0.x; sacc[t][1] = u0.y;
                sacc[t][2] = u1.x; sacc[t][3] = u1.y;
                if (domask) {
                    int colb = kb0 + t * 8 + gc * 2;
#pragma unroll
                    for (int q = 0; q < 4; q++) {
                        int col = colb + (q & 1);
                        int row = row0 + ((q >> 1) << 3);
                        if (col > row) sacc[t][q] = -1e30f;
                    }
                }
            }
            float tm0 = -1e30f, tm1 = -1e30f;
#pragma unroll
            for (int t = 0; t < 8; t++) {
                tm0 = fmaxf(tm0, fmaxf(sacc[t][0], sacc[t][1]));
                tm1 = fmaxf(tm1, fmaxf(sacc[t][2], sacc[t][3]));
            }
#pragma unroll
            for (int o = 1; o <= 2; o <<= 1) {
                tm0 = fmaxf(tm0, __shfl_xor_sync(0xffffffffu, tm0, o));
                tm1 = fmaxf(tm1, __shfl_xor_sync(0xffffffffu, tm1, o));
            }
            float mn0 = fmaxf(m0f, tm0), mn1 = fmaxf(m1f, tm1);
            float sc0 = ex2(m0f - mn0), sc1 = ex2(m1f - mn1);
            m0f = mn0; m1f = mn1;
            float ls0 = 0.f, ls1 = 0.f;
#pragma unroll
            for (int t = 0; t < 8; t++) {
                float p0 = ex2(sacc[t][0] - mn0);
                float p1 = ex2(sacc[t][1] - mn0);
                float p2 = ex2(sacc[t][2] - mn1);
                float p3 = ex2(sacc[t][3] - mn1);
                sacc[t][0] = p0; sacc[t][1] = p1; sacc[t][2] = p2; sacc[t][3] = p3;
                ls0 += p0 + p1; ls1 += p2 + p3;
            }
#pragma unroll
            for (int o = 1; o <= 2; o <<= 1) {
                ls0 += __shfl_xor_sync(0xffffffffu, ls0, o);
                ls1 += __shfl_xor_sync(0xffffffffu, ls1, o);
            }
            l0f = l0f * sc0 + ls0;
            l1f = l1f * sc1 + ls1;
#pragma unroll
            for (int t = 0; t < 8; t++) {
                acc_o[t][0] *= sc0; acc_o[t][1] *= sc0;
                acc_o[t][2] *= sc1; acc_o[t][3] *= sc1;
            }
#pragma unroll
            for (int ks = 0; ks < 4; ks++) {
                float* p0 = sacc[2 * ks];
                float* p1 = sacc[2 * ks + 1];
                uint32_t ah[4];
                ah[0] = packh(p0[0], p0[1]);
                ah[1] = packh(p0[2], p0[3]);
                ah[2] = packh(p1[0], p1[1]);
                ah[3] = packh(p1[2], p1[3]);
#pragma unroll
                for (int dj = 0; dj < 4; dj++) {
                    int krow = ks * 16 + (g & 1) * 8 + li;
                    int dcol = dj * 16 + (g >> 1) * 8;
                    uint32_t off = sw128((uint32_t)(krow * 128 + dcol * 2));
                    uint32_t vb[4];
                    ldm_x4t(vb, vhB + off);
                    mma16816(acc_o[2 * dj],     ah, vb);
                    mma16816(acc_o[2 * dj + 1], ah, vb + 2);
                }
            }
        }
        __syncthreads();
    }

    // epilogue: x1h = fp16(x + O/l); LN2 partial sums via atomics
    float inv0 = 1.f / l0f, inv1 = 1.f / l1f;
    int r0g = wrow_min + gr;
    int r0 = b * TT + r0g;
    int r1 = r0 + 8;
    int cb = h * 64 + gc * 2;
    float s0 = 0.f, q0 = 0.f, s1 = 0.f, q1 = 0.f;
#pragma unroll
    for (int dj = 0; dj < 8; dj++) {
        int col = cb + dj * 8;
        float2 x0 = *(const float2*)(x + (size_t)r0 * DD + col);
        float2 x1v = *(const float2*)(x + (size_t)r1 * DD + col);
        float2 o0 = { acc_o[dj][0] * inv0 + x0.x,  acc_o[dj][1] * inv0 + x0.y };
        float2 o1 = { acc_o[dj][2] * inv1 + x1v.x, acc_o[dj][3] * inv1 + x1v.y };
        *(__half2*)(x1h + (size_t)r0 * DD + col) =
            __halves2half2(__float2half_rn(o0.x), __float2half_rn(o0.y));
        *(__half2*)(x1h + (size_t)r1 * DD + col) =
            __halves2half2(__float2half_rn(o1.x), __float2half_rn(o1.y));
        s0 += o0.x + o0.y;  q0 += o0.x * o0.x + o0.y * o0.y;
        s1 += o1.x + o1.y;  q1 += o1.x * o1.x + o1.y * o1.y;
    }
    // reduce over the 4 gc lanes (same row, different cols)
#pragma unroll
    for (int o = 1; o <= 2; o <<= 1) {
        s0 += __shfl_xor_sync(0xffffffffu, s0, o);
        q0 += __shfl_xor_sync(0xffffffffu, q0, o);
        s1 += __shfl_xor_sync(0xffffffffu, s1, o);
        q1 += __shfl_xor_sync(0xffffffffu, q1, o);
    }
    if (gc == 0) {
        atomicAdd(&ssum[r0].x, s0);
        atomicAdd(&ssum[r0].y, q0);
        atomicAdd(&ssum[r1].x, s1);
        atomicAdd(&ssum[r1].y, q1);
    }
#undef STAGE_KV
}

// ---------------- launch ----------------
#define DSM_MI2  (3 * (2 * 64 * 128 + 16384) + 1024)   // 99328
#define DSM_MI1  (3 * (1 * 64 * 128 + 16384) + 1024)   // 74752

extern "C" void kernel_launch(void* const* d_in, const int* in_sizes, int n_in,
                              void* d_out, int out_size) {
    const float* x      = (const float*)d_in[0];
    const float* Wq     = (const float*)d_in[1];
    const float* Wk     = (const float*)d_in[2];
    const float* Wv     = (const float*)d_in[3];
    const float* W1     = (const float*)d_in[4];
    const float* b1     = (const float*)d_in[5];
    const float* W2     = (const float*)d_in[6];
    const float* b2     = (const float*)d_in[7];
    const float* gamma1 = (const float*)d_in[8];
    const float* beta1  = (const float*)d_in[9];
    const float* gamma2 = (const float*)d_in[10];
    const float* beta2  = (const float*)d_in[11];
    float* out = (float*)d_out;

    __half *a_hi, *wqkv_hi, *w1_hi, *w2_hi, *f_hi, *qkv_hi, *x1h;
    float *c1, *cb;
    float2* ssum;
    cudaGetSymbolAddress((void**)&a_hi, g_a_hi);
    cudaGetSymbolAddress((void**)&wqkv_hi, g_wqkv_hi);
    cudaGetSymbolAddress((void**)&w1_hi, g_w1_hi);
    cudaGetSymbolAddress((void**)&w2_hi, g_w2_hi);
    cudaGetSymbolAddress((void**)&f_hi, g_ff1_hi);
    cudaGetSymbolAddress((void**)&qkv_hi, g_qkv_hi);
    cudaGetSymbolAddress((void**)&x1h, g_x1h);
    cudaGetSymbolAddress((void**)&ssum, g_ssum);
    cudaGetSymbolAddress((void**)&c1, g_c1);
    cudaGetSymbolAddress((void**)&cb, g_cb);

    cudaFuncSetAttribute((hmma_gemm_kernel<2, 3, 2>), cudaFuncAttributeMaxDynamicSharedMemorySize, DSM_MI2);
    cudaFuncSetAttribute((hmma_gemm_kernel<2, 4, 2>), cudaFuncAttributeMaxDynamicSharedMemorySize, DSM_MI2);
    cudaFuncSetAttribute((hmma_gemm_kernel<1, 5, 3>), cudaFuncAttributeMaxDynamicSharedMemorySize, DSM_MI1);
    cudaFuncSetAttribute(attn_hmma_kernel, cudaFuncAttributeMaxDynamicSharedMemorySize, AT_DSM);

    // 1. Prologue: LN1 + weight repacks + out/ssum zeroing + c1/cb, ONE launch
    prologue_kernel<<<NB_TOT, 256>>>(
        x, gamma1, beta1, a_hi, Wq, Wk, Wv, wqkv_hi, W1, w1_hi, W2, w2_hi,
        gamma2, beta2, b1, c1, cb, out, (float*)ssum);
    // 2. QKV projection -> fp16 (Q cols pre-scaled by QSCALE)
    hmma_gemm_kernel<2, 3, 2><<<dim3(3 * DD / 128, MM / 128), 256, DSM_MI2>>>(
        a_hi, wqkv_hi, DD, 3 * DD, nullptr, qkv_hi, nullptr, nullptr, nullptr, nullptr, nullptr);
    // 3. HMMA flash attention + residual -> x1h (fp16) + LN2 sums (atomics)
    attn_hmma_kernel<<<dim3(TT / 128, BB * HH), 256, AT_DSM>>>(qkv_hi, x, x1h, ssum);
    // 4. FFN1 with folded LN2 (stats from ssum): relu(...) -> fp16
    hmma_gemm_kernel<2, 4, 2><<<dim3(DFF / 128, MM / 128), 256, DSM_MI2>>>(
        x1h, w1_hi, DD, DFF, nullptr, f_hi, nullptr, nullptr, ssum, c1, cb);
    // 5. FFN2 split-K=2: atomic accumulate into zeroed out (+bias + fp16 residual on slice 0)
    hmma_gemm_kernel<1, 5, 3><<<dim3(DD / 128, MM / 64, 2), 256, DSM_MI1>>>(
        f_hi, w2_hi, DFF, DD, out, nullptr, b2, x1h, nullptr, nullptr, nullptr);
}